// round 1
// baseline (speedup 1.0000x reference)
#include <cuda_runtime.h>
#include <math.h>

// Problem constants
#define B_   2
#define S_   2048
#define H_   2048
#define NH_  16
#define NKV_ 4
#define HD_  128
#define I_   8192
#define NTOK (B_*S_)          // 4096
#define EPSF 1e-6f

// ---------------------------------------------------------------------------
// Scratch (device globals; no allocation allowed)
// ---------------------------------------------------------------------------
__device__ float g_h [NTOK * H_];          // rmsnorm output (h and h2)
__device__ float g_q [NTOK * NH_ * HD_];   // Q
__device__ float g_k [NTOK * NKV_ * HD_];  // K
__device__ float g_v [NTOK * NKV_ * HD_];  // V
__device__ float g_o [NTOK * NH_ * HD_];   // attention output (pre-Wo)
__device__ float g_x [NTOK * H_];          // post-attention residual
__device__ float g_g [NTOK * I_];          // gate  (then swiglu result)
__device__ float g_u [NTOK * I_];          // up
__device__ float g_rope[S_ * HD_];         // [pos][0..63]=cos, [64..127]=sin

// ---------------------------------------------------------------------------
// RoPE cos/sin table (matches reference fp32 math)
// ---------------------------------------------------------------------------
__global__ void rope_table_kernel() {
    int idx = blockIdx.x * blockDim.x + threadIdx.x;
    if (idx >= S_ * 64) return;
    int pos = idx >> 6;
    int i   = idx & 63;
    float invf = 1.0f / powf(10000.0f, (float)i / 64.0f);
    float ang  = (float)pos * invf;
    g_rope[pos * HD_ + i]      = cosf(ang);
    g_rope[pos * HD_ + 64 + i] = sinf(ang);
}

// ---------------------------------------------------------------------------
// RMSNorm over H_=2048, one block per row
// ---------------------------------------------------------------------------
__global__ __launch_bounds__(256) void rmsnorm_kernel(
    const float* __restrict__ x, const float* __restrict__ w,
    float* __restrict__ out)
{
    int row = blockIdx.x;
    const float* xr = x + (size_t)row * H_;
    float ss = 0.f;
#pragma unroll
    for (int it = 0; it < H_ / (256 * 4); it++) {
        int c = (it * 256 + threadIdx.x) * 4;
        float4 t = *(const float4*)(xr + c);
        ss += t.x * t.x + t.y * t.y + t.z * t.z + t.w * t.w;
    }
#pragma unroll
    for (int o = 16; o; o >>= 1) ss += __shfl_xor_sync(0xffffffffu, ss, o);
    __shared__ float red[8];
    if ((threadIdx.x & 31) == 0) red[threadIdx.x >> 5] = ss;
    __syncthreads();
    float tot = 0.f;
#pragma unroll
    for (int i = 0; i < 8; i++) tot += red[i];
    float inv = rsqrtf(tot * (1.0f / H_) + EPSF);
    float* orow = out + (size_t)row * H_;
#pragma unroll
    for (int it = 0; it < H_ / (256 * 4); it++) {
        int c = (it * 256 + threadIdx.x) * 4;
        float4 t  = *(const float4*)(xr + c);
        float4 wv = *(const float4*)(w + c);
        t.x = wv.x * t.x * inv; t.y = wv.y * t.y * inv;
        t.z = wv.z * t.z * inv; t.w = wv.w * t.w * inv;
        *(float4*)(orow + c) = t;
    }
}

// ---------------------------------------------------------------------------
// SGEMM: C[M,N] = A[M,K] @ B[K,N] (+ addend), all row-major, dims % 128/16 == 0
// 128x128 block, BK=16, 256 threads, 8x8 per thread
// ---------------------------------------------------------------------------
__global__ __launch_bounds__(256) void sgemm_kernel(
    const float* __restrict__ A, const float* __restrict__ B,
    const float* __restrict__ addend, float* __restrict__ C,
    int M, int N, int K)
{
    __shared__ float As[16][128];   // transposed A tile
    __shared__ float Bs[16][128];

    int tid  = threadIdx.x;
    int cRow = blockIdx.y, cCol = blockIdx.x;

    int aRow = tid >> 2;          // 0..63
    int aCol = (tid & 3) << 2;    // 0,4,8,12
    int bRow = tid >> 5;          // 0..7
    int bCol = (tid & 31) << 2;   // 0..124
    int tRow = tid >> 4;          // 0..15
    int tCol = tid & 15;          // 0..15

    const float* Ab = A + (size_t)(cRow * 128) * K;
    const float* Bb = B + (size_t)cCol * 128;

    float acc[8][8];
#pragma unroll
    for (int i = 0; i < 8; i++)
#pragma unroll
        for (int j = 0; j < 8; j++) acc[i][j] = 0.f;

    for (int kt = 0; kt < K; kt += 16) {
#pragma unroll
        for (int s = 0; s < 2; s++) {
            int r = aRow + s * 64;
            float4 t = *(const float4*)(Ab + (size_t)r * K + kt + aCol);
            As[aCol + 0][r] = t.x; As[aCol + 1][r] = t.y;
            As[aCol + 2][r] = t.z; As[aCol + 3][r] = t.w;
        }
#pragma unroll
        for (int s = 0; s < 2; s++) {
            int r = bRow + s * 8;
            *(float4*)(&Bs[r][bCol]) = *(const float4*)(Bb + (size_t)(kt + r) * N + bCol);
        }
        __syncthreads();
#pragma unroll
        for (int kk = 0; kk < 16; kk++) {
            float am[8], bn[8];
            *(float4*)(am)     = *(const float4*)(&As[kk][tRow * 8]);
            *(float4*)(am + 4) = *(const float4*)(&As[kk][tRow * 8 + 4]);
            *(float4*)(bn)     = *(const float4*)(&Bs[kk][tCol * 8]);
            *(float4*)(bn + 4) = *(const float4*)(&Bs[kk][tCol * 8 + 4]);
#pragma unroll
            for (int i = 0; i < 8; i++)
#pragma unroll
                for (int j = 0; j < 8; j++)
                    acc[i][j] += am[i] * bn[j];
        }
        __syncthreads();
    }

#pragma unroll
    for (int i = 0; i < 8; i++) {
        size_t row = (size_t)(cRow * 128 + tRow * 8 + i);
        float* crow = C + row * N + cCol * 128 + tCol * 8;
        if (addend) {
            const float* arow = addend + row * N + cCol * 128 + tCol * 8;
            float4 a0 = *(const float4*)(arow);
            float4 a1 = *(const float4*)(arow + 4);
            float4 r0 = make_float4(acc[i][0] + a0.x, acc[i][1] + a0.y,
                                    acc[i][2] + a0.z, acc[i][3] + a0.w);
            float4 r1 = make_float4(acc[i][4] + a1.x, acc[i][5] + a1.y,
                                    acc[i][6] + a1.z, acc[i][7] + a1.w);
            *(float4*)(crow)     = r0;
            *(float4*)(crow + 4) = r1;
        } else {
            float4 r0 = make_float4(acc[i][0], acc[i][1], acc[i][2], acc[i][3]);
            float4 r1 = make_float4(acc[i][4], acc[i][5], acc[i][6], acc[i][7]);
            *(float4*)(crow)     = r0;
            *(float4*)(crow + 4) = r1;
        }
    }
}

// ---------------------------------------------------------------------------
// RoPE + QK RMSNorm (in place). One warp per (token, head). hd=128.
// ---------------------------------------------------------------------------
__global__ __launch_bounds__(128) void rope_norm_kernel(
    float* __restrict__ qk, const float* __restrict__ w, int nheads)
{
    int tok  = blockIdx.x;
    int warp = threadIdx.x >> 5;
    int lane = threadIdx.x & 31;
    int head = blockIdx.y * 4 + warp;
    int pos  = tok % S_;   // position_ids == arange(S) per batch

    float* base = qk + ((size_t)tok * nheads + head) * HD_;
    float a0 = base[lane];      float a1 = base[lane + 32];
    float b0 = base[lane + 64]; float b1 = base[lane + 96];

    const float* rc = g_rope + (size_t)pos * HD_;
    float c0 = rc[lane],      s0 = rc[64 + lane];
    float c1 = rc[lane + 32], s1 = rc[96 + lane];

    float r0  = a0 * c0 - b0 * s0;
    float r64 = b0 * c0 + a0 * s0;
    float r32 = a1 * c1 - b1 * s1;
    float r96 = b1 * c1 + a1 * s1;

    float ss = r0 * r0 + r32 * r32 + r64 * r64 + r96 * r96;
#pragma unroll
    for (int o = 16; o; o >>= 1) ss += __shfl_xor_sync(0xffffffffu, ss, o);
    float inv = rsqrtf(ss * (1.0f / HD_) + EPSF);

    base[lane]      = w[lane]      * r0  * inv;
    base[lane + 32] = w[lane + 32] * r32 * inv;
    base[lane + 64] = w[lane + 64] * r64 * inv;
    base[lane + 96] = w[lane + 96] * r96 * inv;
}

// ---------------------------------------------------------------------------
// Flash attention (causal, GQA). BQ=BK=64, hd=128, 128 threads.
// Thread layout: ty = tid/8 (16 row-groups of 4), tx = tid%8 (8 col-groups of 8)
// Each thread: S tile 4x8, O tile 4x16.
// ---------------------------------------------------------------------------
#define FBQ 64
#define FBK 64
#define QS_STRIDE 131
#define KS_STRIDE 131
#define VS_STRIDE 132
#define PS_STRIDE 65
#define FLASH_SMEM ((FBQ*QS_STRIDE + FBK*KS_STRIDE + FBK*VS_STRIDE + FBQ*PS_STRIDE) * 4)

__global__ __launch_bounds__(128) void flash_kernel(
    const float* __restrict__ q, const float* __restrict__ k,
    const float* __restrict__ v, float* __restrict__ o)
{
    extern __shared__ float sm[];
    float* Qs = sm;
    float* Ks = Qs + FBQ * QS_STRIDE;
    float* Vs = Ks + FBK * KS_STRIDE;
    float* Ps = Vs + FBK * VS_STRIDE;

    int qb = gridDim.x - 1 - blockIdx.x;  // big tiles first (load balance)
    int bh = blockIdx.y;
    int b  = bh / NH_, h = bh % NH_;
    int kvh = h / (NH_ / NKV_);

    int tid = threadIdx.x;
    int ty = tid >> 3, tx = tid & 7;

    const float scale = 0.08838834764831845f;  // 1/sqrt(128)

    // Load Q tile (scaled)
    const float* qbase = q + ((size_t)(b * S_ + qb * FBQ) * NH_ + h) * HD_;
    for (int i = tid; i < FBQ * (HD_ / 4); i += 128) {
        int r  = i >> 5;
        int c4 = (i & 31) * 4;
        float4 t = *(const float4*)(qbase + (size_t)r * NH_ * HD_ + c4);
        float* dst = Qs + r * QS_STRIDE + c4;
        dst[0] = t.x * scale; dst[1] = t.y * scale;
        dst[2] = t.z * scale; dst[3] = t.w * scale;
    }

    float m_i[4], l_i[4], acc[4][16];
#pragma unroll
    for (int i = 0; i < 4; i++) {
        m_i[i] = -1e30f; l_i[i] = 0.f;
#pragma unroll
        for (int c = 0; c < 16; c++) acc[i][c] = 0.f;
    }

    for (int kb = 0; kb <= qb; kb++) {
        __syncthreads();
        const float* kbase = k + ((size_t)(b * S_ + kb * FBK) * NKV_ + kvh) * HD_;
        const float* vbase = v + ((size_t)(b * S_ + kb * FBK) * NKV_ + kvh) * HD_;
        for (int i = tid; i < FBK * (HD_ / 4); i += 128) {
            int r  = i >> 5;
            int c4 = (i & 31) * 4;
            float4 tk = *(const float4*)(kbase + (size_t)r * NKV_ * HD_ + c4);
            float* kd = Ks + r * KS_STRIDE + c4;
            kd[0] = tk.x; kd[1] = tk.y; kd[2] = tk.z; kd[3] = tk.w;
            float4 tv = *(const float4*)(vbase + (size_t)r * NKV_ * HD_ + c4);
            *(float4*)(Vs + r * VS_STRIDE + c4) = tv;
        }
        __syncthreads();

        // S = Q K^T
        float s[4][8];
#pragma unroll
        for (int i = 0; i < 4; i++)
#pragma unroll
            for (int j = 0; j < 8; j++) s[i][j] = 0.f;

#pragma unroll 8
        for (int kk = 0; kk < HD_; kk++) {
            float qr[4], kr[8];
#pragma unroll
            for (int i = 0; i < 4; i++) qr[i] = Qs[(ty * 4 + i) * QS_STRIDE + kk];
#pragma unroll
            for (int j = 0; j < 8; j++) kr[j] = Ks[(tx * 8 + j) * KS_STRIDE + kk];
#pragma unroll
            for (int i = 0; i < 4; i++)
#pragma unroll
                for (int j = 0; j < 8; j++)
                    s[i][j] += qr[i] * kr[j];
        }

        // causal mask (only relevant on the diagonal tile)
        if (kb == qb) {
#pragma unroll
            for (int i = 0; i < 4; i++)
#pragma unroll
                for (int j = 0; j < 8; j++)
                    if (tx * 8 + j > ty * 4 + i) s[i][j] = -1e30f;
        }

        // online softmax (row stats across the 8 lanes of a row-group)
#pragma unroll
        for (int i = 0; i < 4; i++) {
            float mx = s[i][0];
#pragma unroll
            for (int j = 1; j < 8; j++) mx = fmaxf(mx, s[i][j]);
            mx = fmaxf(mx, __shfl_xor_sync(0xffffffffu, mx, 1));
            mx = fmaxf(mx, __shfl_xor_sync(0xffffffffu, mx, 2));
            mx = fmaxf(mx, __shfl_xor_sync(0xffffffffu, mx, 4));
            float m_new = fmaxf(m_i[i], mx);
            float corr  = expf(m_i[i] - m_new);
            m_i[i] = m_new;
            float rs = 0.f;
#pragma unroll
            for (int j = 0; j < 8; j++) {
                float p = expf(s[i][j] - m_new);
                rs += p;
                Ps[(ty * 4 + i) * PS_STRIDE + tx * 8 + j] = p;
            }
            rs += __shfl_xor_sync(0xffffffffu, rs, 1);
            rs += __shfl_xor_sync(0xffffffffu, rs, 2);
            rs += __shfl_xor_sync(0xffffffffu, rs, 4);
            l_i[i] = l_i[i] * corr + rs;
#pragma unroll
            for (int c = 0; c < 16; c++) acc[i][c] *= corr;
        }
        __syncwarp();

        // O += P V
#pragma unroll 4
        for (int j = 0; j < FBK; j++) {
            float pr[4];
#pragma unroll
            for (int i = 0; i < 4; i++) pr[i] = Ps[(ty * 4 + i) * PS_STRIDE + j];
            const float* vrow = Vs + j * VS_STRIDE + tx * 16;
            float4 v0 = *(const float4*)(vrow);
            float4 v1 = *(const float4*)(vrow + 4);
            float4 v2 = *(const float4*)(vrow + 8);
            float4 v3 = *(const float4*)(vrow + 12);
#pragma unroll
            for (int i = 0; i < 4; i++) {
                acc[i][0]  += pr[i] * v0.x; acc[i][1]  += pr[i] * v0.y;
                acc[i][2]  += pr[i] * v0.z; acc[i][3]  += pr[i] * v0.w;
                acc[i][4]  += pr[i] * v1.x; acc[i][5]  += pr[i] * v1.y;
                acc[i][6]  += pr[i] * v1.z; acc[i][7]  += pr[i] * v1.w;
                acc[i][8]  += pr[i] * v2.x; acc[i][9]  += pr[i] * v2.y;
                acc[i][10] += pr[i] * v2.z; acc[i][11] += pr[i] * v2.w;
                acc[i][12] += pr[i] * v3.x; acc[i][13] += pr[i] * v3.y;
                acc[i][14] += pr[i] * v3.z; acc[i][15] += pr[i] * v3.w;
            }
        }
    }

    // epilogue
    float* obase = o + ((size_t)(b * S_ + qb * FBQ) * NH_ + h) * HD_;
#pragma unroll
    for (int i = 0; i < 4; i++) {
        float inv = 1.0f / l_i[i];
        int r = ty * 4 + i;
        float* dst = obase + (size_t)r * NH_ * HD_ + tx * 16;
        float4 r0 = make_float4(acc[i][0]*inv,  acc[i][1]*inv,  acc[i][2]*inv,  acc[i][3]*inv);
        float4 r1 = make_float4(acc[i][4]*inv,  acc[i][5]*inv,  acc[i][6]*inv,  acc[i][7]*inv);
        float4 r2 = make_float4(acc[i][8]*inv,  acc[i][9]*inv,  acc[i][10]*inv, acc[i][11]*inv);
        float4 r3 = make_float4(acc[i][12]*inv, acc[i][13]*inv, acc[i][14]*inv, acc[i][15]*inv);
        *(float4*)(dst)      = r0;
        *(float4*)(dst + 4)  = r1;
        *(float4*)(dst + 8)  = r2;
        *(float4*)(dst + 12) = r3;
    }
}

// ---------------------------------------------------------------------------
// SwiGLU: g = silu(g) * u  (in place on g)
// ---------------------------------------------------------------------------
__global__ __launch_bounds__(256) void swiglu_kernel(
    float* __restrict__ g, const float* __restrict__ u)
{
    int idx = blockIdx.x * 256 + threadIdx.x;
    if (idx >= NTOK * (I_ / 4)) return;
    float4 gv = ((float4*)g)[idx];
    float4 uv = ((const float4*)u)[idx];
    gv.x = gv.x / (1.f + expf(-gv.x)) * uv.x;
    gv.y = gv.y / (1.f + expf(-gv.y)) * uv.y;
    gv.z = gv.z / (1.f + expf(-gv.z)) * uv.z;
    gv.w = gv.w / (1.f + expf(-gv.w)) * uv.w;
    ((float4*)g)[idx] = gv;
}

// ---------------------------------------------------------------------------
// Launch
// ---------------------------------------------------------------------------
extern "C" void kernel_launch(void* const* d_in, const int* in_sizes, int n_in,
                              void* d_out, int out_size)
{
    const float* hidden = (const float*)d_in[0];
    // d_in[1] attention_mask: causal -1e9 triu, applied structurally
    // d_in[2] position_ids: arange(S) per batch, applied structurally
    const float* ln1_w = (const float*)d_in[3];
    const float* Wq    = (const float*)d_in[4];
    const float* Wk    = (const float*)d_in[5];
    const float* Wv    = (const float*)d_in[6];
    const float* Wo    = (const float*)d_in[7];
    const float* qn_w  = (const float*)d_in[8];
    const float* kn_w  = (const float*)d_in[9];
    const float* ln2_w = (const float*)d_in[10];
    const float* Wg    = (const float*)d_in[11];
    const float* Wu    = (const float*)d_in[12];
    const float* Wd    = (const float*)d_in[13];
    float* out = (float*)d_out;

    float *p_h, *p_q, *p_k, *p_v, *p_o, *p_x, *p_g, *p_u;
    cudaGetSymbolAddress((void**)&p_h, g_h);
    cudaGetSymbolAddress((void**)&p_q, g_q);
    cudaGetSymbolAddress((void**)&p_k, g_k);
    cudaGetSymbolAddress((void**)&p_v, g_v);
    cudaGetSymbolAddress((void**)&p_o, g_o);
    cudaGetSymbolAddress((void**)&p_x, g_x);
    cudaGetSymbolAddress((void**)&p_g, g_g);
    cudaGetSymbolAddress((void**)&p_u, g_u);

    cudaFuncSetAttribute(flash_kernel,
                         cudaFuncAttributeMaxDynamicSharedMemorySize, FLASH_SMEM);

    // RoPE table
    rope_table_kernel<<<(S_ * 64 + 255) / 256, 256>>>();

    // Attention block
    rmsnorm_kernel<<<NTOK, 256>>>(hidden, ln1_w, p_h);
    sgemm_kernel<<<dim3((NH_ * HD_) / 128, NTOK / 128), 256>>>(p_h, Wq, nullptr, p_q, NTOK, NH_ * HD_, H_);
    sgemm_kernel<<<dim3((NKV_ * HD_) / 128, NTOK / 128), 256>>>(p_h, Wk, nullptr, p_k, NTOK, NKV_ * HD_, H_);
    sgemm_kernel<<<dim3((NKV_ * HD_) / 128, NTOK / 128), 256>>>(p_h, Wv, nullptr, p_v, NTOK, NKV_ * HD_, H_);
    rope_norm_kernel<<<dim3(NTOK, NH_ / 4), 128>>>(p_q, qn_w, NH_);
    rope_norm_kernel<<<dim3(NTOK, NKV_ / 4), 128>>>(p_k, kn_w, NKV_);
    flash_kernel<<<dim3(S_ / FBQ, B_ * NH_), 128, FLASH_SMEM>>>(p_q, p_k, p_v, p_o);
    sgemm_kernel<<<dim3(H_ / 128, NTOK / 128), 256>>>(p_o, Wo, hidden, p_x, NTOK, H_, H_);

    // MLP block
    rmsnorm_kernel<<<NTOK, 256>>>(p_x, ln2_w, p_h);
    sgemm_kernel<<<dim3(I_ / 128, NTOK / 128), 256>>>(p_h, Wg, nullptr, p_g, NTOK, I_, H_);
    sgemm_kernel<<<dim3(I_ / 128, NTOK / 128), 256>>>(p_h, Wu, nullptr, p_u, NTOK, I_, H_);
    swiglu_kernel<<<(NTOK * (I_ / 4) + 255) / 256, 256>>>(p_g, p_u);
    sgemm_kernel<<<dim3(H_ / 128, NTOK / 128), 256>>>(p_g, Wd, p_x, out, NTOK, H_, I_);
}

// round 2
// speedup vs baseline: 2.2654x; 2.2654x over previous
#include <cuda_runtime.h>
#include <math.h>

// Problem constants
#define B_   2
#define S_   2048
#define H_   2048
#define NH_  16
#define NKV_ 4
#define HD_  128
#define I_   8192
#define NTOK (B_*S_)          // 4096
#define EPSF 1e-6f

// ---------------------------------------------------------------------------
// Scratch (device globals; no allocation allowed)
// ---------------------------------------------------------------------------
__device__ float g_h [NTOK * H_];
__device__ float g_q [NTOK * NH_ * HD_];
__device__ float g_k [NTOK * NKV_ * HD_];
__device__ float g_v [NTOK * NKV_ * HD_];
__device__ float g_o [NTOK * NH_ * HD_];
__device__ float g_x [NTOK * H_];
__device__ float g_g [NTOK * I_];
__device__ float g_u [NTOK * I_];
__device__ float g_rope[S_ * HD_];

// ---------------------------------------------------------------------------
__global__ void rope_table_kernel() {
    int idx = blockIdx.x * blockDim.x + threadIdx.x;
    if (idx >= S_ * 64) return;
    int pos = idx >> 6;
    int i   = idx & 63;
    float invf = 1.0f / powf(10000.0f, (float)i / 64.0f);
    float ang  = (float)pos * invf;
    g_rope[pos * HD_ + i]      = cosf(ang);
    g_rope[pos * HD_ + 64 + i] = sinf(ang);
}

// ---------------------------------------------------------------------------
__global__ __launch_bounds__(256) void rmsnorm_kernel(
    const float* __restrict__ x, const float* __restrict__ w,
    float* __restrict__ out)
{
    int row = blockIdx.x;
    const float* xr = x + (size_t)row * H_;
    float ss = 0.f;
#pragma unroll
    for (int it = 0; it < H_ / (256 * 4); it++) {
        int c = (it * 256 + threadIdx.x) * 4;
        float4 t = *(const float4*)(xr + c);
        ss += t.x * t.x + t.y * t.y + t.z * t.z + t.w * t.w;
    }
#pragma unroll
    for (int o = 16; o; o >>= 1) ss += __shfl_xor_sync(0xffffffffu, ss, o);
    __shared__ float red[8];
    if ((threadIdx.x & 31) == 0) red[threadIdx.x >> 5] = ss;
    __syncthreads();
    float tot = 0.f;
#pragma unroll
    for (int i = 0; i < 8; i++) tot += red[i];
    float inv = rsqrtf(tot * (1.0f / H_) + EPSF);
    float* orow = out + (size_t)row * H_;
#pragma unroll
    for (int it = 0; it < H_ / (256 * 4); it++) {
        int c = (it * 256 + threadIdx.x) * 4;
        float4 t  = *(const float4*)(xr + c);
        float4 wv = *(const float4*)(w + c);
        t.x = wv.x * t.x * inv; t.y = wv.y * t.y * inv;
        t.z = wv.z * t.z * inv; t.w = wv.w * t.w * inv;
        *(float4*)(orow + c) = t;
    }
}

// ---------------------------------------------------------------------------
// TF32 tensor-core GEMM: C[M,N] = A[M,K] @ B[K,N] (+addend), row-major.
// 128x128 block, BK=32, 256 threads (8 warps), warp tile 64x32 via m16n8k8.
// ---------------------------------------------------------------------------
#define GA_STRIDE 36            // As row stride (32 + 4)
#define GB_STRIDE 132           // Bs row stride (128 + 4)
#define GA_BUF (128 * GA_STRIDE)
#define GB_BUF (32 * GB_STRIDE)
#define GEMM_SMEM ((2 * GA_BUF + 2 * GB_BUF) * 4)

__device__ __forceinline__ unsigned f2tf32(float x) {
    unsigned u;
    asm("cvt.rna.tf32.f32 %0, %1;" : "=r"(u) : "f"(x));
    return u;
}

__device__ __forceinline__ void mma_tf32(float* c, const unsigned* a, const unsigned* b) {
    asm volatile(
        "mma.sync.aligned.m16n8k8.row.col.f32.tf32.tf32.f32 "
        "{%0,%1,%2,%3},{%4,%5,%6,%7},{%8,%9},{%0,%1,%2,%3};\n"
        : "+f"(c[0]), "+f"(c[1]), "+f"(c[2]), "+f"(c[3])
        : "r"(a[0]), "r"(a[1]), "r"(a[2]), "r"(a[3]), "r"(b[0]), "r"(b[1]));
}

__global__ __launch_bounds__(256) void gemm_tf32_kernel(
    const float* __restrict__ A, const float* __restrict__ B,
    const float* __restrict__ addend, float* __restrict__ C,
    int M, int N, int K)
{
    extern __shared__ float sm[];
    float* AsBase = sm;                 // [2][128][36]
    float* BsBase = sm + 2 * GA_BUF;    // [2][32][132]

    int tid = threadIdx.x;
    int bm = blockIdx.y * 128, bn = blockIdx.x * 128;
    int wid = tid >> 5, lane = tid & 31;
    int wm = (wid & 1) * 64;
    int wn = (wid >> 1) * 32;
    int grp = lane >> 2, qk = lane & 3;

    // global load mapping
    int arow = tid >> 3;           // 0..31 (+32*s)
    int acol = (tid & 7) * 4;      // 0..28
    int brow = tid >> 5;           // 0..7 (+8*s)
    int bcol = (tid & 31) * 4;     // 0..124

    const float* Ag = A + (size_t)(bm + arow) * K + acol;
    const float* Bg = B + (size_t)brow * N + bn + bcol;

    float acc[4][4][4];
#pragma unroll
    for (int mt = 0; mt < 4; mt++)
#pragma unroll
        for (int nt = 0; nt < 4; nt++)
#pragma unroll
            for (int r = 0; r < 4; r++) acc[mt][nt][r] = 0.f;

    int nk = K / 32;
    float4 pa[4], pb[4];

    // prologue: load tile 0
#pragma unroll
    for (int s = 0; s < 4; s++)
        pa[s] = *(const float4*)(Ag + (size_t)(32 * s) * K);
#pragma unroll
    for (int s = 0; s < 4; s++)
        pb[s] = *(const float4*)(Bg + (size_t)(8 * s) * N);

    {
        float* As = AsBase;
        float* Bs = BsBase;
#pragma unroll
        for (int s = 0; s < 4; s++) {
            unsigned* d = (unsigned*)(As + (arow + 32 * s) * GA_STRIDE + acol);
            d[0] = f2tf32(pa[s].x); d[1] = f2tf32(pa[s].y);
            d[2] = f2tf32(pa[s].z); d[3] = f2tf32(pa[s].w);
        }
#pragma unroll
        for (int s = 0; s < 4; s++) {
            unsigned* d = (unsigned*)(Bs + (brow + 8 * s) * GB_STRIDE + bcol);
            d[0] = f2tf32(pb[s].x); d[1] = f2tf32(pb[s].y);
            d[2] = f2tf32(pb[s].z); d[3] = f2tf32(pb[s].w);
        }
    }
    __syncthreads();

    for (int kt = 0; kt < nk; kt++) {
        int cur = kt & 1, nxt = cur ^ 1;
        const unsigned* Au = (const unsigned*)(AsBase + cur * GA_BUF);
        const unsigned* Bu = (const unsigned*)(BsBase + cur * GB_BUF);

        // prefetch next tile (global)
        if (kt + 1 < nk) {
            const float* Ag2 = Ag + (size_t)(kt + 1) * 32;
            const float* Bg2 = Bg + (size_t)(kt + 1) * 32 * N;
#pragma unroll
            for (int s = 0; s < 4; s++)
                pa[s] = *(const float4*)(Ag2 + (size_t)(32 * s) * K);
#pragma unroll
            for (int s = 0; s < 4; s++)
                pb[s] = *(const float4*)(Bg2 + (size_t)(8 * s) * N);
        }

        // compute on current tile: 4 k-steps of 8
#pragma unroll
        for (int ks = 0; ks < 4; ks++) {
            int k0 = ks * 8;
            unsigned afr[4][4], bfr[4][2];
#pragma unroll
            for (int mt = 0; mt < 4; mt++) {
                int mr = wm + mt * 16 + grp;
                afr[mt][0] = Au[(mr)     * GA_STRIDE + k0 + qk];
                afr[mt][1] = Au[(mr + 8) * GA_STRIDE + k0 + qk];
                afr[mt][2] = Au[(mr)     * GA_STRIDE + k0 + qk + 4];
                afr[mt][3] = Au[(mr + 8) * GA_STRIDE + k0 + qk + 4];
            }
#pragma unroll
            for (int nt = 0; nt < 4; nt++) {
                int nc = wn + nt * 8 + grp;
                bfr[nt][0] = Bu[(k0 + qk)     * GB_STRIDE + nc];
                bfr[nt][1] = Bu[(k0 + qk + 4) * GB_STRIDE + nc];
            }
#pragma unroll
            for (int mt = 0; mt < 4; mt++)
#pragma unroll
                for (int nt = 0; nt < 4; nt++)
                    mma_tf32(acc[mt][nt], afr[mt], bfr[nt]);
        }

        // store next tile to smem
        if (kt + 1 < nk) {
            float* As = AsBase + nxt * GA_BUF;
            float* Bs = BsBase + nxt * GB_BUF;
#pragma unroll
            for (int s = 0; s < 4; s++) {
                unsigned* d = (unsigned*)(As + (arow + 32 * s) * GA_STRIDE + acol);
                d[0] = f2tf32(pa[s].x); d[1] = f2tf32(pa[s].y);
                d[2] = f2tf32(pa[s].z); d[3] = f2tf32(pa[s].w);
            }
#pragma unroll
            for (int s = 0; s < 4; s++) {
                unsigned* d = (unsigned*)(Bs + (brow + 8 * s) * GB_STRIDE + bcol);
                d[0] = f2tf32(pb[s].x); d[1] = f2tf32(pb[s].y);
                d[2] = f2tf32(pb[s].z); d[3] = f2tf32(pb[s].w);
            }
        }
        __syncthreads();
    }

    // epilogue
#pragma unroll
    for (int mt = 0; mt < 4; mt++) {
#pragma unroll
        for (int nt = 0; nt < 4; nt++) {
            int row0 = bm + wm + mt * 16 + grp;
            int col  = bn + wn + nt * 8 + qk * 2;
            float* c0 = C + (size_t)row0 * N + col;
            float* c1 = C + (size_t)(row0 + 8) * N + col;
            if (addend) {
                const float* a0 = addend + (size_t)row0 * N + col;
                const float* a1 = addend + (size_t)(row0 + 8) * N + col;
                float2 v0 = make_float2(acc[mt][nt][0] + a0[0], acc[mt][nt][1] + a0[1]);
                float2 v1 = make_float2(acc[mt][nt][2] + a1[0], acc[mt][nt][3] + a1[1]);
                *(float2*)c0 = v0;
                *(float2*)c1 = v1;
            } else {
                *(float2*)c0 = make_float2(acc[mt][nt][0], acc[mt][nt][1]);
                *(float2*)c1 = make_float2(acc[mt][nt][2], acc[mt][nt][3]);
            }
        }
    }
}

// ---------------------------------------------------------------------------
// RoPE + QK RMSNorm (in place). One warp per (token, head). hd=128.
// ---------------------------------------------------------------------------
__global__ __launch_bounds__(128) void rope_norm_kernel(
    float* __restrict__ qk, const float* __restrict__ w, int nheads)
{
    int tok  = blockIdx.x;
    int warp = threadIdx.x >> 5;
    int lane = threadIdx.x & 31;
    int head = blockIdx.y * 4 + warp;
    int pos  = tok % S_;

    float* base = qk + ((size_t)tok * nheads + head) * HD_;
    float a0 = base[lane];      float a1 = base[lane + 32];
    float b0 = base[lane + 64]; float b1 = base[lane + 96];

    const float* rc = g_rope + (size_t)pos * HD_;
    float c0 = rc[lane],      s0 = rc[64 + lane];
    float c1 = rc[lane + 32], s1 = rc[96 + lane];

    float r0  = a0 * c0 - b0 * s0;
    float r64 = b0 * c0 + a0 * s0;
    float r32 = a1 * c1 - b1 * s1;
    float r96 = b1 * c1 + a1 * s1;

    float ss = r0 * r0 + r32 * r32 + r64 * r64 + r96 * r96;
#pragma unroll
    for (int o = 16; o; o >>= 1) ss += __shfl_xor_sync(0xffffffffu, ss, o);
    float inv = rsqrtf(ss * (1.0f / HD_) + EPSF);

    base[lane]      = w[lane]      * r0  * inv;
    base[lane + 32] = w[lane + 32] * r32 * inv;
    base[lane + 64] = w[lane + 64] * r64 * inv;
    base[lane + 96] = w[lane + 96] * r96 * inv;
}

// ---------------------------------------------------------------------------
// Flash attention (causal, GQA). BQ=128, BK=64, hd=128, 256 threads.
// ty = tid/8 (32 row-groups of 4), tx = tid%8 (8 col-groups of 8).
// Per thread: S tile 4x8, O tile 4x16.
// ---------------------------------------------------------------------------
#define FBQ 128
#define FBK 64
#define QS_STRIDE 131
#define KS_STRIDE 131
#define VS_STRIDE 132
#define PS_STRIDE 65
#define FLASH_SMEM ((FBQ*QS_STRIDE + FBK*KS_STRIDE + FBK*VS_STRIDE + FBQ*PS_STRIDE) * 4)

__global__ __launch_bounds__(256) void flash_kernel(
    const float* __restrict__ q, const float* __restrict__ k,
    const float* __restrict__ v, float* __restrict__ o)
{
    extern __shared__ float sm[];
    float* Qs = sm;
    float* Ks = Qs + FBQ * QS_STRIDE;
    float* Vs = Ks + FBK * KS_STRIDE;
    float* Ps = Vs + FBK * VS_STRIDE;

    int qb = gridDim.x - 1 - blockIdx.x;
    int bh = blockIdx.y;
    int b  = bh / NH_, h = bh % NH_;
    int kvh = h / (NH_ / NKV_);

    int tid = threadIdx.x;
    int ty = tid >> 3, tx = tid & 7;

    const float scale = 0.08838834764831845f;

    const float* qbase = q + ((size_t)(b * S_ + qb * FBQ) * NH_ + h) * HD_;
    for (int i = tid; i < FBQ * (HD_ / 4); i += 256) {
        int r  = i >> 5;
        int c4 = (i & 31) * 4;
        float4 t = *(const float4*)(qbase + (size_t)r * NH_ * HD_ + c4);
        float* dst = Qs + r * QS_STRIDE + c4;
        dst[0] = t.x * scale; dst[1] = t.y * scale;
        dst[2] = t.z * scale; dst[3] = t.w * scale;
    }

    float m_i[4], l_i[4], acc[4][16];
#pragma unroll
    for (int i = 0; i < 4; i++) {
        m_i[i] = -1e30f; l_i[i] = 0.f;
#pragma unroll
        for (int c = 0; c < 16; c++) acc[i][c] = 0.f;
    }

    int nkb = 2 * qb + 2;   // k-tiles covering [0, (qb+1)*128)
    for (int kb = 0; kb < nkb; kb++) {
        __syncthreads();
        const float* kbase = k + ((size_t)(b * S_ + kb * FBK) * NKV_ + kvh) * HD_;
        const float* vbase = v + ((size_t)(b * S_ + kb * FBK) * NKV_ + kvh) * HD_;
        for (int i = tid; i < FBK * (HD_ / 4); i += 256) {
            int r  = i >> 5;
            int c4 = (i & 31) * 4;
            float4 tk = *(const float4*)(kbase + (size_t)r * NKV_ * HD_ + c4);
            float* kd = Ks + r * KS_STRIDE + c4;
            kd[0] = tk.x; kd[1] = tk.y; kd[2] = tk.z; kd[3] = tk.w;
            float4 tv = *(const float4*)(vbase + (size_t)r * NKV_ * HD_ + c4);
            *(float4*)(Vs + r * VS_STRIDE + c4) = tv;
        }
        __syncthreads();

        float s[4][8];
#pragma unroll
        for (int i = 0; i < 4; i++)
#pragma unroll
            for (int j = 0; j < 8; j++) s[i][j] = 0.f;

#pragma unroll 8
        for (int kk = 0; kk < HD_; kk++) {
            float qr[4], kr[8];
#pragma unroll
            for (int i = 0; i < 4; i++) qr[i] = Qs[(ty * 4 + i) * QS_STRIDE + kk];
#pragma unroll
            for (int j = 0; j < 8; j++) kr[j] = Ks[(tx * 8 + j) * KS_STRIDE + kk];
#pragma unroll
            for (int i = 0; i < 4; i++)
#pragma unroll
                for (int j = 0; j < 8; j++)
                    s[i][j] += qr[i] * kr[j];
        }

        // causal mask on the last two (diagonal-straddling) k-tiles
        if (kb >= 2 * qb) {
            int rbase = qb * FBQ + ty * 4;
            int cbase = kb * FBK + tx * 8;
#pragma unroll
            for (int i = 0; i < 4; i++)
#pragma unroll
                for (int j = 0; j < 8; j++)
                    if (cbase + j > rbase + i) s[i][j] = -1e30f;
        }

#pragma unroll
        for (int i = 0; i < 4; i++) {
            float mx = s[i][0];
#pragma unroll
            for (int j = 1; j < 8; j++) mx = fmaxf(mx, s[i][j]);
            mx = fmaxf(mx, __shfl_xor_sync(0xffffffffu, mx, 1));
            mx = fmaxf(mx, __shfl_xor_sync(0xffffffffu, mx, 2));
            mx = fmaxf(mx, __shfl_xor_sync(0xffffffffu, mx, 4));
            float m_new = fmaxf(m_i[i], mx);
            float corr  = expf(m_i[i] - m_new);
            m_i[i] = m_new;
            float rs = 0.f;
#pragma unroll
            for (int j = 0; j < 8; j++) {
                float p = expf(s[i][j] - m_new);
                rs += p;
                Ps[(ty * 4 + i) * PS_STRIDE + tx * 8 + j] = p;
            }
            rs += __shfl_xor_sync(0xffffffffu, rs, 1);
            rs += __shfl_xor_sync(0xffffffffu, rs, 2);
            rs += __shfl_xor_sync(0xffffffffu, rs, 4);
            l_i[i] = l_i[i] * corr + rs;
#pragma unroll
            for (int c = 0; c < 16; c++) acc[i][c] *= corr;
        }
        __syncwarp();

#pragma unroll 4
        for (int j = 0; j < FBK; j++) {
            float pr[4];
#pragma unroll
            for (int i = 0; i < 4; i++) pr[i] = Ps[(ty * 4 + i) * PS_STRIDE + j];
            const float* vrow = Vs + j * VS_STRIDE + tx * 16;
            float4 v0 = *(const float4*)(vrow);
            float4 v1 = *(const float4*)(vrow + 4);
            float4 v2 = *(const float4*)(vrow + 8);
            float4 v3 = *(const float4*)(vrow + 12);
#pragma unroll
            for (int i = 0; i < 4; i++) {
                acc[i][0]  += pr[i] * v0.x; acc[i][1]  += pr[i] * v0.y;
                acc[i][2]  += pr[i] * v0.z; acc[i][3]  += pr[i] * v0.w;
                acc[i][4]  += pr[i] * v1.x; acc[i][5]  += pr[i] * v1.y;
                acc[i][6]  += pr[i] * v1.z; acc[i][7]  += pr[i] * v1.w;
                acc[i][8]  += pr[i] * v2.x; acc[i][9]  += pr[i] * v2.y;
                acc[i][10] += pr[i] * v2.z; acc[i][11] += pr[i] * v2.w;
                acc[i][12] += pr[i] * v3.x; acc[i][13] += pr[i] * v3.y;
                acc[i][14] += pr[i] * v3.z; acc[i][15] += pr[i] * v3.w;
            }
        }
    }

    float* obase = o + ((size_t)(b * S_ + qb * FBQ) * NH_ + h) * HD_;
#pragma unroll
    for (int i = 0; i < 4; i++) {
        float inv = 1.0f / l_i[i];
        int r = ty * 4 + i;
        float* dst = obase + (size_t)r * NH_ * HD_ + tx * 16;
        float4 r0 = make_float4(acc[i][0]*inv,  acc[i][1]*inv,  acc[i][2]*inv,  acc[i][3]*inv);
        float4 r1 = make_float4(acc[i][4]*inv,  acc[i][5]*inv,  acc[i][6]*inv,  acc[i][7]*inv);
        float4 r2 = make_float4(acc[i][8]*inv,  acc[i][9]*inv,  acc[i][10]*inv, acc[i][11]*inv);
        float4 r3 = make_float4(acc[i][12]*inv, acc[i][13]*inv, acc[i][14]*inv, acc[i][15]*inv);
        *(float4*)(dst)      = r0;
        *(float4*)(dst + 4)  = r1;
        *(float4*)(dst + 8)  = r2;
        *(float4*)(dst + 12) = r3;
    }
}

// ---------------------------------------------------------------------------
__global__ __launch_bounds__(256) void swiglu_kernel(
    float* __restrict__ g, const float* __restrict__ u)
{
    int idx = blockIdx.x * 256 + threadIdx.x;
    if (idx >= NTOK * (I_ / 4)) return;
    float4 gv = ((float4*)g)[idx];
    float4 uv = ((const float4*)u)[idx];
    gv.x = gv.x / (1.f + expf(-gv.x)) * uv.x;
    gv.y = gv.y / (1.f + expf(-gv.y)) * uv.y;
    gv.z = gv.z / (1.f + expf(-gv.z)) * uv.z;
    gv.w = gv.w / (1.f + expf(-gv.w)) * uv.w;
    ((float4*)g)[idx] = gv;
}

// ---------------------------------------------------------------------------
extern "C" void kernel_launch(void* const* d_in, const int* in_sizes, int n_in,
                              void* d_out, int out_size)
{
    const float* hidden = (const float*)d_in[0];
    const float* ln1_w = (const float*)d_in[3];
    const float* Wq    = (const float*)d_in[4];
    const float* Wk    = (const float*)d_in[5];
    const float* Wv    = (const float*)d_in[6];
    const float* Wo    = (const float*)d_in[7];
    const float* qn_w  = (const float*)d_in[8];
    const float* kn_w  = (const float*)d_in[9];
    const float* ln2_w = (const float*)d_in[10];
    const float* Wg    = (const float*)d_in[11];
    const float* Wu    = (const float*)d_in[12];
    const float* Wd    = (const float*)d_in[13];
    float* out = (float*)d_out;

    float *p_h, *p_q, *p_k, *p_v, *p_o, *p_x, *p_g, *p_u;
    cudaGetSymbolAddress((void**)&p_h, g_h);
    cudaGetSymbolAddress((void**)&p_q, g_q);
    cudaGetSymbolAddress((void**)&p_k, g_k);
    cudaGetSymbolAddress((void**)&p_v, g_v);
    cudaGetSymbolAddress((void**)&p_o, g_o);
    cudaGetSymbolAddress((void**)&p_x, g_x);
    cudaGetSymbolAddress((void**)&p_g, g_g);
    cudaGetSymbolAddress((void**)&p_u, g_u);

    cudaFuncSetAttribute(flash_kernel,
                         cudaFuncAttributeMaxDynamicSharedMemorySize, FLASH_SMEM);
    cudaFuncSetAttribute(gemm_tf32_kernel,
                         cudaFuncAttributeMaxDynamicSharedMemorySize, GEMM_SMEM);

    rope_table_kernel<<<(S_ * 64 + 255) / 256, 256>>>();

    // Attention block
    rmsnorm_kernel<<<NTOK, 256>>>(hidden, ln1_w, p_h);
    gemm_tf32_kernel<<<dim3((NH_ * HD_) / 128, NTOK / 128), 256, GEMM_SMEM>>>(p_h, Wq, nullptr, p_q, NTOK, NH_ * HD_, H_);
    gemm_tf32_kernel<<<dim3((NKV_ * HD_) / 128, NTOK / 128), 256, GEMM_SMEM>>>(p_h, Wk, nullptr, p_k, NTOK, NKV_ * HD_, H_);
    gemm_tf32_kernel<<<dim3((NKV_ * HD_) / 128, NTOK / 128), 256, GEMM_SMEM>>>(p_h, Wv, nullptr, p_v, NTOK, NKV_ * HD_, H_);
    rope_norm_kernel<<<dim3(NTOK, NH_ / 4), 128>>>(p_q, qn_w, NH_);
    rope_norm_kernel<<<dim3(NTOK, NKV_ / 4), 128>>>(p_k, kn_w, NKV_);
    flash_kernel<<<dim3(S_ / FBQ, B_ * NH_), 256, FLASH_SMEM>>>(p_q, p_k, p_v, p_o);
    gemm_tf32_kernel<<<dim3(H_ / 128, NTOK / 128), 256, GEMM_SMEM>>>(p_o, Wo, hidden, p_x, NTOK, H_, H_);

    // MLP block
    rmsnorm_kernel<<<NTOK, 256>>>(p_x, ln2_w, p_h);
    gemm_tf32_kernel<<<dim3(I_ / 128, NTOK / 128), 256, GEMM_SMEM>>>(p_h, Wg, nullptr, p_g, NTOK, I_, H_);
    gemm_tf32_kernel<<<dim3(I_ / 128, NTOK / 128), 256, GEMM_SMEM>>>(p_h, Wu, nullptr, p_u, NTOK, I_, H_);
    swiglu_kernel<<<(NTOK * (I_ / 4) + 255) / 256, 256>>>(p_g, p_u);
    gemm_tf32_kernel<<<dim3(H_ / 128, NTOK / 128), 256, GEMM_SMEM>>>(p_g, Wd, p_x, out, NTOK, H_, I_);
}

// round 4
// speedup vs baseline: 3.2586x; 1.4385x over previous
#include <cuda_runtime.h>
#include <math.h>

#define B_   2
#define S_   2048
#define H_   2048
#define NH_  16
#define NKV_ 4
#define HD_  128
#define I_   8192
#define NTOK (B_*S_)
#define EPSF 1e-6f

// ---------------------------------------------------------------------------
__device__ float g_h [NTOK * H_];
__device__ float g_q [NTOK * NH_ * HD_];
__device__ float g_k [NTOK * NKV_ * HD_];
__device__ float g_v [NTOK * NKV_ * HD_];
__device__ float g_o [NTOK * NH_ * HD_];
__device__ float g_x [NTOK * H_];
__device__ float g_g [NTOK * I_];
__device__ float g_u [NTOK * I_];
__device__ float g_rope[S_ * HD_];

// ---------------------------------------------------------------------------
__global__ void rope_table_kernel() {
    int idx = blockIdx.x * blockDim.x + threadIdx.x;
    if (idx >= S_ * 64) return;
    int pos = idx >> 6;
    int i   = idx & 63;
    float invf = 1.0f / powf(10000.0f, (float)i / 64.0f);
    float ang  = (float)pos * invf;
    g_rope[pos * HD_ + i]      = cosf(ang);
    g_rope[pos * HD_ + 64 + i] = sinf(ang);
}

// ---------------------------------------------------------------------------
__global__ __launch_bounds__(256) void rmsnorm_kernel(
    const float* __restrict__ x, const float* __restrict__ w,
    float* __restrict__ out)
{
    int row = blockIdx.x;
    const float* xr = x + (size_t)row * H_;
    float ss = 0.f;
#pragma unroll
    for (int it = 0; it < H_ / (256 * 4); it++) {
        int c = (it * 256 + threadIdx.x) * 4;
        float4 t = *(const float4*)(xr + c);
        ss += t.x * t.x + t.y * t.y + t.z * t.z + t.w * t.w;
    }
#pragma unroll
    for (int o = 16; o; o >>= 1) ss += __shfl_xor_sync(0xffffffffu, ss, o);
    __shared__ float red[8];
    if ((threadIdx.x & 31) == 0) red[threadIdx.x >> 5] = ss;
    __syncthreads();
    float tot = 0.f;
#pragma unroll
    for (int i = 0; i < 8; i++) tot += red[i];
    float inv = rsqrtf(tot * (1.0f / H_) + EPSF);
    float* orow = out + (size_t)row * H_;
#pragma unroll
    for (int it = 0; it < H_ / (256 * 4); it++) {
        int c = (it * 256 + threadIdx.x) * 4;
        float4 t  = *(const float4*)(xr + c);
        float4 wv = *(const float4*)(w + c);
        t.x = wv.x * t.x * inv; t.y = wv.y * t.y * inv;
        t.z = wv.z * t.z * inv; t.w = wv.w * t.w * inv;
        *(float4*)(orow + c) = t;
    }
}

// ---------------------------------------------------------------------------
// TF32 tensor-core GEMM, 128x128x32 tiles, 8 warps. Optional second (B,C)
// pair selected by blockIdx.z (used to fuse the K and V projections).
// ---------------------------------------------------------------------------
#define GA_STRIDE 36
#define GB_STRIDE 132
#define GA_BUF (128 * GA_STRIDE)
#define GB_BUF (32 * GB_STRIDE)
#define GEMM_SMEM ((2 * GA_BUF + 2 * GB_BUF) * 4)

__device__ __forceinline__ unsigned f2tf32(float x) {
    unsigned u;
    asm("cvt.rna.tf32.f32 %0, %1;" : "=r"(u) : "f"(x));
    return u;
}

__device__ __forceinline__ void mma_tf32(float* c, const unsigned* a, const unsigned* b) {
    asm volatile(
        "mma.sync.aligned.m16n8k8.row.col.f32.tf32.tf32.f32 "
        "{%0,%1,%2,%3},{%4,%5,%6,%7},{%8,%9},{%0,%1,%2,%3};\n"
        : "+f"(c[0]), "+f"(c[1]), "+f"(c[2]), "+f"(c[3])
        : "r"(a[0]), "r"(a[1]), "r"(a[2]), "r"(a[3]), "r"(b[0]), "r"(b[1]));
}

__global__ __launch_bounds__(256) void gemm_tf32_kernel(
    const float* __restrict__ A, const float* __restrict__ B,
    const float* __restrict__ B2,
    const float* __restrict__ addend, float* __restrict__ C,
    float* __restrict__ C2,
    int M, int N, int K)
{
    extern __shared__ float sm[];
    float* AsBase = sm;
    float* BsBase = sm + 2 * GA_BUF;

    if (blockIdx.z == 1) { B = B2; C = C2; }

    int tid = threadIdx.x;
    int bm = blockIdx.y * 128, bn = blockIdx.x * 128;
    int wid = tid >> 5, lane = tid & 31;
    int wm = (wid & 1) * 64;
    int wn = (wid >> 1) * 32;
    int grp = lane >> 2, qk = lane & 3;

    int arow = tid >> 3;
    int acol = (tid & 7) * 4;
    int brow = tid >> 5;
    int bcol = (tid & 31) * 4;

    const float* Ag = A + (size_t)(bm + arow) * K + acol;
    const float* Bg = B + (size_t)brow * N + bn + bcol;

    float acc[4][4][4];
#pragma unroll
    for (int mt = 0; mt < 4; mt++)
#pragma unroll
        for (int nt = 0; nt < 4; nt++)
#pragma unroll
            for (int r = 0; r < 4; r++) acc[mt][nt][r] = 0.f;

    int nk = K / 32;
    float4 pa[4], pb[4];

#pragma unroll
    for (int s = 0; s < 4; s++)
        pa[s] = *(const float4*)(Ag + (size_t)(32 * s) * K);
#pragma unroll
    for (int s = 0; s < 4; s++)
        pb[s] = *(const float4*)(Bg + (size_t)(8 * s) * N);

    {
        float* As = AsBase;
        float* Bs = BsBase;
#pragma unroll
        for (int s = 0; s < 4; s++) {
            unsigned* d = (unsigned*)(As + (arow + 32 * s) * GA_STRIDE + acol);
            d[0] = f2tf32(pa[s].x); d[1] = f2tf32(pa[s].y);
            d[2] = f2tf32(pa[s].z); d[3] = f2tf32(pa[s].w);
        }
#pragma unroll
        for (int s = 0; s < 4; s++) {
            unsigned* d = (unsigned*)(Bs + (brow + 8 * s) * GB_STRIDE + bcol);
            d[0] = f2tf32(pb[s].x); d[1] = f2tf32(pb[s].y);
            d[2] = f2tf32(pb[s].z); d[3] = f2tf32(pb[s].w);
        }
    }
    __syncthreads();

    for (int kt = 0; kt < nk; kt++) {
        int cur = kt & 1, nxt = cur ^ 1;
        const unsigned* Au = (const unsigned*)(AsBase + cur * GA_BUF);
        const unsigned* Bu = (const unsigned*)(BsBase + cur * GB_BUF);

        if (kt + 1 < nk) {
            const float* Ag2 = Ag + (size_t)(kt + 1) * 32;
            const float* Bg2 = Bg + (size_t)(kt + 1) * 32 * N;
#pragma unroll
            for (int s = 0; s < 4; s++)
                pa[s] = *(const float4*)(Ag2 + (size_t)(32 * s) * K);
#pragma unroll
            for (int s = 0; s < 4; s++)
                pb[s] = *(const float4*)(Bg2 + (size_t)(8 * s) * N);
        }

#pragma unroll
        for (int ks = 0; ks < 4; ks++) {
            int k0 = ks * 8;
            unsigned afr[4][4], bfr[4][2];
#pragma unroll
            for (int mt = 0; mt < 4; mt++) {
                int mr = wm + mt * 16 + grp;
                afr[mt][0] = Au[(mr)     * GA_STRIDE + k0 + qk];
                afr[mt][1] = Au[(mr + 8) * GA_STRIDE + k0 + qk];
                afr[mt][2] = Au[(mr)     * GA_STRIDE + k0 + qk + 4];
                afr[mt][3] = Au[(mr + 8) * GA_STRIDE + k0 + qk + 4];
            }
#pragma unroll
            for (int nt = 0; nt < 4; nt++) {
                int nc = wn + nt * 8 + grp;
                bfr[nt][0] = Bu[(k0 + qk)     * GB_STRIDE + nc];
                bfr[nt][1] = Bu[(k0 + qk + 4) * GB_STRIDE + nc];
            }
#pragma unroll
            for (int mt = 0; mt < 4; mt++)
#pragma unroll
                for (int nt = 0; nt < 4; nt++)
                    mma_tf32(acc[mt][nt], afr[mt], bfr[nt]);
        }

        if (kt + 1 < nk) {
            float* As = AsBase + nxt * GA_BUF;
            float* Bs = BsBase + nxt * GB_BUF;
#pragma unroll
            for (int s = 0; s < 4; s++) {
                unsigned* d = (unsigned*)(As + (arow + 32 * s) * GA_STRIDE + acol);
                d[0] = f2tf32(pa[s].x); d[1] = f2tf32(pa[s].y);
                d[2] = f2tf32(pa[s].z); d[3] = f2tf32(pa[s].w);
            }
#pragma unroll
            for (int s = 0; s < 4; s++) {
                unsigned* d = (unsigned*)(Bs + (brow + 8 * s) * GB_STRIDE + bcol);
                d[0] = f2tf32(pb[s].x); d[1] = f2tf32(pb[s].y);
                d[2] = f2tf32(pb[s].z); d[3] = f2tf32(pb[s].w);
            }
        }
        __syncthreads();
    }

#pragma unroll
    for (int mt = 0; mt < 4; mt++) {
#pragma unroll
        for (int nt = 0; nt < 4; nt++) {
            int row0 = bm + wm + mt * 16 + grp;
            int col  = bn + wn + nt * 8 + qk * 2;
            float* c0 = C + (size_t)row0 * N + col;
            float* c1 = C + (size_t)(row0 + 8) * N + col;
            if (addend) {
                const float* a0 = addend + (size_t)row0 * N + col;
                const float* a1 = addend + (size_t)(row0 + 8) * N + col;
                *(float2*)c0 = make_float2(acc[mt][nt][0] + a0[0], acc[mt][nt][1] + a0[1]);
                *(float2*)c1 = make_float2(acc[mt][nt][2] + a1[0], acc[mt][nt][3] + a1[1]);
            } else {
                *(float2*)c0 = make_float2(acc[mt][nt][0], acc[mt][nt][1]);
                *(float2*)c1 = make_float2(acc[mt][nt][2], acc[mt][nt][3]);
            }
        }
    }
}

// ---------------------------------------------------------------------------
__global__ __launch_bounds__(128) void rope_norm_kernel(
    float* __restrict__ qkp, const float* __restrict__ w, int nheads)
{
    int tok  = blockIdx.x;
    int warp = threadIdx.x >> 5;
    int lane = threadIdx.x & 31;
    int head = blockIdx.y * 4 + warp;
    int pos  = tok % S_;

    float* base = qkp + ((size_t)tok * nheads + head) * HD_;
    float a0 = base[lane];      float a1 = base[lane + 32];
    float b0 = base[lane + 64]; float b1 = base[lane + 96];

    const float* rc = g_rope + (size_t)pos * HD_;
    float c0 = rc[lane],      s0 = rc[64 + lane];
    float c1 = rc[lane + 32], s1 = rc[96 + lane];

    float r0  = a0 * c0 - b0 * s0;
    float r64 = b0 * c0 + a0 * s0;
    float r32 = a1 * c1 - b1 * s1;
    float r96 = b1 * c1 + a1 * s1;

    float ss = r0 * r0 + r32 * r32 + r64 * r64 + r96 * r96;
#pragma unroll
    for (int o = 16; o; o >>= 1) ss += __shfl_xor_sync(0xffffffffu, ss, o);
    float inv = rsqrtf(ss * (1.0f / HD_) + EPSF);

    base[lane]      = w[lane]      * r0  * inv;
    base[lane + 32] = w[lane + 32] * r32 * inv;
    base[lane + 64] = w[lane + 64] * r64 * inv;
    base[lane + 96] = w[lane + 96] * r96 * inv;
}

// ---------------------------------------------------------------------------
// Tensor-core flash attention (causal, GQA). BQ=128, BK=64, hd=128,
// 256 threads (8 warps), warp tile = 16 Q rows. tf32 m16n8k8 MMA for
// both QK^T and PV. P re-fragmented through smem.
// ---------------------------------------------------------------------------
#define FBQ 128
#define FBK 64
#define FQS 132   // ≡4 mod 32
#define FKS 132
#define FVS 136   // ≡8 mod 32
#define FPS 68    // ≡4 mod 32
#define FLASH_SMEM ((FBQ*FQS + FBK*FKS + FBK*FVS + FBQ*FPS) * 4)

__global__ __launch_bounds__(256) void flash_kernel(
    const float* __restrict__ q, const float* __restrict__ k,
    const float* __restrict__ v, float* __restrict__ o)
{
    extern __shared__ float sm[];
    unsigned* Qs = (unsigned*)sm;
    unsigned* Ks = Qs + FBQ * FQS;
    unsigned* Vs = Ks + FBK * FKS;
    unsigned* Ps = Vs + FBK * FVS;

    int qb = gridDim.x - 1 - blockIdx.x;
    int bh = blockIdx.y;
    int b  = bh / NH_, h = bh % NH_;
    int kvh = h / (NH_ / NKV_);

    int tid = threadIdx.x;
    int wid = tid >> 5, lane = tid & 31;
    int wm = wid * 16;
    int grp = lane >> 2, qk = lane & 3;

    const float scale = 0.08838834764831845f;

    // load Q tile (scaled, tf32)
    const float* qbase = q + ((size_t)(b * S_ + qb * FBQ) * NH_ + h) * HD_;
    for (int i = tid; i < FBQ * (HD_ / 4); i += 256) {
        int r  = i >> 5;
        int c4 = (i & 31) * 4;
        float4 t = *(const float4*)(qbase + (size_t)r * NH_ * HD_ + c4);
        unsigned* dst = Qs + r * FQS + c4;
        dst[0] = f2tf32(t.x * scale); dst[1] = f2tf32(t.y * scale);
        dst[2] = f2tf32(t.z * scale); dst[3] = f2tf32(t.w * scale);
    }

    float m0 = -1e30f, m1 = -1e30f, l0 = 0.f, l1 = 0.f;
    float oacc[16][4];
#pragma unroll
    for (int nt = 0; nt < 16; nt++)
#pragma unroll
        for (int r = 0; r < 4; r++) oacc[nt][r] = 0.f;

    int nkb = 2 * qb + 2;
    for (int kb = 0; kb < nkb; kb++) {
        __syncthreads();
        const float* kbase = k + ((size_t)(b * S_ + kb * FBK) * NKV_ + kvh) * HD_;
        const float* vbase = v + ((size_t)(b * S_ + kb * FBK) * NKV_ + kvh) * HD_;
        for (int i = tid; i < FBK * (HD_ / 4); i += 256) {
            int r  = i >> 5;
            int c4 = (i & 31) * 4;
            float4 tk = *(const float4*)(kbase + (size_t)r * NKV_ * HD_ + c4);
            unsigned* kd = Ks + r * FKS + c4;
            kd[0] = f2tf32(tk.x); kd[1] = f2tf32(tk.y);
            kd[2] = f2tf32(tk.z); kd[3] = f2tf32(tk.w);
            float4 tv = *(const float4*)(vbase + (size_t)r * NKV_ * HD_ + c4);
            unsigned* vd = Vs + r * FVS + c4;
            vd[0] = f2tf32(tv.x); vd[1] = f2tf32(tv.y);
            vd[2] = f2tf32(tv.z); vd[3] = f2tf32(tv.w);
        }
        __syncthreads();

        // ---- S = Q K^T : warp tile 16x64, k=128 ----
        float s[8][4];
#pragma unroll
        for (int nt = 0; nt < 8; nt++)
#pragma unroll
            for (int r = 0; r < 4; r++) s[nt][r] = 0.f;

#pragma unroll
        for (int ks = 0; ks < 16; ks++) {
            int k0 = ks * 8;
            unsigned a[4];
            a[0] = Qs[(wm + grp)     * FQS + k0 + qk];
            a[1] = Qs[(wm + grp + 8) * FQS + k0 + qk];
            a[2] = Qs[(wm + grp)     * FQS + k0 + qk + 4];
            a[3] = Qs[(wm + grp + 8) * FQS + k0 + qk + 4];
#pragma unroll
            for (int nt = 0; nt < 8; nt++) {
                unsigned bfr[2];
                bfr[0] = Ks[(nt * 8 + grp) * FKS + k0 + qk];
                bfr[1] = Ks[(nt * 8 + grp) * FKS + k0 + qk + 4];
                mma_tf32(s[nt], a, bfr);
            }
        }

        // causal mask on diagonal-straddling tiles
        if (kb >= 2 * qb) {
            int r0 = qb * FBQ + wm + grp;
            int cb = kb * FBK + qk * 2;
#pragma unroll
            for (int nt = 0; nt < 8; nt++) {
                int c0 = cb + nt * 8;
                if (c0     > r0)     s[nt][0] = -1e30f;
                if (c0 + 1 > r0)     s[nt][1] = -1e30f;
                if (c0     > r0 + 8) s[nt][2] = -1e30f;
                if (c0 + 1 > r0 + 8) s[nt][3] = -1e30f;
            }
        }

        // ---- online softmax ----
        float mx0 = -1e30f, mx1 = -1e30f;
#pragma unroll
        for (int nt = 0; nt < 8; nt++) {
            mx0 = fmaxf(mx0, fmaxf(s[nt][0], s[nt][1]));
            mx1 = fmaxf(mx1, fmaxf(s[nt][2], s[nt][3]));
        }
        mx0 = fmaxf(mx0, __shfl_xor_sync(0xffffffffu, mx0, 1));
        mx0 = fmaxf(mx0, __shfl_xor_sync(0xffffffffu, mx0, 2));
        mx1 = fmaxf(mx1, __shfl_xor_sync(0xffffffffu, mx1, 1));
        mx1 = fmaxf(mx1, __shfl_xor_sync(0xffffffffu, mx1, 2));

        float mn0 = fmaxf(m0, mx0), mn1 = fmaxf(m1, mx1);
        float corr0 = __expf(m0 - mn0), corr1 = __expf(m1 - mn1);
        m0 = mn0; m1 = mn1;

        float rs0 = 0.f, rs1 = 0.f;
#pragma unroll
        for (int nt = 0; nt < 8; nt++) {
            float p0 = __expf(s[nt][0] - mn0);
            float p1 = __expf(s[nt][1] - mn0);
            float p2 = __expf(s[nt][2] - mn1);
            float p3 = __expf(s[nt][3] - mn1);
            rs0 += p0 + p1; rs1 += p2 + p3;
            unsigned* pr0 = Ps + (wm + grp)     * FPS + nt * 8 + qk * 2;
            unsigned* pr1 = Ps + (wm + grp + 8) * FPS + nt * 8 + qk * 2;
            pr0[0] = f2tf32(p0); pr0[1] = f2tf32(p1);
            pr1[0] = f2tf32(p2); pr1[1] = f2tf32(p3);
        }
        rs0 += __shfl_xor_sync(0xffffffffu, rs0, 1);
        rs0 += __shfl_xor_sync(0xffffffffu, rs0, 2);
        rs1 += __shfl_xor_sync(0xffffffffu, rs1, 1);
        rs1 += __shfl_xor_sync(0xffffffffu, rs1, 2);
        l0 = l0 * corr0 + rs0;
        l1 = l1 * corr1 + rs1;

#pragma unroll
        for (int nt = 0; nt < 16; nt++) {
            oacc[nt][0] *= corr0; oacc[nt][1] *= corr0;
            oacc[nt][2] *= corr1; oacc[nt][3] *= corr1;
        }
        __syncwarp();

        // ---- O += P V : warp tile 16x128, k=64 ----
#pragma unroll
        for (int ks = 0; ks < 8; ks++) {
            int k0 = ks * 8;
            unsigned a[4];
            a[0] = Ps[(wm + grp)     * FPS + k0 + qk];
            a[1] = Ps[(wm + grp + 8) * FPS + k0 + qk];
            a[2] = Ps[(wm + grp)     * FPS + k0 + qk + 4];
            a[3] = Ps[(wm + grp + 8) * FPS + k0 + qk + 4];
#pragma unroll
            for (int nt = 0; nt < 16; nt++) {
                unsigned bfr[2];
                bfr[0] = Vs[(k0 + qk)     * FVS + nt * 8 + grp];
                bfr[1] = Vs[(k0 + qk + 4) * FVS + nt * 8 + grp];
                mma_tf32(oacc[nt], a, bfr);
            }
        }
    }

    // epilogue
    float inv0 = 1.0f / l0, inv1 = 1.0f / l1;
    int r0 = qb * FBQ + wm + grp;
    float* out0 = o + ((size_t)(b * S_ + r0) * NH_ + h) * HD_;
    float* out1 = o + ((size_t)(b * S_ + r0 + 8) * NH_ + h) * HD_;
#pragma unroll
    for (int nt = 0; nt < 16; nt++) {
        int col = nt * 8 + qk * 2;
        *(float2*)(out0 + col) = make_float2(oacc[nt][0] * inv0, oacc[nt][1] * inv0);
        *(float2*)(out1 + col) = make_float2(oacc[nt][2] * inv1, oacc[nt][3] * inv1);
    }
}

// ---------------------------------------------------------------------------
__global__ __launch_bounds__(256) void swiglu_kernel(
    float* __restrict__ g, const float* __restrict__ u)
{
    int idx = blockIdx.x * 256 + threadIdx.x;
    if (idx >= NTOK * (I_ / 4)) return;
    float4 gv = ((float4*)g)[idx];
    float4 uv = ((const float4*)u)[idx];
    gv.x = gv.x / (1.f + __expf(-gv.x)) * uv.x;
    gv.y = gv.y / (1.f + __expf(-gv.y)) * uv.y;
    gv.z = gv.z / (1.f + __expf(-gv.z)) * uv.z;
    gv.w = gv.w / (1.f + __expf(-gv.w)) * uv.w;
    ((float4*)g)[idx] = gv;
}

// ---------------------------------------------------------------------------
extern "C" void kernel_launch(void* const* d_in, const int* in_sizes, int n_in,
                              void* d_out, int out_size)
{
    const float* hidden = (const float*)d_in[0];
    const float* ln1_w = (const float*)d_in[3];
    const float* Wq    = (const float*)d_in[4];
    const float* Wk    = (const float*)d_in[5];
    const float* Wv    = (const float*)d_in[6];
    const float* Wo    = (const float*)d_in[7];
    const float* qn_w  = (const float*)d_in[8];
    const float* kn_w  = (const float*)d_in[9];
    const float* ln2_w = (const float*)d_in[10];
    const float* Wg    = (const float*)d_in[11];
    const float* Wu    = (const float*)d_in[12];
    const float* Wd    = (const float*)d_in[13];
    float* out = (float*)d_out;

    float *p_h, *p_q, *p_k, *p_v, *p_o, *p_x, *p_g, *p_u;
    cudaGetSymbolAddress((void**)&p_h, g_h);
    cudaGetSymbolAddress((void**)&p_q, g_q);
    cudaGetSymbolAddress((void**)&p_k, g_k);
    cudaGetSymbolAddress((void**)&p_v, g_v);
    cudaGetSymbolAddress((void**)&p_o, g_o);
    cudaGetSymbolAddress((void**)&p_x, g_x);
    cudaGetSymbolAddress((void**)&p_g, g_g);
    cudaGetSymbolAddress((void**)&p_u, g_u);

    cudaFuncSetAttribute(flash_kernel,
                         cudaFuncAttributeMaxDynamicSharedMemorySize, FLASH_SMEM);
    cudaFuncSetAttribute(gemm_tf32_kernel,
                         cudaFuncAttributeMaxDynamicSharedMemorySize, GEMM_SMEM);

    rope_table_kernel<<<(S_ * 64 + 255) / 256, 256>>>();

    // Attention block
    rmsnorm_kernel<<<NTOK, 256>>>(hidden, ln1_w, p_h);
    gemm_tf32_kernel<<<dim3((NH_ * HD_) / 128, NTOK / 128, 1), 256, GEMM_SMEM>>>(
        p_h, Wq, nullptr, nullptr, p_q, nullptr, NTOK, NH_ * HD_, H_);
    gemm_tf32_kernel<<<dim3((NKV_ * HD_) / 128, NTOK / 128, 2), 256, GEMM_SMEM>>>(
        p_h, Wk, Wv, nullptr, p_k, p_v, NTOK, NKV_ * HD_, H_);
    rope_norm_kernel<<<dim3(NTOK, NH_ / 4), 128>>>(p_q, qn_w, NH_);
    rope_norm_kernel<<<dim3(NTOK, NKV_ / 4), 128>>>(p_k, kn_w, NKV_);
    flash_kernel<<<dim3(S_ / FBQ, B_ * NH_), 256, FLASH_SMEM>>>(p_q, p_k, p_v, p_o);
    gemm_tf32_kernel<<<dim3(H_ / 128, NTOK / 128, 1), 256, GEMM_SMEM>>>(
        p_o, Wo, nullptr, hidden, p_x, nullptr, NTOK, H_, H_);

    // MLP block
    rmsnorm_kernel<<<NTOK, 256>>>(p_x, ln2_w, p_h);
    gemm_tf32_kernel<<<dim3(I_ / 128, NTOK / 128, 1), 256, GEMM_SMEM>>>(
        p_h, Wg, nullptr, nullptr, p_g, nullptr, NTOK, I_, H_);
    gemm_tf32_kernel<<<dim3(I_ / 128, NTOK / 128, 1), 256, GEMM_SMEM>>>(
        p_h, Wu, nullptr, nullptr, p_u, nullptr, NTOK, I_, H_);
    swiglu_kernel<<<(NTOK * (I_ / 4) + 255) / 256, 256>>>(p_g, p_u);
    gemm_tf32_kernel<<<dim3(H_ / 128, NTOK / 128, 1), 256, GEMM_SMEM>>>(
        p_g, Wd, nullptr, p_x, out, nullptr, NTOK, H_, I_);
}

// round 5
// speedup vs baseline: 3.3897x; 1.0402x over previous
#include <cuda_runtime.h>
#include <math.h>

#define B_   2
#define S_   2048
#define H_   2048
#define NH_  16
#define NKV_ 4
#define HD_  128
#define I_   8192
#define NTOK (B_*S_)
#define EPSF 1e-6f

// ---------------------------------------------------------------------------
__device__ float g_h [NTOK * H_];
__device__ float g_q [NTOK * NH_ * HD_];
__device__ float g_k [NTOK * NKV_ * HD_];
__device__ float g_v [NTOK * NKV_ * HD_];
__device__ float g_o [NTOK * NH_ * HD_];
__device__ float g_x [NTOK * H_];
__device__ float g_g [NTOK * I_];
__device__ float g_u [NTOK * I_];
__device__ float g_rope[S_ * HD_];

// ---------------------------------------------------------------------------
__global__ void rope_table_kernel() {
    int idx = blockIdx.x * blockDim.x + threadIdx.x;
    if (idx >= S_ * 64) return;
    int pos = idx >> 6;
    int i   = idx & 63;
    float invf = 1.0f / powf(10000.0f, (float)i / 64.0f);
    float ang  = (float)pos * invf;
    g_rope[pos * HD_ + i]      = cosf(ang);
    g_rope[pos * HD_ + 64 + i] = sinf(ang);
}

// ---------------------------------------------------------------------------
__global__ __launch_bounds__(256) void rmsnorm_kernel(
    const float* __restrict__ x, const float* __restrict__ w,
    float* __restrict__ out)
{
    int row = blockIdx.x;
    const float* xr = x + (size_t)row * H_;
    float ss = 0.f;
#pragma unroll
    for (int it = 0; it < H_ / (256 * 4); it++) {
        int c = (it * 256 + threadIdx.x) * 4;
        float4 t = *(const float4*)(xr + c);
        ss += t.x * t.x + t.y * t.y + t.z * t.z + t.w * t.w;
    }
#pragma unroll
    for (int o = 16; o; o >>= 1) ss += __shfl_xor_sync(0xffffffffu, ss, o);
    __shared__ float red[8];
    if ((threadIdx.x & 31) == 0) red[threadIdx.x >> 5] = ss;
    __syncthreads();
    float tot = 0.f;
#pragma unroll
    for (int i = 0; i < 8; i++) tot += red[i];
    float inv = rsqrtf(tot * (1.0f / H_) + EPSF);
    float* orow = out + (size_t)row * H_;
#pragma unroll
    for (int it = 0; it < H_ / (256 * 4); it++) {
        int c = (it * 256 + threadIdx.x) * 4;
        float4 t  = *(const float4*)(xr + c);
        float4 wv = *(const float4*)(w + c);
        t.x = wv.x * t.x * inv; t.y = wv.y * t.y * inv;
        t.z = wv.z * t.z * inv; t.w = wv.w * t.w * inv;
        *(float4*)(orow + c) = t;
    }
}

// ---------------------------------------------------------------------------
// TF32 tensor-core GEMM, 128x128x32 tiles, 8 warps, fragment-order smem.
// A block (mtile,ks): 132 floats; value (grp,qk,v) at (grp*4+qk)*4+v.
// B block (ks,ntile): 66 floats;  value (grp,qk,v) at (grp*4+qk)*2+v.
// ---------------------------------------------------------------------------
#define GA_BLK 132
#define GB_BLK 66
#define GA_BUF (32 * GA_BLK)   // 4224 floats
#define GB_BUF (64 * GB_BLK)   // 4224 floats
#define GEMM_SMEM ((2 * GA_BUF + 2 * GB_BUF) * 4)

__device__ __forceinline__ unsigned f2tf32(float x) {
    unsigned u;
    asm("cvt.rna.tf32.f32 %0, %1;" : "=r"(u) : "f"(x));
    return u;
}

__device__ __forceinline__ void mma_tf32(float* c, const unsigned* a, const unsigned* b) {
    asm volatile(
        "mma.sync.aligned.m16n8k8.row.col.f32.tf32.tf32.f32 "
        "{%0,%1,%2,%3},{%4,%5,%6,%7},{%8,%9},{%0,%1,%2,%3};\n"
        : "+f"(c[0]), "+f"(c[1]), "+f"(c[2]), "+f"(c[3])
        : "r"(a[0]), "r"(a[1]), "r"(a[2]), "r"(a[3]), "r"(b[0]), "r"(b[1]));
}

// store one A float4 (row r, cols c0..c0+3 of the 32-wide k tile)
__device__ __forceinline__ void storeA(unsigned* As, int r, int c0, float4 t) {
    int mtile = r >> 4, grp = r & 7, half = (r >> 3) & 1;
    int ks = c0 >> 3, qsel = (c0 >> 2) & 1;
    unsigned* base = As + (mtile * 4 + ks) * GA_BLK + grp * 16 + half + 2 * qsel;
    base[0]  = f2tf32(t.x);
    base[4]  = f2tf32(t.y);
    base[8]  = f2tf32(t.z);
    base[12] = f2tf32(t.w);
}

// store one B float4 (k-row c, cols n0..n0+3 of the 128-wide n tile)
__device__ __forceinline__ void storeB(unsigned* Bs, int c, int n0, float4 t) {
    int ks = c >> 3, qk = c & 3, qsel = (c >> 2) & 1;
    int ntile = n0 >> 3, g0 = n0 & 7;
    unsigned* base = Bs + (ks * 16 + ntile) * GB_BLK + (g0 * 4 + qk) * 2 + qsel;
    base[0]  = f2tf32(t.x);
    base[8]  = f2tf32(t.y);
    base[16] = f2tf32(t.z);
    base[24] = f2tf32(t.w);
}

__global__ __launch_bounds__(256) void gemm_tf32_kernel(
    const float* __restrict__ A, const float* __restrict__ B,
    const float* __restrict__ B2,
    const float* __restrict__ addend, float* __restrict__ C,
    float* __restrict__ C2,
    int M, int N, int K)
{
    extern __shared__ float sm[];
    unsigned* AsBase = (unsigned*)sm;
    unsigned* BsBase = AsBase + 2 * GA_BUF;

    if (blockIdx.z == 1) { B = B2; C = C2; }

    int tid = threadIdx.x;
    int bm = blockIdx.y * 128, bn = blockIdx.x * 128;
    int wid = tid >> 5, lane = tid & 31;
    int mtb = (wid & 1) * 4;     // A mtile base
    int ntb = (wid >> 1) * 4;    // B ntile base
    int grp = lane >> 2, qk = lane & 3;

    int arow = tid >> 3;
    int acol = (tid & 7) * 4;
    int brow = tid >> 5;
    int bcol = (tid & 31) * 4;

    const float* Ag = A + (size_t)(bm + arow) * K + acol;
    const float* Bg = B + (size_t)brow * N + bn + bcol;

    float acc[4][4][4];
#pragma unroll
    for (int mt = 0; mt < 4; mt++)
#pragma unroll
        for (int nt = 0; nt < 4; nt++)
#pragma unroll
            for (int r = 0; r < 4; r++) acc[mt][nt][r] = 0.f;

    int nk = K / 32;
    float4 pa[4], pb[4];

#pragma unroll
    for (int s = 0; s < 4; s++)
        pa[s] = *(const float4*)(Ag + (size_t)(32 * s) * K);
#pragma unroll
    for (int s = 0; s < 4; s++)
        pb[s] = *(const float4*)(Bg + (size_t)(8 * s) * N);

    {
        unsigned* As = AsBase;
        unsigned* Bs = BsBase;
#pragma unroll
        for (int s = 0; s < 4; s++) storeA(As, arow + 32 * s, acol, pa[s]);
#pragma unroll
        for (int s = 0; s < 4; s++) storeB(Bs, brow + 8 * s, bcol, pb[s]);
    }
    __syncthreads();

    for (int kt = 0; kt < nk; kt++) {
        int cur = kt & 1, nxt = cur ^ 1;
        const unsigned* Au = AsBase + cur * GA_BUF;
        const unsigned* Bu = BsBase + cur * GB_BUF;

        if (kt + 1 < nk) {
            const float* Ag2 = Ag + (size_t)(kt + 1) * 32;
            const float* Bg2 = Bg + (size_t)(kt + 1) * 32 * N;
#pragma unroll
            for (int s = 0; s < 4; s++)
                pa[s] = *(const float4*)(Ag2 + (size_t)(32 * s) * K);
#pragma unroll
            for (int s = 0; s < 4; s++)
                pb[s] = *(const float4*)(Bg2 + (size_t)(8 * s) * N);
        }

#pragma unroll
        for (int ks = 0; ks < 4; ks++) {
            unsigned afr[4][4], bfr[4][2];
#pragma unroll
            for (int mt = 0; mt < 4; mt++) {
                uint4 av = *(const uint4*)(Au + ((mtb + mt) * 4 + ks) * GA_BLK + lane * 4);
                afr[mt][0] = av.x; afr[mt][1] = av.y;
                afr[mt][2] = av.z; afr[mt][3] = av.w;
            }
#pragma unroll
            for (int nt = 0; nt < 4; nt++) {
                uint2 bv = *(const uint2*)(Bu + (ks * 16 + ntb + nt) * GB_BLK + lane * 2);
                bfr[nt][0] = bv.x; bfr[nt][1] = bv.y;
            }
#pragma unroll
            for (int mt = 0; mt < 4; mt++)
#pragma unroll
                for (int nt = 0; nt < 4; nt++)
                    mma_tf32(acc[mt][nt], afr[mt], bfr[nt]);
        }

        if (kt + 1 < nk) {
            unsigned* As = AsBase + nxt * GA_BUF;
            unsigned* Bs = BsBase + nxt * GB_BUF;
#pragma unroll
            for (int s = 0; s < 4; s++) storeA(As, arow + 32 * s, acol, pa[s]);
#pragma unroll
            for (int s = 0; s < 4; s++) storeB(Bs, brow + 8 * s, bcol, pb[s]);
        }
        __syncthreads();
    }

    // epilogue: warp tile rows = mtb*16 .. ; cols = ntb*8 ..
#pragma unroll
    for (int mt = 0; mt < 4; mt++) {
#pragma unroll
        for (int nt = 0; nt < 4; nt++) {
            int row0 = bm + (mtb + mt) * 16 + grp;
            int col  = bn + (ntb + nt) * 8 + qk * 2;
            float* c0 = C + (size_t)row0 * N + col;
            float* c1 = C + (size_t)(row0 + 8) * N + col;
            if (addend) {
                const float* a0 = addend + (size_t)row0 * N + col;
                const float* a1 = addend + (size_t)(row0 + 8) * N + col;
                *(float2*)c0 = make_float2(acc[mt][nt][0] + a0[0], acc[mt][nt][1] + a0[1]);
                *(float2*)c1 = make_float2(acc[mt][nt][2] + a1[0], acc[mt][nt][3] + a1[1]);
            } else {
                *(float2*)c0 = make_float2(acc[mt][nt][0], acc[mt][nt][1]);
                *(float2*)c1 = make_float2(acc[mt][nt][2], acc[mt][nt][3]);
            }
        }
    }
}

// ---------------------------------------------------------------------------
__global__ __launch_bounds__(128) void rope_norm_kernel(
    float* __restrict__ qkp, const float* __restrict__ w, int nheads)
{
    int tok  = blockIdx.x;
    int warp = threadIdx.x >> 5;
    int lane = threadIdx.x & 31;
    int head = blockIdx.y * 4 + warp;
    int pos  = tok % S_;

    float* base = qkp + ((size_t)tok * nheads + head) * HD_;
    float a0 = base[lane];      float a1 = base[lane + 32];
    float b0 = base[lane + 64]; float b1 = base[lane + 96];

    const float* rc = g_rope + (size_t)pos * HD_;
    float c0 = rc[lane],      s0 = rc[64 + lane];
    float c1 = rc[lane + 32], s1 = rc[96 + lane];

    float r0  = a0 * c0 - b0 * s0;
    float r64 = b0 * c0 + a0 * s0;
    float r32 = a1 * c1 - b1 * s1;
    float r96 = b1 * c1 + a1 * s1;

    float ss = r0 * r0 + r32 * r32 + r64 * r64 + r96 * r96;
#pragma unroll
    for (int o = 16; o; o >>= 1) ss += __shfl_xor_sync(0xffffffffu, ss, o);
    float inv = rsqrtf(ss * (1.0f / HD_) + EPSF);

    base[lane]      = w[lane]      * r0  * inv;
    base[lane + 32] = w[lane + 32] * r32 * inv;
    base[lane + 64] = w[lane + 64] * r64 * inv;
    base[lane + 96] = w[lane + 96] * r96 * inv;
}

// ---------------------------------------------------------------------------
// Tensor-core flash attention (causal, GQA). BQ=128, BK=64, hd=128,
// 256 threads (8 warps), warp tile = 16 Q rows. tf32 m16n8k8 MMA.
// ---------------------------------------------------------------------------
#define FBQ 128
#define FBK 64
#define FQS 132
#define FKS 132
#define FVS 136
#define FPS 68
#define FLASH_SMEM ((FBQ*FQS + FBK*FKS + FBK*FVS + FBQ*FPS) * 4)

__global__ __launch_bounds__(256) void flash_kernel(
    const float* __restrict__ q, const float* __restrict__ k,
    const float* __restrict__ v, float* __restrict__ o)
{
    extern __shared__ float sm[];
    unsigned* Qs = (unsigned*)sm;
    unsigned* Ks = Qs + FBQ * FQS;
    unsigned* Vs = Ks + FBK * FKS;
    unsigned* Ps = Vs + FBK * FVS;

    int qb = gridDim.x - 1 - blockIdx.x;
    int bh = blockIdx.y;
    int b  = bh / NH_, h = bh % NH_;
    int kvh = h / (NH_ / NKV_);

    int tid = threadIdx.x;
    int wid = tid >> 5, lane = tid & 31;
    int wm = wid * 16;
    int grp = lane >> 2, qk = lane & 3;

    const float scale = 0.08838834764831845f;

    const float* qbase = q + ((size_t)(b * S_ + qb * FBQ) * NH_ + h) * HD_;
    for (int i = tid; i < FBQ * (HD_ / 4); i += 256) {
        int r  = i >> 5;
        int c4 = (i & 31) * 4;
        float4 t = *(const float4*)(qbase + (size_t)r * NH_ * HD_ + c4);
        unsigned* dst = Qs + r * FQS + c4;
        dst[0] = f2tf32(t.x * scale); dst[1] = f2tf32(t.y * scale);
        dst[2] = f2tf32(t.z * scale); dst[3] = f2tf32(t.w * scale);
    }

    float m0 = -1e30f, m1 = -1e30f, l0 = 0.f, l1 = 0.f;
    float oacc[16][4];
#pragma unroll
    for (int nt = 0; nt < 16; nt++)
#pragma unroll
        for (int r = 0; r < 4; r++) oacc[nt][r] = 0.f;

    int nkb = 2 * qb + 2;
    for (int kb = 0; kb < nkb; kb++) {
        __syncthreads();
        const float* kbase = k + ((size_t)(b * S_ + kb * FBK) * NKV_ + kvh) * HD_;
        const float* vbase = v + ((size_t)(b * S_ + kb * FBK) * NKV_ + kvh) * HD_;
        for (int i = tid; i < FBK * (HD_ / 4); i += 256) {
            int r  = i >> 5;
            int c4 = (i & 31) * 4;
            float4 tk = *(const float4*)(kbase + (size_t)r * NKV_ * HD_ + c4);
            unsigned* kd = Ks + r * FKS + c4;
            kd[0] = f2tf32(tk.x); kd[1] = f2tf32(tk.y);
            kd[2] = f2tf32(tk.z); kd[3] = f2tf32(tk.w);
            float4 tv = *(const float4*)(vbase + (size_t)r * NKV_ * HD_ + c4);
            unsigned* vd = Vs + r * FVS + c4;
            vd[0] = f2tf32(tv.x); vd[1] = f2tf32(tv.y);
            vd[2] = f2tf32(tv.z); vd[3] = f2tf32(tv.w);
        }
        __syncthreads();

        float s[8][4];
#pragma unroll
        for (int nt = 0; nt < 8; nt++)
#pragma unroll
            for (int r = 0; r < 4; r++) s[nt][r] = 0.f;

#pragma unroll
        for (int ks = 0; ks < 16; ks++) {
            int k0 = ks * 8;
            unsigned a[4];
            a[0] = Qs[(wm + grp)     * FQS + k0 + qk];
            a[1] = Qs[(wm + grp + 8) * FQS + k0 + qk];
            a[2] = Qs[(wm + grp)     * FQS + k0 + qk + 4];
            a[3] = Qs[(wm + grp + 8) * FQS + k0 + qk + 4];
#pragma unroll
            for (int nt = 0; nt < 8; nt++) {
                unsigned bfr[2];
                bfr[0] = Ks[(nt * 8 + grp) * FKS + k0 + qk];
                bfr[1] = Ks[(nt * 8 + grp) * FKS + k0 + qk + 4];
                mma_tf32(s[nt], a, bfr);
            }
        }

        if (kb >= 2 * qb) {
            int r0 = qb * FBQ + wm + grp;
            int cb = kb * FBK + qk * 2;
#pragma unroll
            for (int nt = 0; nt < 8; nt++) {
                int c0 = cb + nt * 8;
                if (c0     > r0)     s[nt][0] = -1e30f;
                if (c0 + 1 > r0)     s[nt][1] = -1e30f;
                if (c0     > r0 + 8) s[nt][2] = -1e30f;
                if (c0 + 1 > r0 + 8) s[nt][3] = -1e30f;
            }
        }

        float mx0 = -1e30f, mx1 = -1e30f;
#pragma unroll
        for (int nt = 0; nt < 8; nt++) {
            mx0 = fmaxf(mx0, fmaxf(s[nt][0], s[nt][1]));
            mx1 = fmaxf(mx1, fmaxf(s[nt][2], s[nt][3]));
        }
        mx0 = fmaxf(mx0, __shfl_xor_sync(0xffffffffu, mx0, 1));
        mx0 = fmaxf(mx0, __shfl_xor_sync(0xffffffffu, mx0, 2));
        mx1 = fmaxf(mx1, __shfl_xor_sync(0xffffffffu, mx1, 1));
        mx1 = fmaxf(mx1, __shfl_xor_sync(0xffffffffu, mx1, 2));

        float mn0 = fmaxf(m0, mx0), mn1 = fmaxf(m1, mx1);
        float corr0 = __expf(m0 - mn0), corr1 = __expf(m1 - mn1);
        m0 = mn0; m1 = mn1;

        float rs0 = 0.f, rs1 = 0.f;
#pragma unroll
        for (int nt = 0; nt < 8; nt++) {
            float p0 = __expf(s[nt][0] - mn0);
            float p1 = __expf(s[nt][1] - mn0);
            float p2 = __expf(s[nt][2] - mn1);
            float p3 = __expf(s[nt][3] - mn1);
            rs0 += p0 + p1; rs1 += p2 + p3;
            unsigned* pr0 = Ps + (wm + grp)     * FPS + nt * 8 + qk * 2;
            unsigned* pr1 = Ps + (wm + grp + 8) * FPS + nt * 8 + qk * 2;
            pr0[0] = f2tf32(p0); pr0[1] = f2tf32(p1);
            pr1[0] = f2tf32(p2); pr1[1] = f2tf32(p3);
        }
        rs0 += __shfl_xor_sync(0xffffffffu, rs0, 1);
        rs0 += __shfl_xor_sync(0xffffffffu, rs0, 2);
        rs1 += __shfl_xor_sync(0xffffffffu, rs1, 1);
        rs1 += __shfl_xor_sync(0xffffffffu, rs1, 2);
        l0 = l0 * corr0 + rs0;
        l1 = l1 * corr1 + rs1;

#pragma unroll
        for (int nt = 0; nt < 16; nt++) {
            oacc[nt][0] *= corr0; oacc[nt][1] *= corr0;
            oacc[nt][2] *= corr1; oacc[nt][3] *= corr1;
        }
        __syncwarp();

#pragma unroll
        for (int ks = 0; ks < 8; ks++) {
            int k0 = ks * 8;
            unsigned a[4];
            a[0] = Ps[(wm + grp)     * FPS + k0 + qk];
            a[1] = Ps[(wm + grp + 8) * FPS + k0 + qk];
            a[2] = Ps[(wm + grp)     * FPS + k0 + qk + 4];
            a[3] = Ps[(wm + grp + 8) * FPS + k0 + qk + 4];
#pragma unroll
            for (int nt = 0; nt < 16; nt++) {
                unsigned bfr[2];
                bfr[0] = Vs[(k0 + qk)     * FVS + nt * 8 + grp];
                bfr[1] = Vs[(k0 + qk + 4) * FVS + nt * 8 + grp];
                mma_tf32(oacc[nt], a, bfr);
            }
        }
    }

    float inv0 = 1.0f / l0, inv1 = 1.0f / l1;
    int r0 = qb * FBQ + wm + grp;
    float* out0 = o + ((size_t)(b * S_ + r0) * NH_ + h) * HD_;
    float* out1 = o + ((size_t)(b * S_ + r0 + 8) * NH_ + h) * HD_;
#pragma unroll
    for (int nt = 0; nt < 16; nt++) {
        int col = nt * 8 + qk * 2;
        *(float2*)(out0 + col) = make_float2(oacc[nt][0] * inv0, oacc[nt][1] * inv0);
        *(float2*)(out1 + col) = make_float2(oacc[nt][2] * inv1, oacc[nt][3] * inv1);
    }
}

// ---------------------------------------------------------------------------
__global__ __launch_bounds__(256) void swiglu_kernel(
    float* __restrict__ g, const float* __restrict__ u)
{
    int idx = blockIdx.x * 256 + threadIdx.x;
    if (idx >= NTOK * (I_ / 4)) return;
    float4 gv = ((float4*)g)[idx];
    float4 uv = ((const float4*)u)[idx];
    gv.x = gv.x / (1.f + __expf(-gv.x)) * uv.x;
    gv.y = gv.y / (1.f + __expf(-gv.y)) * uv.y;
    gv.z = gv.z / (1.f + __expf(-gv.z)) * uv.z;
    gv.w = gv.w / (1.f + __expf(-gv.w)) * uv.w;
    ((float4*)g)[idx] = gv;
}

// ---------------------------------------------------------------------------
extern "C" void kernel_launch(void* const* d_in, const int* in_sizes, int n_in,
                              void* d_out, int out_size)
{
    const float* hidden = (const float*)d_in[0];
    const float* ln1_w = (const float*)d_in[3];
    const float* Wq    = (const float*)d_in[4];
    const float* Wk    = (const float*)d_in[5];
    const float* Wv    = (const float*)d_in[6];
    const float* Wo    = (const float*)d_in[7];
    const float* qn_w  = (const float*)d_in[8];
    const float* kn_w  = (const float*)d_in[9];
    const float* ln2_w = (const float*)d_in[10];
    const float* Wg    = (const float*)d_in[11];
    const float* Wu    = (const float*)d_in[12];
    const float* Wd    = (const float*)d_in[13];
    float* out = (float*)d_out;

    float *p_h, *p_q, *p_k, *p_v, *p_o, *p_x, *p_g, *p_u;
    cudaGetSymbolAddress((void**)&p_h, g_h);
    cudaGetSymbolAddress((void**)&p_q, g_q);
    cudaGetSymbolAddress((void**)&p_k, g_k);
    cudaGetSymbolAddress((void**)&p_v, g_v);
    cudaGetSymbolAddress((void**)&p_o, g_o);
    cudaGetSymbolAddress((void**)&p_x, g_x);
    cudaGetSymbolAddress((void**)&p_g, g_g);
    cudaGetSymbolAddress((void**)&p_u, g_u);

    cudaFuncSetAttribute(flash_kernel,
                         cudaFuncAttributeMaxDynamicSharedMemorySize, FLASH_SMEM);
    cudaFuncSetAttribute(gemm_tf32_kernel,
                         cudaFuncAttributeMaxDynamicSharedMemorySize, GEMM_SMEM);

    rope_table_kernel<<<(S_ * 64 + 255) / 256, 256>>>();

    // Attention block
    rmsnorm_kernel<<<NTOK, 256>>>(hidden, ln1_w, p_h);
    gemm_tf32_kernel<<<dim3((NH_ * HD_) / 128, NTOK / 128, 1), 256, GEMM_SMEM>>>(
        p_h, Wq, nullptr, nullptr, p_q, nullptr, NTOK, NH_ * HD_, H_);
    gemm_tf32_kernel<<<dim3((NKV_ * HD_) / 128, NTOK / 128, 2), 256, GEMM_SMEM>>>(
        p_h, Wk, Wv, nullptr, p_k, p_v, NTOK, NKV_ * HD_, H_);
    rope_norm_kernel<<<dim3(NTOK, NH_ / 4), 128>>>(p_q, qn_w, NH_);
    rope_norm_kernel<<<dim3(NTOK, NKV_ / 4), 128>>>(p_k, kn_w, NKV_);
    flash_kernel<<<dim3(S_ / FBQ, B_ * NH_), 256, FLASH_SMEM>>>(p_q, p_k, p_v, p_o);
    gemm_tf32_kernel<<<dim3(H_ / 128, NTOK / 128, 1), 256, GEMM_SMEM>>>(
        p_o, Wo, nullptr, hidden, p_x, nullptr, NTOK, H_, H_);

    // MLP block
    rmsnorm_kernel<<<NTOK, 256>>>(p_x, ln2_w, p_h);
    gemm_tf32_kernel<<<dim3(I_ / 128, NTOK / 128, 1), 256, GEMM_SMEM>>>(
        p_h, Wg, nullptr, nullptr, p_g, nullptr, NTOK, I_, H_);
    gemm_tf32_kernel<<<dim3(I_ / 128, NTOK / 128, 1), 256, GEMM_SMEM>>>(
        p_h, Wu, nullptr, nullptr, p_u, nullptr, NTOK, I_, H_);
    swiglu_kernel<<<(NTOK * (I_ / 4) + 255) / 256, 256>>>(p_g, p_u);
    gemm_tf32_kernel<<<dim3(H_ / 128, NTOK / 128, 1), 256, GEMM_SMEM>>>(
        p_g, Wd, nullptr, p_x, out, nullptr, NTOK, H_, I_);
}

// round 8
// speedup vs baseline: 5.8143x; 1.7153x over previous
#include <cuda_runtime.h>
#include <cuda_fp16.h>
#include <math.h>
#include <stdint.h>

#define B_   2
#define S_   2048
#define H_   2048
#define NH_  16
#define NKV_ 4
#define HD_  128
#define I_   8192
#define NTOK (B_*S_)
#define EPSF 1e-6f

// ---------------------------------------------------------------------------
// Scratch
// ---------------------------------------------------------------------------
__device__ float  g_q [NTOK * NH_ * HD_];
__device__ float  g_k [NTOK * NKV_ * HD_];
__device__ float  g_v [NTOK * NKV_ * HD_];
__device__ float  g_x [NTOK * H_];
__device__ float  g_g [NTOK * I_];
__device__ float  g_u [NTOK * I_];
__device__ float  g_rope[S_ * HD_];
__device__ __half g_hh [NTOK * H_];          // rmsnorm out (fp16)
__device__ __half g_oh [NTOK * NH_ * HD_];   // flash out (fp16)
__device__ __half g_gh [NTOK * I_];          // swiglu out (fp16)
// transposed fp16 weights [N][K]
__device__ __half g_wqT[2048 * 2048];
__device__ __half g_wkT[512 * 2048];
__device__ __half g_wvT[512 * 2048];
__device__ __half g_woT[2048 * 2048];
__device__ __half g_wgT[8192 * 2048];
__device__ __half g_wuT[8192 * 2048];
__device__ __half g_wdT[2048 * 8192];

// ---------------------------------------------------------------------------
__device__ __forceinline__ unsigned f2tf32(float x) {
    unsigned u;
    asm("cvt.rna.tf32.f32 %0, %1;" : "=r"(u) : "f"(x));
    return u;
}

__device__ __forceinline__ void mma_tf32(float* c, const unsigned* a, const unsigned* b) {
    asm volatile(
        "mma.sync.aligned.m16n8k8.row.col.f32.tf32.tf32.f32 "
        "{%0,%1,%2,%3},{%4,%5,%6,%7},{%8,%9},{%0,%1,%2,%3};\n"
        : "+f"(c[0]), "+f"(c[1]), "+f"(c[2]), "+f"(c[3])
        : "r"(a[0]), "r"(a[1]), "r"(a[2]), "r"(a[3]), "r"(b[0]), "r"(b[1]));
}

__device__ __forceinline__ void mma_f16(float* c, const unsigned* a, const unsigned* b) {
    asm volatile(
        "mma.sync.aligned.m16n8k16.row.col.f32.f16.f16.f32 "
        "{%0,%1,%2,%3},{%4,%5,%6,%7},{%8,%9},{%0,%1,%2,%3};\n"
        : "+f"(c[0]), "+f"(c[1]), "+f"(c[2]), "+f"(c[3])
        : "r"(a[0]), "r"(a[1]), "r"(a[2]), "r"(a[3]), "r"(b[0]), "r"(b[1]));
}

// ---------------------------------------------------------------------------
__global__ void rope_table_kernel() {
    int idx = blockIdx.x * blockDim.x + threadIdx.x;
    if (idx >= S_ * 64) return;
    int pos = idx >> 6;
    int i   = idx & 63;
    float invf = 1.0f / powf(10000.0f, (float)i / 64.0f);
    float ang  = (float)pos * invf;
    g_rope[pos * HD_ + i]      = cosf(ang);
    g_rope[pos * HD_ + 64 + i] = sinf(ang);
}

// ---------------------------------------------------------------------------
// weight transpose + fp16 cvt: W [K x N] fp32 -> Wt [N x K] fp16
// ---------------------------------------------------------------------------
__global__ __launch_bounds__(256) void transpose_cvt_kernel(
    const float* __restrict__ W, __half* __restrict__ Wt, int K, int N)
{
    __shared__ float t[32][33];
    int k0 = blockIdx.x * 32, n0 = blockIdx.y * 32;
    int tx = threadIdx.x, ty = threadIdx.y;
#pragma unroll
    for (int j = ty; j < 32; j += 8)
        t[j][tx] = W[(size_t)(k0 + j) * N + n0 + tx];
    __syncthreads();
    if (tx < 16) {
#pragma unroll
        for (int j = ty; j < 32; j += 8) {
            __half2 hv = __floats2half2_rn(t[2 * tx][j], t[2 * tx + 1][j]);
            *(__half2*)(Wt + (size_t)(n0 + j) * K + k0 + 2 * tx) = hv;
        }
    }
}

// ---------------------------------------------------------------------------
// RMSNorm -> fp16 output
// ---------------------------------------------------------------------------
__global__ __launch_bounds__(256) void rmsnorm_kernel(
    const float* __restrict__ x, const float* __restrict__ w,
    __half* __restrict__ out)
{
    int row = blockIdx.x;
    const float* xr = x + (size_t)row * H_;
    float ss = 0.f;
#pragma unroll
    for (int it = 0; it < H_ / (256 * 4); it++) {
        int c = (it * 256 + threadIdx.x) * 4;
        float4 t = *(const float4*)(xr + c);
        ss += t.x * t.x + t.y * t.y + t.z * t.z + t.w * t.w;
    }
#pragma unroll
    for (int o = 16; o; o >>= 1) ss += __shfl_xor_sync(0xffffffffu, ss, o);
    __shared__ float red[8];
    if ((threadIdx.x & 31) == 0) red[threadIdx.x >> 5] = ss;
    __syncthreads();
    float tot = 0.f;
#pragma unroll
    for (int i = 0; i < 8; i++) tot += red[i];
    float inv = rsqrtf(tot * (1.0f / H_) + EPSF);
    __half* orow = out + (size_t)row * H_;
#pragma unroll
    for (int it = 0; it < H_ / (256 * 4); it++) {
        int c = (it * 256 + threadIdx.x) * 4;
        float4 t  = *(const float4*)(xr + c);
        float4 wv = *(const float4*)(w + c);
        __half2 h0 = __floats2half2_rn(wv.x * t.x * inv, wv.y * t.y * inv);
        __half2 h1 = __floats2half2_rn(wv.z * t.z * inv, wv.w * t.w * inv);
        *(__half2*)(orow + c)     = h0;
        *(__half2*)(orow + c + 2) = h1;
    }
}

// ---------------------------------------------------------------------------
// FP16 tensor-core GEMM: C[M,N] = A[M,K] @ Bt[N,K]^T (+addend), fp32 accum.
// 128x128x64 tiles, 256 threads, warp tile 64x32 via m16n8k16.
// Smem: K-major rows, 72-half stride (conflict-free fragments).
// ---------------------------------------------------------------------------
#define HSTR 72                         // halves per smem row
#define HBUF (128 * HSTR)               // halves per (matrix, buffer)
#define HG_SMEM (4 * HBUF * 2)          // bytes: A0,B0,A1,B1

__global__ __launch_bounds__(256) void gemm_h_kernel(
    const __half* __restrict__ A, const __half* __restrict__ Bt,
    const __half* __restrict__ Bt2, const float* __restrict__ addend,
    float* __restrict__ C, float* __restrict__ C2,
    int M, int N, int K)
{
    extern __shared__ __half smh[];
    __half* As0 = smh;
    __half* Bs0 = smh + HBUF;
    __half* As1 = smh + 2 * HBUF;
    __half* Bs1 = smh + 3 * HBUF;

    if (blockIdx.z == 1) { Bt = Bt2; C = C2; }

    int tid = threadIdx.x;
    int bm = blockIdx.y * 128, bn = blockIdx.x * 128;
    int wid = tid >> 5, lane = tid & 31;
    int wm = (wid & 1) * 64;
    int wn = (wid >> 1) * 32;
    int grp = lane >> 2, qk = lane & 3;

    int lrow = tid >> 3;        // 0..31 (+32s)
    int lseg = (tid & 7) * 8;   // half offset within row

    const __half* Ag = A  + (size_t)(bm + lrow) * K + lseg;
    const __half* Bg = Bt + (size_t)(bn + lrow) * K + lseg;

    float acc[4][4][4];
#pragma unroll
    for (int mt = 0; mt < 4; mt++)
#pragma unroll
        for (int nt = 0; nt < 4; nt++)
#pragma unroll
            for (int r = 0; r < 4; r++) acc[mt][nt][r] = 0.f;

    int nk = K / 64;
    uint4 pa[4], pb[4];

#pragma unroll
    for (int s = 0; s < 4; s++) {
        pa[s] = *(const uint4*)(Ag + (size_t)(32 * s) * K);
        pb[s] = *(const uint4*)(Bg + (size_t)(32 * s) * K);
    }
    {
#pragma unroll
        for (int s = 0; s < 4; s++) {
            *(uint4*)(As0 + (lrow + 32 * s) * HSTR + lseg) = pa[s];
            *(uint4*)(Bs0 + (lrow + 32 * s) * HSTR + lseg) = pb[s];
        }
    }
    __syncthreads();

    for (int kt = 0; kt < nk; kt++) {
        const uint32_t* Au = (const uint32_t*)((kt & 1) ? As1 : As0);
        const uint32_t* Bu = (const uint32_t*)((kt & 1) ? Bs1 : Bs0);
        __half* Asn = (kt & 1) ? As0 : As1;
        __half* Bsn = (kt & 1) ? Bs0 : Bs1;

        if (kt + 1 < nk) {
            const __half* Ag2 = Ag + (size_t)(kt + 1) * 64;
            const __half* Bg2 = Bg + (size_t)(kt + 1) * 64;
#pragma unroll
            for (int s = 0; s < 4; s++) {
                pa[s] = *(const uint4*)(Ag2 + (size_t)(32 * s) * K);
                pb[s] = *(const uint4*)(Bg2 + (size_t)(32 * s) * K);
            }
        }

#pragma unroll
        for (int ks = 0; ks < 4; ks++) {
            int w0 = ks * 8;
            unsigned afr[4][4], bfr[4][2];
#pragma unroll
            for (int mt = 0; mt < 4; mt++) {
                int r = wm + mt * 16 + grp;
                afr[mt][0] = Au[r * 36 + w0 + qk];
                afr[mt][1] = Au[(r + 8) * 36 + w0 + qk];
                afr[mt][2] = Au[r * 36 + w0 + qk + 4];
                afr[mt][3] = Au[(r + 8) * 36 + w0 + qk + 4];
            }
#pragma unroll
            for (int nt = 0; nt < 4; nt++) {
                int n = wn + nt * 8 + grp;
                bfr[nt][0] = Bu[n * 36 + w0 + qk];
                bfr[nt][1] = Bu[n * 36 + w0 + qk + 4];
            }
#pragma unroll
            for (int mt = 0; mt < 4; mt++)
#pragma unroll
                for (int nt = 0; nt < 4; nt++)
                    mma_f16(acc[mt][nt], afr[mt], bfr[nt]);
        }

        if (kt + 1 < nk) {
#pragma unroll
            for (int s = 0; s < 4; s++) {
                *(uint4*)(Asn + (lrow + 32 * s) * HSTR + lseg) = pa[s];
                *(uint4*)(Bsn + (lrow + 32 * s) * HSTR + lseg) = pb[s];
            }
        }
        __syncthreads();
    }

#pragma unroll
    for (int mt = 0; mt < 4; mt++) {
#pragma unroll
        for (int nt = 0; nt < 4; nt++) {
            int row0 = bm + wm + mt * 16 + grp;
            int col  = bn + wn + nt * 8 + qk * 2;
            float* c0 = C + (size_t)row0 * N + col;
            float* c1 = C + (size_t)(row0 + 8) * N + col;
            if (addend) {
                const float* a0 = addend + (size_t)row0 * N + col;
                const float* a1 = addend + (size_t)(row0 + 8) * N + col;
                *(float2*)c0 = make_float2(acc[mt][nt][0] + a0[0], acc[mt][nt][1] + a0[1]);
                *(float2*)c1 = make_float2(acc[mt][nt][2] + a1[0], acc[mt][nt][3] + a1[1]);
            } else {
                *(float2*)c0 = make_float2(acc[mt][nt][0], acc[mt][nt][1]);
                *(float2*)c1 = make_float2(acc[mt][nt][2], acc[mt][nt][3]);
            }
        }
    }
}

// ---------------------------------------------------------------------------
__global__ __launch_bounds__(128) void rope_norm_kernel(
    float* __restrict__ qkp, const float* __restrict__ w, int nheads)
{
    int tok  = blockIdx.x;
    int warp = threadIdx.x >> 5;
    int lane = threadIdx.x & 31;
    int head = blockIdx.y * 4 + warp;
    int pos  = tok % S_;

    float* base = qkp + ((size_t)tok * nheads + head) * HD_;
    float a0 = base[lane];      float a1 = base[lane + 32];
    float b0 = base[lane + 64]; float b1 = base[lane + 96];

    const float* rc = g_rope + (size_t)pos * HD_;
    float c0 = rc[lane],      s0 = rc[64 + lane];
    float c1 = rc[lane + 32], s1 = rc[96 + lane];

    float r0  = a0 * c0 - b0 * s0;
    float r64 = b0 * c0 + a0 * s0;
    float r32 = a1 * c1 - b1 * s1;
    float r96 = b1 * c1 + a1 * s1;

    float ss = r0 * r0 + r32 * r32 + r64 * r64 + r96 * r96;
#pragma unroll
    for (int o = 16; o; o >>= 1) ss += __shfl_xor_sync(0xffffffffu, ss, o);
    float inv = rsqrtf(ss * (1.0f / HD_) + EPSF);

    base[lane]      = w[lane]      * r0  * inv;
    base[lane + 32] = w[lane + 32] * r32 * inv;
    base[lane + 64] = w[lane + 64] * r64 * inv;
    base[lane + 96] = w[lane + 96] * r96 * inv;
}

// ---------------------------------------------------------------------------
// Tensor-core flash attention (tf32 mma.sync). Output fp16.
// ---------------------------------------------------------------------------
#define FBQ 128
#define FBK 64
#define FQS 132
#define FKS 132
#define FVS 136
#define FPS 68
#define FLASH_SMEM ((FBQ*FQS + FBK*FKS + FBK*FVS + FBQ*FPS) * 4)

__global__ __launch_bounds__(256) void flash_kernel(
    const float* __restrict__ q, const float* __restrict__ k,
    const float* __restrict__ v, __half* __restrict__ o)
{
    extern __shared__ float sm[];
    unsigned* Qs = (unsigned*)sm;
    unsigned* Ks = Qs + FBQ * FQS;
    unsigned* Vs = Ks + FBK * FKS;
    unsigned* Ps = Vs + FBK * FVS;

    int qb = gridDim.x - 1 - blockIdx.x;
    int bh = blockIdx.y;
    int b  = bh / NH_, h = bh % NH_;
    int kvh = h / (NH_ / NKV_);

    int tid = threadIdx.x;
    int wid = tid >> 5, lane = tid & 31;
    int wm = wid * 16;
    int grp = lane >> 2, qk = lane & 3;

    const float scale = 0.08838834764831845f;

    const float* qbase = q + ((size_t)(b * S_ + qb * FBQ) * NH_ + h) * HD_;
    for (int i = tid; i < FBQ * (HD_ / 4); i += 256) {
        int r  = i >> 5;
        int c4 = (i & 31) * 4;
        float4 t = *(const float4*)(qbase + (size_t)r * NH_ * HD_ + c4);
        unsigned* dst = Qs + r * FQS + c4;
        dst[0] = f2tf32(t.x * scale); dst[1] = f2tf32(t.y * scale);
        dst[2] = f2tf32(t.z * scale); dst[3] = f2tf32(t.w * scale);
    }

    float m0 = -1e30f, m1 = -1e30f, l0 = 0.f, l1 = 0.f;
    float oacc[16][4];
#pragma unroll
    for (int nt = 0; nt < 16; nt++)
#pragma unroll
        for (int r = 0; r < 4; r++) oacc[nt][r] = 0.f;

    int nkb = 2 * qb + 2;
    for (int kb = 0; kb < nkb; kb++) {
        __syncthreads();
        const float* kbase = k + ((size_t)(b * S_ + kb * FBK) * NKV_ + kvh) * HD_;
        const float* vbase = v + ((size_t)(b * S_ + kb * FBK) * NKV_ + kvh) * HD_;
        for (int i = tid; i < FBK * (HD_ / 4); i += 256) {
            int r  = i >> 5;
            int c4 = (i & 31) * 4;
            float4 tk = *(const float4*)(kbase + (size_t)r * NKV_ * HD_ + c4);
            unsigned* kd = Ks + r * FKS + c4;
            kd[0] = f2tf32(tk.x); kd[1] = f2tf32(tk.y);
            kd[2] = f2tf32(tk.z); kd[3] = f2tf32(tk.w);
            float4 tv = *(const float4*)(vbase + (size_t)r * NKV_ * HD_ + c4);
            unsigned* vd = Vs + r * FVS + c4;
            vd[0] = f2tf32(tv.x); vd[1] = f2tf32(tv.y);
            vd[2] = f2tf32(tv.z); vd[3] = f2tf32(tv.w);
        }
        __syncthreads();

        float s[8][4];
#pragma unroll
        for (int nt = 0; nt < 8; nt++)
#pragma unroll
            for (int r = 0; r < 4; r++) s[nt][r] = 0.f;

#pragma unroll
        for (int ks = 0; ks < 16; ks++) {
            int k0 = ks * 8;
            unsigned a[4];
            a[0] = Qs[(wm + grp)     * FQS + k0 + qk];
            a[1] = Qs[(wm + grp + 8) * FQS + k0 + qk];
            a[2] = Qs[(wm + grp)     * FQS + k0 + qk + 4];
            a[3] = Qs[(wm + grp + 8) * FQS + k0 + qk + 4];
#pragma unroll
            for (int nt = 0; nt < 8; nt++) {
                unsigned bfr[2];
                bfr[0] = Ks[(nt * 8 + grp) * FKS + k0 + qk];
                bfr[1] = Ks[(nt * 8 + grp) * FKS + k0 + qk + 4];
                mma_tf32(s[nt], a, bfr);
            }
        }

        if (kb >= 2 * qb) {
            int r0 = qb * FBQ + wm + grp;
            int cb = kb * FBK + qk * 2;
#pragma unroll
            for (int nt = 0; nt < 8; nt++) {
                int c0 = cb + nt * 8;
                if (c0     > r0)     s[nt][0] = -1e30f;
                if (c0 + 1 > r0)     s[nt][1] = -1e30f;
                if (c0     > r0 + 8) s[nt][2] = -1e30f;
                if (c0 + 1 > r0 + 8) s[nt][3] = -1e30f;
            }
        }

        float mx0 = -1e30f, mx1 = -1e30f;
#pragma unroll
        for (int nt = 0; nt < 8; nt++) {
            mx0 = fmaxf(mx0, fmaxf(s[nt][0], s[nt][1]));
            mx1 = fmaxf(mx1, fmaxf(s[nt][2], s[nt][3]));
        }
        mx0 = fmaxf(mx0, __shfl_xor_sync(0xffffffffu, mx0, 1));
        mx0 = fmaxf(mx0, __shfl_xor_sync(0xffffffffu, mx0, 2));
        mx1 = fmaxf(mx1, __shfl_xor_sync(0xffffffffu, mx1, 1));
        mx1 = fmaxf(mx1, __shfl_xor_sync(0xffffffffu, mx1, 2));

        float mn0 = fmaxf(m0, mx0), mn1 = fmaxf(m1, mx1);
        float corr0 = __expf(m0 - mn0), corr1 = __expf(m1 - mn1);
        m0 = mn0; m1 = mn1;

        float rs0 = 0.f, rs1 = 0.f;
#pragma unroll
        for (int nt = 0; nt < 8; nt++) {
            float p0 = __expf(s[nt][0] - mn0);
            float p1 = __expf(s[nt][1] - mn0);
            float p2 = __expf(s[nt][2] - mn1);
            float p3 = __expf(s[nt][3] - mn1);
            rs0 += p0 + p1; rs1 += p2 + p3;
            unsigned* pr0 = Ps + (wm + grp)     * FPS + nt * 8 + qk * 2;
            unsigned* pr1 = Ps + (wm + grp + 8) * FPS + nt * 8 + qk * 2;
            pr0[0] = f2tf32(p0); pr0[1] = f2tf32(p1);
            pr1[0] = f2tf32(p2); pr1[1] = f2tf32(p3);
        }
        rs0 += __shfl_xor_sync(0xffffffffu, rs0, 1);
        rs0 += __shfl_xor_sync(0xffffffffu, rs0, 2);
        rs1 += __shfl_xor_sync(0xffffffffu, rs1, 1);
        rs1 += __shfl_xor_sync(0xffffffffu, rs1, 2);
        l0 = l0 * corr0 + rs0;
        l1 = l1 * corr1 + rs1;

#pragma unroll
        for (int nt = 0; nt < 16; nt++) {
            oacc[nt][0] *= corr0; oacc[nt][1] *= corr0;
            oacc[nt][2] *= corr1; oacc[nt][3] *= corr1;
        }
        __syncwarp();

#pragma unroll
        for (int ks = 0; ks < 8; ks++) {
            int k0 = ks * 8;
            unsigned a[4];
            a[0] = Ps[(wm + grp)     * FPS + k0 + qk];
            a[1] = Ps[(wm + grp + 8) * FPS + k0 + qk];
            a[2] = Ps[(wm + grp)     * FPS + k0 + qk + 4];
            a[3] = Ps[(wm + grp + 8) * FPS + k0 + qk + 4];
#pragma unroll
            for (int nt = 0; nt < 16; nt++) {
                unsigned bfr[2];
                bfr[0] = Vs[(k0 + qk)     * FVS + nt * 8 + grp];
                bfr[1] = Vs[(k0 + qk + 4) * FVS + nt * 8 + grp];
                mma_tf32(oacc[nt], a, bfr);
            }
        }
    }

    float inv0 = 1.0f / l0, inv1 = 1.0f / l1;
    int r0 = qb * FBQ + wm + grp;
    __half* out0 = o + ((size_t)(b * S_ + r0) * NH_ + h) * HD_;
    __half* out1 = o + ((size_t)(b * S_ + r0 + 8) * NH_ + h) * HD_;
#pragma unroll
    for (int nt = 0; nt < 16; nt++) {
        int col = nt * 8 + qk * 2;
        *(__half2*)(out0 + col) = __floats2half2_rn(oacc[nt][0] * inv0, oacc[nt][1] * inv0);
        *(__half2*)(out1 + col) = __floats2half2_rn(oacc[nt][2] * inv1, oacc[nt][3] * inv1);
    }
}

// ---------------------------------------------------------------------------
__global__ __launch_bounds__(256) void swiglu_kernel(
    const float* __restrict__ g, const float* __restrict__ u,
    __half* __restrict__ outh)
{
    int idx = blockIdx.x * 256 + threadIdx.x;
    if (idx >= NTOK * (I_ / 4)) return;
    float4 gv = ((const float4*)g)[idx];
    float4 uv = ((const float4*)u)[idx];
    float r0 = gv.x / (1.f + __expf(-gv.x)) * uv.x;
    float r1 = gv.y / (1.f + __expf(-gv.y)) * uv.y;
    float r2 = gv.z / (1.f + __expf(-gv.z)) * uv.z;
    float r3 = gv.w / (1.f + __expf(-gv.w)) * uv.w;
    __half* dst = outh + (size_t)idx * 4;
    *(__half2*)(dst)     = __floats2half2_rn(r0, r1);
    *(__half2*)(dst + 2) = __floats2half2_rn(r2, r3);
}

// ---------------------------------------------------------------------------
extern "C" void kernel_launch(void* const* d_in, const int* in_sizes, int n_in,
                              void* d_out, int out_size)
{
    const float* hidden = (const float*)d_in[0];
    const float* ln1_w = (const float*)d_in[3];
    const float* Wq    = (const float*)d_in[4];
    const float* Wk    = (const float*)d_in[5];
    const float* Wv    = (const float*)d_in[6];
    const float* Wo    = (const float*)d_in[7];
    const float* qn_w  = (const float*)d_in[8];
    const float* kn_w  = (const float*)d_in[9];
    const float* ln2_w = (const float*)d_in[10];
    const float* Wg    = (const float*)d_in[11];
    const float* Wu    = (const float*)d_in[12];
    const float* Wd    = (const float*)d_in[13];
    float* out = (float*)d_out;

    float *p_q, *p_k, *p_v, *p_x, *p_g, *p_u;
    __half *p_hh, *p_oh, *p_gh;
    __half *p_wqT, *p_wkT, *p_wvT, *p_woT, *p_wgT, *p_wuT, *p_wdT;
    cudaGetSymbolAddress((void**)&p_q, g_q);
    cudaGetSymbolAddress((void**)&p_k, g_k);
    cudaGetSymbolAddress((void**)&p_v, g_v);
    cudaGetSymbolAddress((void**)&p_x, g_x);
    cudaGetSymbolAddress((void**)&p_g, g_g);
    cudaGetSymbolAddress((void**)&p_u, g_u);
    cudaGetSymbolAddress((void**)&p_hh, g_hh);
    cudaGetSymbolAddress((void**)&p_oh, g_oh);
    cudaGetSymbolAddress((void**)&p_gh, g_gh);
    cudaGetSymbolAddress((void**)&p_wqT, g_wqT);
    cudaGetSymbolAddress((void**)&p_wkT, g_wkT);
    cudaGetSymbolAddress((void**)&p_wvT, g_wvT);
    cudaGetSymbolAddress((void**)&p_woT, g_woT);
    cudaGetSymbolAddress((void**)&p_wgT, g_wgT);
    cudaGetSymbolAddress((void**)&p_wuT, g_wuT);
    cudaGetSymbolAddress((void**)&p_wdT, g_wdT);

    cudaFuncSetAttribute(flash_kernel,
                         cudaFuncAttributeMaxDynamicSharedMemorySize, FLASH_SMEM);
    cudaFuncSetAttribute(gemm_h_kernel,
                         cudaFuncAttributeMaxDynamicSharedMemorySize, HG_SMEM);

    rope_table_kernel<<<(S_ * 64 + 255) / 256, 256>>>();

    dim3 tb(32, 8);
    transpose_cvt_kernel<<<dim3(64, 64),  tb>>>(Wq, p_wqT, 2048, 2048);
    transpose_cvt_kernel<<<dim3(64, 16),  tb>>>(Wk, p_wkT, 2048, 512);
    transpose_cvt_kernel<<<dim3(64, 16),  tb>>>(Wv, p_wvT, 2048, 512);
    transpose_cvt_kernel<<<dim3(64, 64),  tb>>>(Wo, p_woT, 2048, 2048);
    transpose_cvt_kernel<<<dim3(64, 256), tb>>>(Wg, p_wgT, 2048, 8192);
    transpose_cvt_kernel<<<dim3(64, 256), tb>>>(Wu, p_wuT, 2048, 8192);
    transpose_cvt_kernel<<<dim3(256, 64), tb>>>(Wd, p_wdT, 8192, 2048);

    // Attention block
    rmsnorm_kernel<<<NTOK, 256>>>(hidden, ln1_w, p_hh);
    gemm_h_kernel<<<dim3((NH_ * HD_) / 128, NTOK / 128, 1), 256, HG_SMEM>>>(
        p_hh, p_wqT, nullptr, nullptr, p_q, nullptr, NTOK, NH_ * HD_, H_);
    gemm_h_kernel<<<dim3((NKV_ * HD_) / 128, NTOK / 128, 2), 256, HG_SMEM>>>(
        p_hh, p_wkT, p_wvT, nullptr, p_k, p_v, NTOK, NKV_ * HD_, H_);
    rope_norm_kernel<<<dim3(NTOK, NH_ / 4), 128>>>(p_q, qn_w, NH_);
    rope_norm_kernel<<<dim3(NTOK, NKV_ / 4), 128>>>(p_k, kn_w, NKV_);
    flash_kernel<<<dim3(S_ / FBQ, B_ * NH_), 256, FLASH_SMEM>>>(p_q, p_k, p_v, p_oh);
    gemm_h_kernel<<<dim3(H_ / 128, NTOK / 128, 1), 256, HG_SMEM>>>(
        p_oh, p_woT, nullptr, hidden, p_x, nullptr, NTOK, H_, H_);

    // MLP block
    rmsnorm_kernel<<<NTOK, 256>>>(p_x, ln2_w, p_hh);
    gemm_h_kernel<<<dim3(I_ / 128, NTOK / 128, 2), 256, HG_SMEM>>>(
        p_hh, p_wgT, p_wuT, nullptr, p_g, p_u, NTOK, I_, H_);
    swiglu_kernel<<<(NTOK * (I_ / 4) + 255) / 256, 256>>>(p_g, p_u, p_gh);
    gemm_h_kernel<<<dim3(H_ / 128, NTOK / 128, 1), 256, HG_SMEM>>>(
        p_gh, p_wdT, nullptr, p_x, out, nullptr, NTOK, H_, I_);
}

// round 9
// speedup vs baseline: 5.8374x; 1.0040x over previous
#include <cuda_runtime.h>
#include <cuda_fp16.h>
#include <math.h>
#include <stdint.h>

#define B_   2
#define S_   2048
#define H_   2048
#define NH_  16
#define NKV_ 4
#define HD_  128
#define I_   8192
#define NTOK (B_*S_)
#define EPSF 1e-6f

// ---------------------------------------------------------------------------
// Scratch
// ---------------------------------------------------------------------------
__device__ float  g_q [NTOK * NH_ * HD_];
__device__ float  g_k [NTOK * NKV_ * HD_];
__device__ float  g_v [NTOK * NKV_ * HD_];
__device__ float  g_x [NTOK * H_];
__device__ float  g_g [NTOK * I_];
__device__ float  g_u [NTOK * I_];
__device__ float  g_rope[S_ * HD_];
__device__ __half g_hh [NTOK * H_];
__device__ __half g_oh [NTOK * NH_ * HD_];
__device__ __half g_gh [NTOK * I_];
__device__ __half g_wqT[2048 * 2048];
__device__ __half g_wkT[512 * 2048];
__device__ __half g_wvT[512 * 2048];
__device__ __half g_woT[2048 * 2048];
__device__ __half g_wgT[8192 * 2048];
__device__ __half g_wuT[8192 * 2048];
__device__ __half g_wdT[2048 * 8192];

// ---------------------------------------------------------------------------
__device__ __forceinline__ void mma_f16(float* c, const unsigned* a, const unsigned* b) {
    asm volatile(
        "mma.sync.aligned.m16n8k16.row.col.f32.f16.f16.f32 "
        "{%0,%1,%2,%3},{%4,%5,%6,%7},{%8,%9},{%0,%1,%2,%3};\n"
        : "+f"(c[0]), "+f"(c[1]), "+f"(c[2]), "+f"(c[3])
        : "r"(a[0]), "r"(a[1]), "r"(a[2]), "r"(a[3]), "r"(b[0]), "r"(b[1]));
}

__device__ __forceinline__ unsigned h2u(__half2 h) {
    return *(unsigned*)&h;
}

// ---------------------------------------------------------------------------
__global__ void rope_table_kernel() {
    int idx = blockIdx.x * blockDim.x + threadIdx.x;
    if (idx >= S_ * 64) return;
    int pos = idx >> 6;
    int i   = idx & 63;
    float invf = 1.0f / powf(10000.0f, (float)i / 64.0f);
    float ang  = (float)pos * invf;
    g_rope[pos * HD_ + i]      = cosf(ang);
    g_rope[pos * HD_ + 64 + i] = sinf(ang);
}

// ---------------------------------------------------------------------------
__global__ __launch_bounds__(256) void transpose_cvt_kernel(
    const float* __restrict__ W, __half* __restrict__ Wt, int K, int N)
{
    __shared__ float t[32][33];
    int k0 = blockIdx.x * 32, n0 = blockIdx.y * 32;
    int tx = threadIdx.x, ty = threadIdx.y;
#pragma unroll
    for (int j = ty; j < 32; j += 8)
        t[j][tx] = W[(size_t)(k0 + j) * N + n0 + tx];
    __syncthreads();
    if (tx < 16) {
#pragma unroll
        for (int j = ty; j < 32; j += 8) {
            __half2 hv = __floats2half2_rn(t[2 * tx][j], t[2 * tx + 1][j]);
            *(__half2*)(Wt + (size_t)(n0 + j) * K + k0 + 2 * tx) = hv;
        }
    }
}

// ---------------------------------------------------------------------------
__global__ __launch_bounds__(256) void rmsnorm_kernel(
    const float* __restrict__ x, const float* __restrict__ w,
    __half* __restrict__ out)
{
    int row = blockIdx.x;
    const float* xr = x + (size_t)row * H_;
    float ss = 0.f;
#pragma unroll
    for (int it = 0; it < H_ / (256 * 4); it++) {
        int c = (it * 256 + threadIdx.x) * 4;
        float4 t = *(const float4*)(xr + c);
        ss += t.x * t.x + t.y * t.y + t.z * t.z + t.w * t.w;
    }
#pragma unroll
    for (int o = 16; o; o >>= 1) ss += __shfl_xor_sync(0xffffffffu, ss, o);
    __shared__ float red[8];
    if ((threadIdx.x & 31) == 0) red[threadIdx.x >> 5] = ss;
    __syncthreads();
    float tot = 0.f;
#pragma unroll
    for (int i = 0; i < 8; i++) tot += red[i];
    float inv = rsqrtf(tot * (1.0f / H_) + EPSF);
    __half* orow = out + (size_t)row * H_;
#pragma unroll
    for (int it = 0; it < H_ / (256 * 4); it++) {
        int c = (it * 256 + threadIdx.x) * 4;
        float4 t  = *(const float4*)(xr + c);
        float4 wv = *(const float4*)(w + c);
        __half2 h0 = __floats2half2_rn(wv.x * t.x * inv, wv.y * t.y * inv);
        __half2 h1 = __floats2half2_rn(wv.z * t.z * inv, wv.w * t.w * inv);
        *(__half2*)(orow + c)     = h0;
        *(__half2*)(orow + c + 2) = h1;
    }
}

// ---------------------------------------------------------------------------
// FP16 GEMM (unchanged from R8): 128x128x64 tiles, 256 threads.
// ---------------------------------------------------------------------------
#define HSTR 72
#define HBUF (128 * HSTR)
#define HG_SMEM (4 * HBUF * 2)

__global__ __launch_bounds__(256) void gemm_h_kernel(
    const __half* __restrict__ A, const __half* __restrict__ Bt,
    const __half* __restrict__ Bt2, const float* __restrict__ addend,
    float* __restrict__ C, float* __restrict__ C2,
    int M, int N, int K)
{
    extern __shared__ __half smh[];
    __half* As0 = smh;
    __half* Bs0 = smh + HBUF;
    __half* As1 = smh + 2 * HBUF;
    __half* Bs1 = smh + 3 * HBUF;

    if (blockIdx.z == 1) { Bt = Bt2; C = C2; }

    int tid = threadIdx.x;
    int bm = blockIdx.y * 128, bn = blockIdx.x * 128;
    int wid = tid >> 5, lane = tid & 31;
    int wm = (wid & 1) * 64;
    int wn = (wid >> 1) * 32;
    int grp = lane >> 2, qk = lane & 3;

    int lrow = tid >> 3;
    int lseg = (tid & 7) * 8;

    const __half* Ag = A  + (size_t)(bm + lrow) * K + lseg;
    const __half* Bg = Bt + (size_t)(bn + lrow) * K + lseg;

    float acc[4][4][4];
#pragma unroll
    for (int mt = 0; mt < 4; mt++)
#pragma unroll
        for (int nt = 0; nt < 4; nt++)
#pragma unroll
            for (int r = 0; r < 4; r++) acc[mt][nt][r] = 0.f;

    int nk = K / 64;
    uint4 pa[4], pb[4];

#pragma unroll
    for (int s = 0; s < 4; s++) {
        pa[s] = *(const uint4*)(Ag + (size_t)(32 * s) * K);
        pb[s] = *(const uint4*)(Bg + (size_t)(32 * s) * K);
    }
#pragma unroll
    for (int s = 0; s < 4; s++) {
        *(uint4*)(As0 + (lrow + 32 * s) * HSTR + lseg) = pa[s];
        *(uint4*)(Bs0 + (lrow + 32 * s) * HSTR + lseg) = pb[s];
    }
    __syncthreads();

    for (int kt = 0; kt < nk; kt++) {
        const uint32_t* Au = (const uint32_t*)((kt & 1) ? As1 : As0);
        const uint32_t* Bu = (const uint32_t*)((kt & 1) ? Bs1 : Bs0);
        __half* Asn = (kt & 1) ? As0 : As1;
        __half* Bsn = (kt & 1) ? Bs0 : Bs1;

        if (kt + 1 < nk) {
            const __half* Ag2 = Ag + (size_t)(kt + 1) * 64;
            const __half* Bg2 = Bg + (size_t)(kt + 1) * 64;
#pragma unroll
            for (int s = 0; s < 4; s++) {
                pa[s] = *(const uint4*)(Ag2 + (size_t)(32 * s) * K);
                pb[s] = *(const uint4*)(Bg2 + (size_t)(32 * s) * K);
            }
        }

#pragma unroll
        for (int ks = 0; ks < 4; ks++) {
            int w0 = ks * 8;
            unsigned afr[4][4], bfr[4][2];
#pragma unroll
            for (int mt = 0; mt < 4; mt++) {
                int r = wm + mt * 16 + grp;
                afr[mt][0] = Au[r * 36 + w0 + qk];
                afr[mt][1] = Au[(r + 8) * 36 + w0 + qk];
                afr[mt][2] = Au[r * 36 + w0 + qk + 4];
                afr[mt][3] = Au[(r + 8) * 36 + w0 + qk + 4];
            }
#pragma unroll
            for (int nt = 0; nt < 4; nt++) {
                int n = wn + nt * 8 + grp;
                bfr[nt][0] = Bu[n * 36 + w0 + qk];
                bfr[nt][1] = Bu[n * 36 + w0 + qk + 4];
            }
#pragma unroll
            for (int mt = 0; mt < 4; mt++)
#pragma unroll
                for (int nt = 0; nt < 4; nt++)
                    mma_f16(acc[mt][nt], afr[mt], bfr[nt]);
        }

        if (kt + 1 < nk) {
#pragma unroll
            for (int s = 0; s < 4; s++) {
                *(uint4*)(Asn + (lrow + 32 * s) * HSTR + lseg) = pa[s];
                *(uint4*)(Bsn + (lrow + 32 * s) * HSTR + lseg) = pb[s];
            }
        }
        __syncthreads();
    }

#pragma unroll
    for (int mt = 0; mt < 4; mt++) {
#pragma unroll
        for (int nt = 0; nt < 4; nt++) {
            int row0 = bm + wm + mt * 16 + grp;
            int col  = bn + wn + nt * 8 + qk * 2;
            float* c0 = C + (size_t)row0 * N + col;
            float* c1 = C + (size_t)(row0 + 8) * N + col;
            if (addend) {
                const float* a0 = addend + (size_t)row0 * N + col;
                const float* a1 = addend + (size_t)(row0 + 8) * N + col;
                *(float2*)c0 = make_float2(acc[mt][nt][0] + a0[0], acc[mt][nt][1] + a0[1]);
                *(float2*)c1 = make_float2(acc[mt][nt][2] + a1[0], acc[mt][nt][3] + a1[1]);
            } else {
                *(float2*)c0 = make_float2(acc[mt][nt][0], acc[mt][nt][1]);
                *(float2*)c1 = make_float2(acc[mt][nt][2], acc[mt][nt][3]);
            }
        }
    }
}

// ---------------------------------------------------------------------------
__global__ __launch_bounds__(128) void rope_norm_kernel(
    float* __restrict__ qkp, const float* __restrict__ w, int nheads)
{
    int tok  = blockIdx.x;
    int warp = threadIdx.x >> 5;
    int lane = threadIdx.x & 31;
    int head = blockIdx.y * 4 + warp;
    int pos  = tok % S_;

    float* base = qkp + ((size_t)tok * nheads + head) * HD_;
    float a0 = base[lane];      float a1 = base[lane + 32];
    float b0 = base[lane + 64]; float b1 = base[lane + 96];

    const float* rc = g_rope + (size_t)pos * HD_;
    float c0 = rc[lane],      s0 = rc[64 + lane];
    float c1 = rc[lane + 32], s1 = rc[96 + lane];

    float r0  = a0 * c0 - b0 * s0;
    float r64 = b0 * c0 + a0 * s0;
    float r32 = a1 * c1 - b1 * s1;
    float r96 = b1 * c1 + a1 * s1;

    float ss = r0 * r0 + r32 * r32 + r64 * r64 + r96 * r96;
#pragma unroll
    for (int o = 16; o; o >>= 1) ss += __shfl_xor_sync(0xffffffffu, ss, o);
    float inv = rsqrtf(ss * (1.0f / HD_) + EPSF);

    base[lane]      = w[lane]      * r0  * inv;
    base[lane + 32] = w[lane + 32] * r32 * inv;
    base[lane + 64] = w[lane + 64] * r64 * inv;
    base[lane + 96] = w[lane + 96] * r96 * inv;
}

// ---------------------------------------------------------------------------
// FP16 tensor-core flash attention. BQ=128, BK=64, 256 threads, m16n8k16.
// Q/K: K-major halves, word stride 36. V: transposed pair-packed words,
// stride 36. P: pair-packed words, stride 36. All LDS conflict-free.
// ---------------------------------------------------------------------------
#define FBQ 128
#define FBK 64
#define FQW 36      // words per Q/K row (64 words data for Q... 128 halves = 64 words)
// Q row = 128 halves = 64 words -> stride 68 words? NO: use 68.
// Recompute: Q/K rows have 128 halves = 64 data words; stride must be ≡4 mod 32 -> 68.
#undef FQW
#define QKW 68      // word stride for Q and K rows (64 + 4 pad)
#define VTW 36      // word stride for Vt rows (32 + 4 pad)
#define PW  36      // word stride for P rows (32 + 4 pad)
#define QS_WORDS (FBQ * QKW)
#define KS_WORDS (FBK * QKW)
#define VT_WORDS (HD_ * VTW)
#define PS_WORDS (FBQ * PW)
#define FLASH_SMEM ((QS_WORDS + KS_WORDS + VT_WORDS + PS_WORDS) * 4)

__global__ __launch_bounds__(256) void flash_kernel(
    const float* __restrict__ q, const float* __restrict__ k,
    const float* __restrict__ v, __half* __restrict__ o)
{
    extern __shared__ unsigned smw[];
    unsigned* Qw = smw;
    unsigned* Kw = Qw + QS_WORDS;
    unsigned* Vw = Kw + KS_WORDS;
    unsigned* Pw = Vw + VT_WORDS;

    int qb = gridDim.x - 1 - blockIdx.x;
    int bh = blockIdx.y;
    int b  = bh / NH_, h = bh % NH_;
    int kvh = h / (NH_ / NKV_);

    int tid = threadIdx.x;
    int wid = tid >> 5, lane = tid & 31;
    int wm = wid * 16;
    int grp = lane >> 2, qk = lane & 3;

    const float scale = 0.08838834764831845f;

    // load Q tile -> fp16 K-major
    const float* qbase = q + ((size_t)(b * S_ + qb * FBQ) * NH_ + h) * HD_;
    for (int i = tid; i < FBQ * (HD_ / 4); i += 256) {
        int r  = i >> 5;
        int c4 = (i & 31) * 4;
        float4 t = *(const float4*)(qbase + (size_t)r * NH_ * HD_ + c4);
        unsigned* dst = Qw + r * QKW + (c4 >> 1);
        dst[0] = h2u(__floats2half2_rn(t.x * scale, t.y * scale));
        dst[1] = h2u(__floats2half2_rn(t.z * scale, t.w * scale));
    }

    float m0 = -1e30f, m1 = -1e30f, l0 = 0.f, l1 = 0.f;
    float oacc[16][4];
#pragma unroll
    for (int nt = 0; nt < 16; nt++)
#pragma unroll
        for (int r = 0; r < 4; r++) oacc[nt][r] = 0.f;

    int nkb = 2 * qb + 2;
    for (int kb = 0; kb < nkb; kb++) {
        __syncthreads();
        const float* kbase = k + ((size_t)(b * S_ + kb * FBK) * NKV_ + kvh) * HD_;
        const float* vbase = v + ((size_t)(b * S_ + kb * FBK) * NKV_ + kvh) * HD_;
        // K tile: fp16 K-major
        for (int i = tid; i < FBK * (HD_ / 4); i += 256) {
            int r  = i >> 5;
            int c4 = (i & 31) * 4;
            float4 tk = *(const float4*)(kbase + (size_t)r * NKV_ * HD_ + c4);
            unsigned* kd = Kw + r * QKW + (c4 >> 1);
            kd[0] = h2u(__floats2half2_rn(tk.x, tk.y));
            kd[1] = h2u(__floats2half2_rn(tk.z, tk.w));
        }
        // V tile: transposed pair-packed. i: sp = seq pair (0..31), cg = hd/4 chunk
        for (int i = tid; i < 32 * 32; i += 256) {
            int sp = i & 31;
            int c4 = (i >> 5) * 4;
            float4 va = *(const float4*)(vbase + (size_t)(2 * sp)     * NKV_ * HD_ + c4);
            float4 vb = *(const float4*)(vbase + (size_t)(2 * sp + 1) * NKV_ * HD_ + c4);
            Vw[(c4 + 0) * VTW + sp] = h2u(__floats2half2_rn(va.x, vb.x));
            Vw[(c4 + 1) * VTW + sp] = h2u(__floats2half2_rn(va.y, vb.y));
            Vw[(c4 + 2) * VTW + sp] = h2u(__floats2half2_rn(va.z, vb.z));
            Vw[(c4 + 3) * VTW + sp] = h2u(__floats2half2_rn(va.w, vb.w));
        }
        __syncthreads();

        // ---- S = Q K^T : warp tile 16x64, k=128 via 8 k16-steps ----
        float s[8][4];
#pragma unroll
        for (int nt = 0; nt < 8; nt++)
#pragma unroll
            for (int r = 0; r < 4; r++) s[nt][r] = 0.f;

#pragma unroll
        for (int ks = 0; ks < 8; ks++) {
            int w0 = ks * 8;
            unsigned a[4];
            a[0] = Qw[(wm + grp)     * QKW + w0 + qk];
            a[1] = Qw[(wm + grp + 8) * QKW + w0 + qk];
            a[2] = Qw[(wm + grp)     * QKW + w0 + qk + 4];
            a[3] = Qw[(wm + grp + 8) * QKW + w0 + qk + 4];
#pragma unroll
            for (int nt = 0; nt < 8; nt++) {
                unsigned bfr[2];
                bfr[0] = Kw[(nt * 8 + grp) * QKW + w0 + qk];
                bfr[1] = Kw[(nt * 8 + grp) * QKW + w0 + qk + 4];
                mma_f16(s[nt], a, bfr);
            }
        }

        if (kb >= 2 * qb) {
            int r0 = qb * FBQ + wm + grp;
            int cb = kb * FBK + qk * 2;
#pragma unroll
            for (int nt = 0; nt < 8; nt++) {
                int c0 = cb + nt * 8;
                if (c0     > r0)     s[nt][0] = -1e30f;
                if (c0 + 1 > r0)     s[nt][1] = -1e30f;
                if (c0     > r0 + 8) s[nt][2] = -1e30f;
                if (c0 + 1 > r0 + 8) s[nt][3] = -1e30f;
            }
        }

        float mx0 = -1e30f, mx1 = -1e30f;
#pragma unroll
        for (int nt = 0; nt < 8; nt++) {
            mx0 = fmaxf(mx0, fmaxf(s[nt][0], s[nt][1]));
            mx1 = fmaxf(mx1, fmaxf(s[nt][2], s[nt][3]));
        }
        mx0 = fmaxf(mx0, __shfl_xor_sync(0xffffffffu, mx0, 1));
        mx0 = fmaxf(mx0, __shfl_xor_sync(0xffffffffu, mx0, 2));
        mx1 = fmaxf(mx1, __shfl_xor_sync(0xffffffffu, mx1, 1));
        mx1 = fmaxf(mx1, __shfl_xor_sync(0xffffffffu, mx1, 2));

        float mn0 = fmaxf(m0, mx0), mn1 = fmaxf(m1, mx1);
        float corr0 = __expf(m0 - mn0), corr1 = __expf(m1 - mn1);
        m0 = mn0; m1 = mn1;

        float rs0 = 0.f, rs1 = 0.f;
#pragma unroll
        for (int nt = 0; nt < 8; nt++) {
            float p0 = __expf(s[nt][0] - mn0);
            float p1 = __expf(s[nt][1] - mn0);
            float p2 = __expf(s[nt][2] - mn1);
            float p3 = __expf(s[nt][3] - mn1);
            rs0 += p0 + p1; rs1 += p2 + p3;
            Pw[(wm + grp)     * PW + nt * 4 + qk] = h2u(__floats2half2_rn(p0, p1));
            Pw[(wm + grp + 8) * PW + nt * 4 + qk] = h2u(__floats2half2_rn(p2, p3));
        }
        rs0 += __shfl_xor_sync(0xffffffffu, rs0, 1);
        rs0 += __shfl_xor_sync(0xffffffffu, rs0, 2);
        rs1 += __shfl_xor_sync(0xffffffffu, rs1, 1);
        rs1 += __shfl_xor_sync(0xffffffffu, rs1, 2);
        l0 = l0 * corr0 + rs0;
        l1 = l1 * corr1 + rs1;

#pragma unroll
        for (int nt = 0; nt < 16; nt++) {
            oacc[nt][0] *= corr0; oacc[nt][1] *= corr0;
            oacc[nt][2] *= corr1; oacc[nt][3] *= corr1;
        }
        __syncwarp();

        // ---- O += P V : warp tile 16x128, k=64 via 4 k16-steps ----
#pragma unroll
        for (int ks = 0; ks < 4; ks++) {
            int w0 = ks * 8;
            unsigned a[4];
            a[0] = Pw[(wm + grp)     * PW + w0 + qk];
            a[1] = Pw[(wm + grp + 8) * PW + w0 + qk];
            a[2] = Pw[(wm + grp)     * PW + w0 + qk + 4];
            a[3] = Pw[(wm + grp + 8) * PW + w0 + qk + 4];
#pragma unroll
            for (int nt = 0; nt < 16; nt++) {
                unsigned bfr[2];
                bfr[0] = Vw[(nt * 8 + grp) * VTW + w0 + qk];
                bfr[1] = Vw[(nt * 8 + grp) * VTW + w0 + qk + 4];
                mma_f16(oacc[nt], a, bfr);
            }
        }
    }

    float inv0 = 1.0f / l0, inv1 = 1.0f / l1;
    int r0 = qb * FBQ + wm + grp;
    __half* out0 = o + ((size_t)(b * S_ + r0) * NH_ + h) * HD_;
    __half* out1 = o + ((size_t)(b * S_ + r0 + 8) * NH_ + h) * HD_;
#pragma unroll
    for (int nt = 0; nt < 16; nt++) {
        int col = nt * 8 + qk * 2;
        *(__half2*)(out0 + col) = __floats2half2_rn(oacc[nt][0] * inv0, oacc[nt][1] * inv0);
        *(__half2*)(out1 + col) = __floats2half2_rn(oacc[nt][2] * inv1, oacc[nt][3] * inv1);
    }
}

// ---------------------------------------------------------------------------
__global__ __launch_bounds__(256) void swiglu_kernel(
    const float* __restrict__ g, const float* __restrict__ u,
    __half* __restrict__ outh)
{
    int idx = blockIdx.x * 256 + threadIdx.x;
    if (idx >= NTOK * (I_ / 4)) return;
    float4 gv = ((const float4*)g)[idx];
    float4 uv = ((const float4*)u)[idx];
    float r0 = gv.x / (1.f + __expf(-gv.x)) * uv.x;
    float r1 = gv.y / (1.f + __expf(-gv.y)) * uv.y;
    float r2 = gv.z / (1.f + __expf(-gv.z)) * uv.z;
    float r3 = gv.w / (1.f + __expf(-gv.w)) * uv.w;
    __half* dst = outh + (size_t)idx * 4;
    *(__half2*)(dst)     = __floats2half2_rn(r0, r1);
    *(__half2*)(dst + 2) = __floats2half2_rn(r2, r3);
}

// ---------------------------------------------------------------------------
extern "C" void kernel_launch(void* const* d_in, const int* in_sizes, int n_in,
                              void* d_out, int out_size)
{
    const float* hidden = (const float*)d_in[0];
    const float* ln1_w = (const float*)d_in[3];
    const float* Wq    = (const float*)d_in[4];
    const float* Wk    = (const float*)d_in[5];
    const float* Wv    = (const float*)d_in[6];
    const float* Wo    = (const float*)d_in[7];
    const float* qn_w  = (const float*)d_in[8];
    const float* kn_w  = (const float*)d_in[9];
    const float* ln2_w = (const float*)d_in[10];
    const float* Wg    = (const float*)d_in[11];
    const float* Wu    = (const float*)d_in[12];
    const float* Wd    = (const float*)d_in[13];
    float* out = (float*)d_out;

    float *p_q, *p_k, *p_v, *p_x, *p_g, *p_u;
    __half *p_hh, *p_oh, *p_gh;
    __half *p_wqT, *p_wkT, *p_wvT, *p_woT, *p_wgT, *p_wuT, *p_wdT;
    cudaGetSymbolAddress((void**)&p_q, g_q);
    cudaGetSymbolAddress((void**)&p_k, g_k);
    cudaGetSymbolAddress((void**)&p_v, g_v);
    cudaGetSymbolAddress((void**)&p_x, g_x);
    cudaGetSymbolAddress((void**)&p_g, g_g);
    cudaGetSymbolAddress((void**)&p_u, g_u);
    cudaGetSymbolAddress((void**)&p_hh, g_hh);
    cudaGetSymbolAddress((void**)&p_oh, g_oh);
    cudaGetSymbolAddress((void**)&p_gh, g_gh);
    cudaGetSymbolAddress((void**)&p_wqT, g_wqT);
    cudaGetSymbolAddress((void**)&p_wkT, g_wkT);
    cudaGetSymbolAddress((void**)&p_wvT, g_wvT);
    cudaGetSymbolAddress((void**)&p_woT, g_woT);
    cudaGetSymbolAddress((void**)&p_wgT, g_wgT);
    cudaGetSymbolAddress((void**)&p_wuT, g_wuT);
    cudaGetSymbolAddress((void**)&p_wdT, g_wdT);

    cudaFuncSetAttribute(flash_kernel,
                         cudaFuncAttributeMaxDynamicSharedMemorySize, FLASH_SMEM);
    cudaFuncSetAttribute(gemm_h_kernel,
                         cudaFuncAttributeMaxDynamicSharedMemorySize, HG_SMEM);

    rope_table_kernel<<<(S_ * 64 + 255) / 256, 256>>>();

    dim3 tb(32, 8);
    transpose_cvt_kernel<<<dim3(64, 64),  tb>>>(Wq, p_wqT, 2048, 2048);
    transpose_cvt_kernel<<<dim3(64, 16),  tb>>>(Wk, p_wkT, 2048, 512);
    transpose_cvt_kernel<<<dim3(64, 16),  tb>>>(Wv, p_wvT, 2048, 512);
    transpose_cvt_kernel<<<dim3(64, 64),  tb>>>(Wo, p_woT, 2048, 2048);
    transpose_cvt_kernel<<<dim3(64, 256), tb>>>(Wg, p_wgT, 2048, 8192);
    transpose_cvt_kernel<<<dim3(64, 256), tb>>>(Wu, p_wuT, 2048, 8192);
    transpose_cvt_kernel<<<dim3(256, 64), tb>>>(Wd, p_wdT, 8192, 2048);

    // Attention block
    rmsnorm_kernel<<<NTOK, 256>>>(hidden, ln1_w, p_hh);
    gemm_h_kernel<<<dim3((NH_ * HD_) / 128, NTOK / 128, 1), 256, HG_SMEM>>>(
        p_hh, p_wqT, nullptr, nullptr, p_q, nullptr, NTOK, NH_ * HD_, H_);
    gemm_h_kernel<<<dim3((NKV_ * HD_) / 128, NTOK / 128, 2), 256, HG_SMEM>>>(
        p_hh, p_wkT, p_wvT, nullptr, p_k, p_v, NTOK, NKV_ * HD_, H_);
    rope_norm_kernel<<<dim3(NTOK, NH_ / 4), 128>>>(p_q, qn_w, NH_);
    rope_norm_kernel<<<dim3(NTOK, NKV_ / 4), 128>>>(p_k, kn_w, NKV_);
    flash_kernel<<<dim3(S_ / FBQ, B_ * NH_), 256, FLASH_SMEM>>>(p_q, p_k, p_v, p_oh);
    gemm_h_kernel<<<dim3(H_ / 128, NTOK / 128, 1), 256, HG_SMEM>>>(
        p_oh, p_woT, nullptr, hidden, p_x, nullptr, NTOK, H_, H_);

    // MLP block
    rmsnorm_kernel<<<NTOK, 256>>>(p_x, ln2_w, p_hh);
    gemm_h_kernel<<<dim3(I_ / 128, NTOK / 128, 2), 256, HG_SMEM>>>(
        p_hh, p_wgT, p_wuT, nullptr, p_g, p_u, NTOK, I_, H_);
    swiglu_kernel<<<(NTOK * (I_ / 4) + 255) / 256, 256>>>(p_g, p_u, p_gh);
    gemm_h_kernel<<<dim3(H_ / 128, NTOK / 128, 1), 256, HG_SMEM>>>(
        p_gh, p_wdT, nullptr, p_x, out, nullptr, NTOK, H_, I_);
}

// round 10
// speedup vs baseline: 6.4781x; 1.1097x over previous
#include <cuda_runtime.h>
#include <cuda_fp16.h>
#include <math.h>
#include <stdint.h>

#define B_   2
#define S_   2048
#define H_   2048
#define NH_  16
#define NKV_ 4
#define HD_  128
#define I_   8192
#define NTOK (B_*S_)
#define EPSF 1e-6f

// ---------------------------------------------------------------------------
// Scratch
// ---------------------------------------------------------------------------
__device__ float  g_q [NTOK * NH_ * HD_];
__device__ float  g_k [NTOK * NKV_ * HD_];
__device__ float  g_v [NTOK * NKV_ * HD_];
__device__ float  g_x [NTOK * H_];
__device__ float  g_g [NTOK * I_];
__device__ float  g_u [NTOK * I_];
__device__ float  g_rope[S_ * HD_];
__device__ __half g_hh [NTOK * H_];
__device__ __half g_oh [NTOK * NH_ * HD_];
__device__ __half g_gh [NTOK * I_];
__device__ __half g_wqT[2048 * 2048];
__device__ __half g_wkT[512 * 2048];
__device__ __half g_wvT[512 * 2048];
__device__ __half g_woT[2048 * 2048];
__device__ __half g_wgT[8192 * 2048];
__device__ __half g_wuT[8192 * 2048];
__device__ __half g_wdT[2048 * 8192];

// ---------------------------------------------------------------------------
__device__ __forceinline__ void mma_f16(float* c, const unsigned* a, const unsigned* b) {
    asm volatile(
        "mma.sync.aligned.m16n8k16.row.col.f32.f16.f16.f32 "
        "{%0,%1,%2,%3},{%4,%5,%6,%7},{%8,%9},{%0,%1,%2,%3};\n"
        : "+f"(c[0]), "+f"(c[1]), "+f"(c[2]), "+f"(c[3])
        : "r"(a[0]), "r"(a[1]), "r"(a[2]), "r"(a[3]), "r"(b[0]), "r"(b[1]));
}

__device__ __forceinline__ unsigned h2u(__half2 h) {
    return *(unsigned*)&h;
}

__device__ __forceinline__ unsigned smem_u32(const void* p) {
    return (unsigned)__cvta_generic_to_shared(p);
}

#define CP_ASYNC16(dst, src) \
    asm volatile("cp.async.ca.shared.global [%0], [%1], 16;" :: "r"(dst), "l"(src))
#define CP_COMMIT() asm volatile("cp.async.commit_group;" ::: "memory")
#define CP_WAIT(n)  asm volatile("cp.async.wait_group %0;" :: "n"(n) : "memory")

// ---------------------------------------------------------------------------
__global__ void rope_table_kernel() {
    int idx = blockIdx.x * blockDim.x + threadIdx.x;
    if (idx >= S_ * 64) return;
    int pos = idx >> 6;
    int i   = idx & 63;
    float invf = 1.0f / powf(10000.0f, (float)i / 64.0f);
    float ang  = (float)pos * invf;
    g_rope[pos * HD_ + i]      = cosf(ang);
    g_rope[pos * HD_ + 64 + i] = sinf(ang);
}

// ---------------------------------------------------------------------------
__global__ __launch_bounds__(256) void transpose_cvt_kernel(
    const float* __restrict__ W, __half* __restrict__ Wt, int K, int N)
{
    __shared__ float t[32][33];
    int k0 = blockIdx.x * 32, n0 = blockIdx.y * 32;
    int tx = threadIdx.x, ty = threadIdx.y;
#pragma unroll
    for (int j = ty; j < 32; j += 8)
        t[j][tx] = W[(size_t)(k0 + j) * N + n0 + tx];
    __syncthreads();
    if (tx < 16) {
#pragma unroll
        for (int j = ty; j < 32; j += 8) {
            __half2 hv = __floats2half2_rn(t[2 * tx][j], t[2 * tx + 1][j]);
            *(__half2*)(Wt + (size_t)(n0 + j) * K + k0 + 2 * tx) = hv;
        }
    }
}

// ---------------------------------------------------------------------------
__global__ __launch_bounds__(256) void rmsnorm_kernel(
    const float* __restrict__ x, const float* __restrict__ w,
    __half* __restrict__ out)
{
    int row = blockIdx.x;
    const float* xr = x + (size_t)row * H_;
    float ss = 0.f;
#pragma unroll
    for (int it = 0; it < H_ / (256 * 4); it++) {
        int c = (it * 256 + threadIdx.x) * 4;
        float4 t = *(const float4*)(xr + c);
        ss += t.x * t.x + t.y * t.y + t.z * t.z + t.w * t.w;
    }
#pragma unroll
    for (int o = 16; o; o >>= 1) ss += __shfl_xor_sync(0xffffffffu, ss, o);
    __shared__ float red[8];
    if ((threadIdx.x & 31) == 0) red[threadIdx.x >> 5] = ss;
    __syncthreads();
    float tot = 0.f;
#pragma unroll
    for (int i = 0; i < 8; i++) tot += red[i];
    float inv = rsqrtf(tot * (1.0f / H_) + EPSF);
    __half* orow = out + (size_t)row * H_;
#pragma unroll
    for (int it = 0; it < H_ / (256 * 4); it++) {
        int c = (it * 256 + threadIdx.x) * 4;
        float4 t  = *(const float4*)(xr + c);
        float4 wv = *(const float4*)(w + c);
        __half2 h0 = __floats2half2_rn(wv.x * t.x * inv, wv.y * t.y * inv);
        __half2 h1 = __floats2half2_rn(wv.z * t.z * inv, wv.w * t.w * inv);
        *(__half2*)(orow + c)     = h0;
        *(__half2*)(orow + c + 2) = h1;
    }
}

// ---------------------------------------------------------------------------
// FP16 GEMM with cp.async, 2-stage, 2 CTAs/SM. 128x128x64 tiles.
// ---------------------------------------------------------------------------
#define HSTR 72
#define HBUF (128 * HSTR)
#define HG_SMEM (4 * HBUF * 2)

__global__ __launch_bounds__(256, 2) void gemm_h_kernel(
    const __half* __restrict__ A, const __half* __restrict__ Bt,
    const __half* __restrict__ Bt2, const float* __restrict__ addend,
    float* __restrict__ C, float* __restrict__ C2,
    int M, int N, int K)
{
    extern __shared__ __half smh[];
    __half* As0 = smh;
    __half* Bs0 = smh + HBUF;
    __half* As1 = smh + 2 * HBUF;
    __half* Bs1 = smh + 3 * HBUF;

    if (blockIdx.z == 1) { Bt = Bt2; C = C2; }

    int tid = threadIdx.x;
    int bm = blockIdx.y * 128, bn = blockIdx.x * 128;
    int wid = tid >> 5, lane = tid & 31;
    int wm = (wid & 1) * 64;
    int wn = (wid >> 1) * 32;
    int grp = lane >> 2, qk = lane & 3;

    int lrow = tid >> 3;
    int lseg = (tid & 7) * 8;

    const __half* Ag = A  + (size_t)(bm + lrow) * K + lseg;
    const __half* Bg = Bt + (size_t)(bn + lrow) * K + lseg;

    unsigned sa[2], sb[2];
    sa[0] = smem_u32(As0 + lrow * HSTR + lseg);
    sb[0] = smem_u32(Bs0 + lrow * HSTR + lseg);
    sa[1] = smem_u32(As1 + lrow * HSTR + lseg);
    sb[1] = smem_u32(Bs1 + lrow * HSTR + lseg);
    const unsigned rowstep = 32 * HSTR * 2;   // bytes per 32 rows

    float acc[4][4][4];
#pragma unroll
    for (int mt = 0; mt < 4; mt++)
#pragma unroll
        for (int nt = 0; nt < 4; nt++)
#pragma unroll
            for (int r = 0; r < 4; r++) acc[mt][nt][r] = 0.f;

    int nk = K / 64;

    // prologue: stage 0 and 1
#pragma unroll
    for (int s = 0; s < 4; s++) {
        CP_ASYNC16(sa[0] + s * rowstep, Ag + (size_t)(32 * s) * K);
        CP_ASYNC16(sb[0] + s * rowstep, Bg + (size_t)(32 * s) * K);
    }
    CP_COMMIT();
    if (nk > 1) {
#pragma unroll
        for (int s = 0; s < 4; s++) {
            CP_ASYNC16(sa[1] + s * rowstep, Ag + (size_t)(32 * s) * K + 64);
            CP_ASYNC16(sb[1] + s * rowstep, Bg + (size_t)(32 * s) * K + 64);
        }
        CP_COMMIT();
        CP_WAIT(1);
    } else {
        CP_WAIT(0);
    }
    __syncthreads();

    for (int kt = 0; kt < nk; kt++) {
        int cur = kt & 1;
        const uint32_t* Au = (const uint32_t*)(cur ? As1 : As0);
        const uint32_t* Bu = (const uint32_t*)(cur ? Bs1 : Bs0);

#pragma unroll
        for (int ks = 0; ks < 4; ks++) {
            int w0 = ks * 8;
            unsigned afr[4][4], bfr[4][2];
#pragma unroll
            for (int mt = 0; mt < 4; mt++) {
                int r = wm + mt * 16 + grp;
                afr[mt][0] = Au[r * 36 + w0 + qk];
                afr[mt][1] = Au[(r + 8) * 36 + w0 + qk];
                afr[mt][2] = Au[r * 36 + w0 + qk + 4];
                afr[mt][3] = Au[(r + 8) * 36 + w0 + qk + 4];
            }
#pragma unroll
            for (int nt = 0; nt < 4; nt++) {
                int n = wn + nt * 8 + grp;
                bfr[nt][0] = Bu[n * 36 + w0 + qk];
                bfr[nt][1] = Bu[n * 36 + w0 + qk + 4];
            }
#pragma unroll
            for (int mt = 0; mt < 4; mt++)
#pragma unroll
                for (int nt = 0; nt < 4; nt++)
                    mma_f16(acc[mt][nt], afr[mt], bfr[nt]);
        }
        __syncthreads();   // everyone done reading buf cur

        if (kt + 2 < nk) {
            const __half* Ag2 = Ag + (size_t)(kt + 2) * 64;
            const __half* Bg2 = Bg + (size_t)(kt + 2) * 64;
#pragma unroll
            for (int s = 0; s < 4; s++) {
                CP_ASYNC16(sa[cur] + s * rowstep, Ag2 + (size_t)(32 * s) * K);
                CP_ASYNC16(sb[cur] + s * rowstep, Bg2 + (size_t)(32 * s) * K);
            }
            CP_COMMIT();
            CP_WAIT(1);         // stage kt+1 complete
            __syncthreads();
        } else if (kt + 1 < nk) {
            CP_WAIT(0);
            __syncthreads();
        }
    }

#pragma unroll
    for (int mt = 0; mt < 4; mt++) {
#pragma unroll
        for (int nt = 0; nt < 4; nt++) {
            int row0 = bm + wm + mt * 16 + grp;
            int col  = bn + wn + nt * 8 + qk * 2;
            float* c0 = C + (size_t)row0 * N + col;
            float* c1 = C + (size_t)(row0 + 8) * N + col;
            if (addend) {
                const float* a0 = addend + (size_t)row0 * N + col;
                const float* a1 = addend + (size_t)(row0 + 8) * N + col;
                *(float2*)c0 = make_float2(acc[mt][nt][0] + a0[0], acc[mt][nt][1] + a0[1]);
                *(float2*)c1 = make_float2(acc[mt][nt][2] + a1[0], acc[mt][nt][3] + a1[1]);
            } else {
                *(float2*)c0 = make_float2(acc[mt][nt][0], acc[mt][nt][1]);
                *(float2*)c1 = make_float2(acc[mt][nt][2], acc[mt][nt][3]);
            }
        }
    }
}

// ---------------------------------------------------------------------------
__global__ __launch_bounds__(128) void rope_norm_kernel(
    float* __restrict__ qkp, const float* __restrict__ w, int nheads)
{
    int tok  = blockIdx.x;
    int warp = threadIdx.x >> 5;
    int lane = threadIdx.x & 31;
    int head = blockIdx.y * 4 + warp;
    int pos  = tok % S_;

    float* base = qkp + ((size_t)tok * nheads + head) * HD_;
    float a0 = base[lane];      float a1 = base[lane + 32];
    float b0 = base[lane + 64]; float b1 = base[lane + 96];

    const float* rc = g_rope + (size_t)pos * HD_;
    float c0 = rc[lane],      s0 = rc[64 + lane];
    float c1 = rc[lane + 32], s1 = rc[96 + lane];

    float r0  = a0 * c0 - b0 * s0;
    float r64 = b0 * c0 + a0 * s0;
    float r32 = a1 * c1 - b1 * s1;
    float r96 = b1 * c1 + a1 * s1;

    float ss = r0 * r0 + r32 * r32 + r64 * r64 + r96 * r96;
#pragma unroll
    for (int o = 16; o; o >>= 1) ss += __shfl_xor_sync(0xffffffffu, ss, o);
    float inv = rsqrtf(ss * (1.0f / HD_) + EPSF);

    base[lane]      = w[lane]      * r0  * inv;
    base[lane + 32] = w[lane + 32] * r32 * inv;
    base[lane + 64] = w[lane + 64] * r64 * inv;
    base[lane + 96] = w[lane + 96] * r96 * inv;
}

// ---------------------------------------------------------------------------
// FP16 tensor-core flash attention, 2 CTAs/SM target.
// ---------------------------------------------------------------------------
#define FBQ 128
#define FBK 64
#define QKW 68
#define VTW 36
#define PW  36
#define QS_WORDS (FBQ * QKW)
#define KS_WORDS (FBK * QKW)
#define VT_WORDS (HD_ * VTW)
#define PS_WORDS (FBQ * PW)
#define FLASH_SMEM ((QS_WORDS + KS_WORDS + VT_WORDS + PS_WORDS) * 4)

__global__ __launch_bounds__(256, 2) void flash_kernel(
    const float* __restrict__ q, const float* __restrict__ k,
    const float* __restrict__ v, __half* __restrict__ o)
{
    extern __shared__ unsigned smw[];
    unsigned* Qw = smw;
    unsigned* Kw = Qw + QS_WORDS;
    unsigned* Vw = Kw + KS_WORDS;
    unsigned* Pw = Vw + VT_WORDS;

    int qb = gridDim.x - 1 - blockIdx.x;
    int bh = blockIdx.y;
    int b  = bh / NH_, h = bh % NH_;
    int kvh = h / (NH_ / NKV_);

    int tid = threadIdx.x;
    int wid = tid >> 5, lane = tid & 31;
    int wm = wid * 16;
    int grp = lane >> 2, qk = lane & 3;

    const float scale = 0.08838834764831845f;

    const float* qbase = q + ((size_t)(b * S_ + qb * FBQ) * NH_ + h) * HD_;
    for (int i = tid; i < FBQ * (HD_ / 4); i += 256) {
        int r  = i >> 5;
        int c4 = (i & 31) * 4;
        float4 t = *(const float4*)(qbase + (size_t)r * NH_ * HD_ + c4);
        unsigned* dst = Qw + r * QKW + (c4 >> 1);
        dst[0] = h2u(__floats2half2_rn(t.x * scale, t.y * scale));
        dst[1] = h2u(__floats2half2_rn(t.z * scale, t.w * scale));
    }

    float m0 = -1e30f, m1 = -1e30f, l0 = 0.f, l1 = 0.f;
    float oacc[16][4];
#pragma unroll
    for (int nt = 0; nt < 16; nt++)
#pragma unroll
        for (int r = 0; r < 4; r++) oacc[nt][r] = 0.f;

    int nkb = 2 * qb + 2;
    for (int kb = 0; kb < nkb; kb++) {
        __syncthreads();
        const float* kbase = k + ((size_t)(b * S_ + kb * FBK) * NKV_ + kvh) * HD_;
        const float* vbase = v + ((size_t)(b * S_ + kb * FBK) * NKV_ + kvh) * HD_;
        for (int i = tid; i < FBK * (HD_ / 4); i += 256) {
            int r  = i >> 5;
            int c4 = (i & 31) * 4;
            float4 tk = *(const float4*)(kbase + (size_t)r * NKV_ * HD_ + c4);
            unsigned* kd = Kw + r * QKW + (c4 >> 1);
            kd[0] = h2u(__floats2half2_rn(tk.x, tk.y));
            kd[1] = h2u(__floats2half2_rn(tk.z, tk.w));
        }
        for (int i = tid; i < 32 * 32; i += 256) {
            int sp = i & 31;
            int c4 = (i >> 5) * 4;
            float4 va = *(const float4*)(vbase + (size_t)(2 * sp)     * NKV_ * HD_ + c4);
            float4 vb = *(const float4*)(vbase + (size_t)(2 * sp + 1) * NKV_ * HD_ + c4);
            Vw[(c4 + 0) * VTW + sp] = h2u(__floats2half2_rn(va.x, vb.x));
            Vw[(c4 + 1) * VTW + sp] = h2u(__floats2half2_rn(va.y, vb.y));
            Vw[(c4 + 2) * VTW + sp] = h2u(__floats2half2_rn(va.z, vb.z));
            Vw[(c4 + 3) * VTW + sp] = h2u(__floats2half2_rn(va.w, vb.w));
        }
        __syncthreads();

        float s[8][4];
#pragma unroll
        for (int nt = 0; nt < 8; nt++)
#pragma unroll
            for (int r = 0; r < 4; r++) s[nt][r] = 0.f;

#pragma unroll
        for (int ks = 0; ks < 8; ks++) {
            int w0 = ks * 8;
            unsigned a[4];
            a[0] = Qw[(wm + grp)     * QKW + w0 + qk];
            a[1] = Qw[(wm + grp + 8) * QKW + w0 + qk];
            a[2] = Qw[(wm + grp)     * QKW + w0 + qk + 4];
            a[3] = Qw[(wm + grp + 8) * QKW + w0 + qk + 4];
#pragma unroll
            for (int nt = 0; nt < 8; nt++) {
                unsigned bfr[2];
                bfr[0] = Kw[(nt * 8 + grp) * QKW + w0 + qk];
                bfr[1] = Kw[(nt * 8 + grp) * QKW + w0 + qk + 4];
                mma_f16(s[nt], a, bfr);
            }
        }

        if (kb >= 2 * qb) {
            int r0 = qb * FBQ + wm + grp;
            int cb = kb * FBK + qk * 2;
#pragma unroll
            for (int nt = 0; nt < 8; nt++) {
                int c0 = cb + nt * 8;
                if (c0     > r0)     s[nt][0] = -1e30f;
                if (c0 + 1 > r0)     s[nt][1] = -1e30f;
                if (c0     > r0 + 8) s[nt][2] = -1e30f;
                if (c0 + 1 > r0 + 8) s[nt][3] = -1e30f;
            }
        }

        float mx0 = -1e30f, mx1 = -1e30f;
#pragma unroll
        for (int nt = 0; nt < 8; nt++) {
            mx0 = fmaxf(mx0, fmaxf(s[nt][0], s[nt][1]));
            mx1 = fmaxf(mx1, fmaxf(s[nt][2], s[nt][3]));
        }
        mx0 = fmaxf(mx0, __shfl_xor_sync(0xffffffffu, mx0, 1));
        mx0 = fmaxf(mx0, __shfl_xor_sync(0xffffffffu, mx0, 2));
        mx1 = fmaxf(mx1, __shfl_xor_sync(0xffffffffu, mx1, 1));
        mx1 = fmaxf(mx1, __shfl_xor_sync(0xffffffffu, mx1, 2));

        float mn0 = fmaxf(m0, mx0), mn1 = fmaxf(m1, mx1);
        float corr0 = __expf(m0 - mn0), corr1 = __expf(m1 - mn1);
        m0 = mn0; m1 = mn1;

        float rs0 = 0.f, rs1 = 0.f;
#pragma unroll
        for (int nt = 0; nt < 8; nt++) {
            float p0 = __expf(s[nt][0] - mn0);
            float p1 = __expf(s[nt][1] - mn0);
            float p2 = __expf(s[nt][2] - mn1);
            float p3 = __expf(s[nt][3] - mn1);
            rs0 += p0 + p1; rs1 += p2 + p3;
            Pw[(wm + grp)     * PW + nt * 4 + qk] = h2u(__floats2half2_rn(p0, p1));
            Pw[(wm + grp + 8) * PW + nt * 4 + qk] = h2u(__floats2half2_rn(p2, p3));
        }
        rs0 += __shfl_xor_sync(0xffffffffu, rs0, 1);
        rs0 += __shfl_xor_sync(0xffffffffu, rs0, 2);
        rs1 += __shfl_xor_sync(0xffffffffu, rs1, 1);
        rs1 += __shfl_xor_sync(0xffffffffu, rs1, 2);
        l0 = l0 * corr0 + rs0;
        l1 = l1 * corr1 + rs1;

#pragma unroll
        for (int nt = 0; nt < 16; nt++) {
            oacc[nt][0] *= corr0; oacc[nt][1] *= corr0;
            oacc[nt][2] *= corr1; oacc[nt][3] *= corr1;
        }
        __syncwarp();

#pragma unroll
        for (int ks = 0; ks < 4; ks++) {
            int w0 = ks * 8;
            unsigned a[4];
            a[0] = Pw[(wm + grp)     * PW + w0 + qk];
            a[1] = Pw[(wm + grp + 8) * PW + w0 + qk];
            a[2] = Pw[(wm + grp)     * PW + w0 + qk + 4];
            a[3] = Pw[(wm + grp + 8) * PW + w0 + qk + 4];
#pragma unroll
            for (int nt = 0; nt < 16; nt++) {
                unsigned bfr[2];
                bfr[0] = Vw[(nt * 8 + grp) * VTW + w0 + qk];
                bfr[1] = Vw[(nt * 8 + grp) * VTW + w0 + qk + 4];
                mma_f16(oacc[nt], a, bfr);
            }
        }
    }

    float inv0 = 1.0f / l0, inv1 = 1.0f / l1;
    int r0 = qb * FBQ + wm + grp;
    __half* out0 = o + ((size_t)(b * S_ + r0) * NH_ + h) * HD_;
    __half* out1 = o + ((size_t)(b * S_ + r0 + 8) * NH_ + h) * HD_;
#pragma unroll
    for (int nt = 0; nt < 16; nt++) {
        int col = nt * 8 + qk * 2;
        *(__half2*)(out0 + col) = __floats2half2_rn(oacc[nt][0] * inv0, oacc[nt][1] * inv0);
        *(__half2*)(out1 + col) = __floats2half2_rn(oacc[nt][2] * inv1, oacc[nt][3] * inv1);
    }
}

// ---------------------------------------------------------------------------
__global__ __launch_bounds__(256) void swiglu_kernel(
    const float* __restrict__ g, const float* __restrict__ u,
    __half* __restrict__ outh)
{
    int idx = blockIdx.x * 256 + threadIdx.x;
    if (idx >= NTOK * (I_ / 4)) return;
    float4 gv = ((const float4*)g)[idx];
    float4 uv = ((const float4*)u)[idx];
    float r0 = gv.x / (1.f + __expf(-gv.x)) * uv.x;
    float r1 = gv.y / (1.f + __expf(-gv.y)) * uv.y;
    float r2 = gv.z / (1.f + __expf(-gv.z)) * uv.z;
    float r3 = gv.w / (1.f + __expf(-gv.w)) * uv.w;
    __half* dst = outh + (size_t)idx * 4;
    *(__half2*)(dst)     = __floats2half2_rn(r0, r1);
    *(__half2*)(dst + 2) = __floats2half2_rn(r2, r3);
}

// ---------------------------------------------------------------------------
extern "C" void kernel_launch(void* const* d_in, const int* in_sizes, int n_in,
                              void* d_out, int out_size)
{
    const float* hidden = (const float*)d_in[0];
    const float* ln1_w = (const float*)d_in[3];
    const float* Wq    = (const float*)d_in[4];
    const float* Wk    = (const float*)d_in[5];
    const float* Wv    = (const float*)d_in[6];
    const float* Wo    = (const float*)d_in[7];
    const float* qn_w  = (const float*)d_in[8];
    const float* kn_w  = (const float*)d_in[9];
    const float* ln2_w = (const float*)d_in[10];
    const float* Wg    = (const float*)d_in[11];
    const float* Wu    = (const float*)d_in[12];
    const float* Wd    = (const float*)d_in[13];
    float* out = (float*)d_out;

    float *p_q, *p_k, *p_v, *p_x, *p_g, *p_u;
    __half *p_hh, *p_oh, *p_gh;
    __half *p_wqT, *p_wkT, *p_wvT, *p_woT, *p_wgT, *p_wuT, *p_wdT;
    cudaGetSymbolAddress((void**)&p_q, g_q);
    cudaGetSymbolAddress((void**)&p_k, g_k);
    cudaGetSymbolAddress((void**)&p_v, g_v);
    cudaGetSymbolAddress((void**)&p_x, g_x);
    cudaGetSymbolAddress((void**)&p_g, g_g);
    cudaGetSymbolAddress((void**)&p_u, g_u);
    cudaGetSymbolAddress((void**)&p_hh, g_hh);
    cudaGetSymbolAddress((void**)&p_oh, g_oh);
    cudaGetSymbolAddress((void**)&p_gh, g_gh);
    cudaGetSymbolAddress((void**)&p_wqT, g_wqT);
    cudaGetSymbolAddress((void**)&p_wkT, g_wkT);
    cudaGetSymbolAddress((void**)&p_wvT, g_wvT);
    cudaGetSymbolAddress((void**)&p_woT, g_woT);
    cudaGetSymbolAddress((void**)&p_wgT, g_wgT);
    cudaGetSymbolAddress((void**)&p_wuT, g_wuT);
    cudaGetSymbolAddress((void**)&p_wdT, g_wdT);

    cudaFuncSetAttribute(flash_kernel,
                         cudaFuncAttributeMaxDynamicSharedMemorySize, FLASH_SMEM);
    cudaFuncSetAttribute(gemm_h_kernel,
                         cudaFuncAttributeMaxDynamicSharedMemorySize, HG_SMEM);

    rope_table_kernel<<<(S_ * 64 + 255) / 256, 256>>>();

    dim3 tb(32, 8);
    transpose_cvt_kernel<<<dim3(64, 64),  tb>>>(Wq, p_wqT, 2048, 2048);
    transpose_cvt_kernel<<<dim3(64, 16),  tb>>>(Wk, p_wkT, 2048, 512);
    transpose_cvt_kernel<<<dim3(64, 16),  tb>>>(Wv, p_wvT, 2048, 512);
    transpose_cvt_kernel<<<dim3(64, 64),  tb>>>(Wo, p_woT, 2048, 2048);
    transpose_cvt_kernel<<<dim3(64, 256), tb>>>(Wg, p_wgT, 2048, 8192);
    transpose_cvt_kernel<<<dim3(64, 256), tb>>>(Wu, p_wuT, 2048, 8192);
    transpose_cvt_kernel<<<dim3(256, 64), tb>>>(Wd, p_wdT, 8192, 2048);

    // Attention block
    rmsnorm_kernel<<<NTOK, 256>>>(hidden, ln1_w, p_hh);
    gemm_h_kernel<<<dim3((NH_ * HD_) / 128, NTOK / 128, 1), 256, HG_SMEM>>>(
        p_hh, p_wqT, nullptr, nullptr, p_q, nullptr, NTOK, NH_ * HD_, H_);
    gemm_h_kernel<<<dim3((NKV_ * HD_) / 128, NTOK / 128, 2), 256, HG_SMEM>>>(
        p_hh, p_wkT, p_wvT, nullptr, p_k, p_v, NTOK, NKV_ * HD_, H_);
    rope_norm_kernel<<<dim3(NTOK, NH_ / 4), 128>>>(p_q, qn_w, NH_);
    rope_norm_kernel<<<dim3(NTOK, NKV_ / 4), 128>>>(p_k, kn_w, NKV_);
    flash_kernel<<<dim3(S_ / FBQ, B_ * NH_), 256, FLASH_SMEM>>>(p_q, p_k, p_v, p_oh);
    gemm_h_kernel<<<dim3(H_ / 128, NTOK / 128, 1), 256, HG_SMEM>>>(
        p_oh, p_woT, nullptr, hidden, p_x, nullptr, NTOK, H_, H_);

    // MLP block
    rmsnorm_kernel<<<NTOK, 256>>>(p_x, ln2_w, p_hh);
    gemm_h_kernel<<<dim3(I_ / 128, NTOK / 128, 2), 256, HG_SMEM>>>(
        p_hh, p_wgT, p_wuT, nullptr, p_g, p_u, NTOK, I_, H_);
    swiglu_kernel<<<(NTOK * (I_ / 4) + 255) / 256, 256>>>(p_g, p_u, p_gh);
    gemm_h_kernel<<<dim3(H_ / 128, NTOK / 128, 1), 256, HG_SMEM>>>(
        p_gh, p_wdT, nullptr, p_x, out, nullptr, NTOK, H_, I_);
}

// round 11
// speedup vs baseline: 7.0926x; 1.0949x over previous
#include <cuda_runtime.h>
#include <cuda_fp16.h>
#include <math.h>
#include <stdint.h>

#define B_   2
#define S_   2048
#define H_   2048
#define NH_  16
#define NKV_ 4
#define HD_  128
#define I_   8192
#define NTOK (B_*S_)
#define EPSF 1e-6f

// ---------------------------------------------------------------------------
__device__ float  g_q [NTOK * NH_ * HD_];
__device__ float  g_k [NTOK * NKV_ * HD_];
__device__ float  g_v [NTOK * NKV_ * HD_];
__device__ float  g_x [NTOK * H_];
__device__ float  g_g [NTOK * I_];
__device__ float  g_u [NTOK * I_];
__device__ float  g_rope[S_ * HD_];
__device__ __half g_hh [NTOK * H_];
__device__ __half g_oh [NTOK * NH_ * HD_];
__device__ __half g_gh [NTOK * I_];
__device__ __half g_wqT[2048 * 2048];
__device__ __half g_wkT[512 * 2048];
__device__ __half g_wvT[512 * 2048];
__device__ __half g_woT[2048 * 2048];
__device__ __half g_wgT[8192 * 2048];
__device__ __half g_wuT[8192 * 2048];
__device__ __half g_wdT[2048 * 8192];

// ---------------------------------------------------------------------------
__device__ __forceinline__ void mma_f16(float* c, const unsigned* a, const unsigned* b) {
    asm volatile(
        "mma.sync.aligned.m16n8k16.row.col.f32.f16.f16.f32 "
        "{%0,%1,%2,%3},{%4,%5,%6,%7},{%8,%9},{%0,%1,%2,%3};\n"
        : "+f"(c[0]), "+f"(c[1]), "+f"(c[2]), "+f"(c[3])
        : "r"(a[0]), "r"(a[1]), "r"(a[2]), "r"(a[3]), "r"(b[0]), "r"(b[1]));
}

__device__ __forceinline__ void ldsm4(unsigned* r, unsigned addr) {
    asm volatile("ldmatrix.sync.aligned.m8n8.x4.shared.b16 {%0,%1,%2,%3}, [%4];"
        : "=r"(r[0]), "=r"(r[1]), "=r"(r[2]), "=r"(r[3]) : "r"(addr));
}

__device__ __forceinline__ unsigned h2u(__half2 h) {
    return *(unsigned*)&h;
}

__device__ __forceinline__ unsigned smem_u32(const void* p) {
    return (unsigned)__cvta_generic_to_shared(p);
}

#define CP_ASYNC16(dst, src) \
    asm volatile("cp.async.ca.shared.global [%0], [%1], 16;" :: "r"(dst), "l"(src))
#define CP_COMMIT() asm volatile("cp.async.commit_group;" ::: "memory")
#define CP_WAIT(n)  asm volatile("cp.async.wait_group %0;" :: "n"(n) : "memory")

// ---------------------------------------------------------------------------
__global__ void rope_table_kernel() {
    int idx = blockIdx.x * blockDim.x + threadIdx.x;
    if (idx >= S_ * 64) return;
    int pos = idx >> 6;
    int i   = idx & 63;
    float invf = 1.0f / powf(10000.0f, (float)i / 64.0f);
    float ang  = (float)pos * invf;
    g_rope[pos * HD_ + i]      = cosf(ang);
    g_rope[pos * HD_ + 64 + i] = sinf(ang);
}

// ---------------------------------------------------------------------------
__global__ __launch_bounds__(256) void transpose_cvt_kernel(
    const float* __restrict__ W, __half* __restrict__ Wt, int K, int N)
{
    __shared__ float t[32][33];
    int k0 = blockIdx.x * 32, n0 = blockIdx.y * 32;
    int tx = threadIdx.x, ty = threadIdx.y;
#pragma unroll
    for (int j = ty; j < 32; j += 8)
        t[j][tx] = W[(size_t)(k0 + j) * N + n0 + tx];
    __syncthreads();
    if (tx < 16) {
#pragma unroll
        for (int j = ty; j < 32; j += 8) {
            __half2 hv = __floats2half2_rn(t[2 * tx][j], t[2 * tx + 1][j]);
            *(__half2*)(Wt + (size_t)(n0 + j) * K + k0 + 2 * tx) = hv;
        }
    }
}

// ---------------------------------------------------------------------------
__global__ __launch_bounds__(256) void rmsnorm_kernel(
    const float* __restrict__ x, const float* __restrict__ w,
    __half* __restrict__ out)
{
    int row = blockIdx.x;
    const float* xr = x + (size_t)row * H_;
    float ss = 0.f;
#pragma unroll
    for (int it = 0; it < H_ / (256 * 4); it++) {
        int c = (it * 256 + threadIdx.x) * 4;
        float4 t = *(const float4*)(xr + c);
        ss += t.x * t.x + t.y * t.y + t.z * t.z + t.w * t.w;
    }
#pragma unroll
    for (int o = 16; o; o >>= 1) ss += __shfl_xor_sync(0xffffffffu, ss, o);
    __shared__ float red[8];
    if ((threadIdx.x & 31) == 0) red[threadIdx.x >> 5] = ss;
    __syncthreads();
    float tot = 0.f;
#pragma unroll
    for (int i = 0; i < 8; i++) tot += red[i];
    float inv = rsqrtf(tot * (1.0f / H_) + EPSF);
    __half* orow = out + (size_t)row * H_;
#pragma unroll
    for (int it = 0; it < H_ / (256 * 4); it++) {
        int c = (it * 256 + threadIdx.x) * 4;
        float4 t  = *(const float4*)(xr + c);
        float4 wv = *(const float4*)(w + c);
        __half2 h0 = __floats2half2_rn(wv.x * t.x * inv, wv.y * t.y * inv);
        __half2 h1 = __floats2half2_rn(wv.z * t.z * inv, wv.w * t.w * inv);
        *(__half2*)(orow + c)     = h0;
        *(__half2*)(orow + c + 2) = h1;
    }
}

// ---------------------------------------------------------------------------
// FP16 GEMM: cp.async 2-stage, ldmatrix fragments, 2 CTAs/SM.
// 128x128x64 tiles, rows 144B stride (conflict-free ldmatrix phases).
// ---------------------------------------------------------------------------
#define HSTR 72
#define HBUF (128 * HSTR)
#define HG_SMEM (4 * HBUF * 2)

__global__ __launch_bounds__(256, 2) void gemm_h_kernel(
    const __half* __restrict__ A, const __half* __restrict__ Bt,
    const __half* __restrict__ Bt2, const float* __restrict__ addend,
    float* __restrict__ C, float* __restrict__ C2,
    int M, int N, int K)
{
    extern __shared__ __half smh[];
    __half* As0 = smh;
    __half* Bs0 = smh + HBUF;
    __half* As1 = smh + 2 * HBUF;
    __half* Bs1 = smh + 3 * HBUF;

    if (blockIdx.z == 1) { Bt = Bt2; C = C2; }

    int tid = threadIdx.x;
    int bm = blockIdx.y * 128, bn = blockIdx.x * 128;
    int wid = tid >> 5, lane = tid & 31;
    int wm = (wid & 1) * 64;
    int wn = (wid >> 1) * 32;
    int grp = lane >> 2, qk = lane & 3;

    int lrow = tid >> 3;
    int lseg = (tid & 7) * 8;

    const __half* Ag = A  + (size_t)(bm + lrow) * K + lseg;
    const __half* Bg = Bt + (size_t)(bn + lrow) * K + lseg;

    unsigned sa[2], sb[2];
    sa[0] = smem_u32(As0 + lrow * HSTR + lseg);
    sb[0] = smem_u32(Bs0 + lrow * HSTR + lseg);
    sa[1] = smem_u32(As1 + lrow * HSTR + lseg);
    sb[1] = smem_u32(Bs1 + lrow * HSTR + lseg);
    const unsigned rowstep = 32 * HSTR * 2;

    // ldmatrix per-lane addresses
    int mi = lane >> 3, lr = lane & 7;
    int miL = mi & 1, miH = mi >> 1;
    unsigned aAdr[2][4], bAdr[2][2];
#pragma unroll
    for (int mt = 0; mt < 4; mt++) {
        int rowA = wm + mt * 16 + miL * 8 + lr;
        aAdr[0][mt] = smem_u32(As0) + rowA * 144 + miH * 16;
        aAdr[1][mt] = smem_u32(As1) + rowA * 144 + miH * 16;
    }
#pragma unroll
    for (int p = 0; p < 2; p++) {
        int rowB = wn + p * 16 + miH * 8 + lr;
        bAdr[0][p] = smem_u32(Bs0) + rowB * 144 + miL * 16;
        bAdr[1][p] = smem_u32(Bs1) + rowB * 144 + miL * 16;
    }

    float acc[4][4][4];
#pragma unroll
    for (int mt = 0; mt < 4; mt++)
#pragma unroll
        for (int nt = 0; nt < 4; nt++)
#pragma unroll
            for (int r = 0; r < 4; r++) acc[mt][nt][r] = 0.f;

    int nk = K / 64;

#pragma unroll
    for (int s = 0; s < 4; s++) {
        CP_ASYNC16(sa[0] + s * rowstep, Ag + (size_t)(32 * s) * K);
        CP_ASYNC16(sb[0] + s * rowstep, Bg + (size_t)(32 * s) * K);
    }
    CP_COMMIT();
    if (nk > 1) {
#pragma unroll
        for (int s = 0; s < 4; s++) {
            CP_ASYNC16(sa[1] + s * rowstep, Ag + (size_t)(32 * s) * K + 64);
            CP_ASYNC16(sb[1] + s * rowstep, Bg + (size_t)(32 * s) * K + 64);
        }
        CP_COMMIT();
        CP_WAIT(1);
    } else {
        CP_WAIT(0);
    }
    __syncthreads();

    for (int kt = 0; kt < nk; kt++) {
        int cur = kt & 1;

#pragma unroll
        for (int ks = 0; ks < 4; ks++) {
            unsigned koff = ks * 32;
            unsigned afr[4][4], bfr[4][2], bt0[4], bt1[4];
#pragma unroll
            for (int mt = 0; mt < 4; mt++)
                ldsm4(afr[mt], aAdr[cur][mt] + koff);
            ldsm4(bt0, bAdr[cur][0] + koff);
            ldsm4(bt1, bAdr[cur][1] + koff);
            bfr[0][0] = bt0[0]; bfr[0][1] = bt0[1];
            bfr[1][0] = bt0[2]; bfr[1][1] = bt0[3];
            bfr[2][0] = bt1[0]; bfr[2][1] = bt1[1];
            bfr[3][0] = bt1[2]; bfr[3][1] = bt1[3];
#pragma unroll
            for (int mt = 0; mt < 4; mt++)
#pragma unroll
                for (int nt = 0; nt < 4; nt++)
                    mma_f16(acc[mt][nt], afr[mt], bfr[nt]);
        }
        __syncthreads();

        if (kt + 2 < nk) {
            const __half* Ag2 = Ag + (size_t)(kt + 2) * 64;
            const __half* Bg2 = Bg + (size_t)(kt + 2) * 64;
#pragma unroll
            for (int s = 0; s < 4; s++) {
                CP_ASYNC16(sa[cur] + s * rowstep, Ag2 + (size_t)(32 * s) * K);
                CP_ASYNC16(sb[cur] + s * rowstep, Bg2 + (size_t)(32 * s) * K);
            }
            CP_COMMIT();
            CP_WAIT(1);
            __syncthreads();
        } else if (kt + 1 < nk) {
            CP_WAIT(0);
            __syncthreads();
        }
    }

#pragma unroll
    for (int mt = 0; mt < 4; mt++) {
#pragma unroll
        for (int nt = 0; nt < 4; nt++) {
            int row0 = bm + wm + mt * 16 + grp;
            int col  = bn + wn + nt * 8 + qk * 2;
            float* c0 = C + (size_t)row0 * N + col;
            float* c1 = C + (size_t)(row0 + 8) * N + col;
            if (addend) {
                const float* a0 = addend + (size_t)row0 * N + col;
                const float* a1 = addend + (size_t)(row0 + 8) * N + col;
                *(float2*)c0 = make_float2(acc[mt][nt][0] + a0[0], acc[mt][nt][1] + a0[1]);
                *(float2*)c1 = make_float2(acc[mt][nt][2] + a1[0], acc[mt][nt][3] + a1[1]);
            } else {
                *(float2*)c0 = make_float2(acc[mt][nt][0], acc[mt][nt][1]);
                *(float2*)c1 = make_float2(acc[mt][nt][2], acc[mt][nt][3]);
            }
        }
    }
}

// ---------------------------------------------------------------------------
__global__ __launch_bounds__(128) void rope_norm_kernel(
    float* __restrict__ qkp, const float* __restrict__ w, int nheads)
{
    int tok  = blockIdx.x;
    int warp = threadIdx.x >> 5;
    int lane = threadIdx.x & 31;
    int head = blockIdx.y * 4 + warp;
    int pos  = tok % S_;

    float* base = qkp + ((size_t)tok * nheads + head) * HD_;
    float a0 = base[lane];      float a1 = base[lane + 32];
    float b0 = base[lane + 64]; float b1 = base[lane + 96];

    const float* rc = g_rope + (size_t)pos * HD_;
    float c0 = rc[lane],      s0 = rc[64 + lane];
    float c1 = rc[lane + 32], s1 = rc[96 + lane];

    float r0  = a0 * c0 - b0 * s0;
    float r64 = b0 * c0 + a0 * s0;
    float r32 = a1 * c1 - b1 * s1;
    float r96 = b1 * c1 + a1 * s1;

    float ss = r0 * r0 + r32 * r32 + r64 * r64 + r96 * r96;
#pragma unroll
    for (int o = 16; o; o >>= 1) ss += __shfl_xor_sync(0xffffffffu, ss, o);
    float inv = rsqrtf(ss * (1.0f / HD_) + EPSF);

    base[lane]      = w[lane]      * r0  * inv;
    base[lane + 32] = w[lane + 32] * r32 * inv;
    base[lane + 64] = w[lane + 64] * r64 * inv;
    base[lane + 96] = w[lane + 96] * r96 * inv;
}

// ---------------------------------------------------------------------------
// FP16 flash attention with ldmatrix fragment feeds. BQ=128, BK=64.
// ---------------------------------------------------------------------------
#define FBQ 128
#define FBK 64
#define QKW 68
#define VTW 36
#define PW  36
#define QS_WORDS (FBQ * QKW)
#define KS_WORDS (FBK * QKW)
#define VT_WORDS (HD_ * VTW)
#define PS_WORDS (FBQ * PW)
#define FLASH_SMEM ((QS_WORDS + KS_WORDS + VT_WORDS + PS_WORDS) * 4)

__global__ __launch_bounds__(256, 2) void flash_kernel(
    const float* __restrict__ q, const float* __restrict__ k,
    const float* __restrict__ v, __half* __restrict__ o)
{
    extern __shared__ unsigned smw[];
    unsigned* Qw = smw;
    unsigned* Kw = Qw + QS_WORDS;
    unsigned* Vw = Kw + KS_WORDS;
    unsigned* Pw = Vw + VT_WORDS;

    int qb = gridDim.x - 1 - blockIdx.x;
    int bh = blockIdx.y;
    int b  = bh / NH_, h = bh % NH_;
    int kvh = h / (NH_ / NKV_);

    int tid = threadIdx.x;
    int wid = tid >> 5, lane = tid & 31;
    int wm = wid * 16;
    int grp = lane >> 2, qk = lane & 3;

    const float scale = 0.08838834764831845f;

    // ldmatrix per-lane addresses
    int mi = lane >> 3, lr = lane & 7;
    int miL = mi & 1, miH = mi >> 1;
    unsigned qAdr, pAdr, kAdr[4], vAdr[8];
    {
        int rowQ = wm + miL * 8 + lr;
        qAdr = smem_u32(Qw) + rowQ * 272 + miH * 16;
        int rowP = wm + miL * 8 + lr;
        pAdr = smem_u32(Pw) + rowP * 144 + miH * 16;
#pragma unroll
        for (int p = 0; p < 4; p++) {
            int rowK = p * 16 + miH * 8 + lr;
            kAdr[p] = smem_u32(Kw) + rowK * 272 + miL * 16;
        }
#pragma unroll
        for (int p = 0; p < 8; p++) {
            int rowV = p * 16 + miH * 8 + lr;
            vAdr[p] = smem_u32(Vw) + rowV * 144 + miL * 16;
        }
    }

    const float* qbase = q + ((size_t)(b * S_ + qb * FBQ) * NH_ + h) * HD_;
    for (int i = tid; i < FBQ * (HD_ / 4); i += 256) {
        int r  = i >> 5;
        int c4 = (i & 31) * 4;
        float4 t = *(const float4*)(qbase + (size_t)r * NH_ * HD_ + c4);
        unsigned* dst = Qw + r * QKW + (c4 >> 1);
        dst[0] = h2u(__floats2half2_rn(t.x * scale, t.y * scale));
        dst[1] = h2u(__floats2half2_rn(t.z * scale, t.w * scale));
    }

    float m0 = -1e30f, m1 = -1e30f, l0 = 0.f, l1 = 0.f;
    float oacc[16][4];
#pragma unroll
    for (int nt = 0; nt < 16; nt++)
#pragma unroll
        for (int r = 0; r < 4; r++) oacc[nt][r] = 0.f;

    int nkb = 2 * qb + 2;
    for (int kb = 0; kb < nkb; kb++) {
        __syncthreads();
        const float* kbase = k + ((size_t)(b * S_ + kb * FBK) * NKV_ + kvh) * HD_;
        const float* vbase = v + ((size_t)(b * S_ + kb * FBK) * NKV_ + kvh) * HD_;
        for (int i = tid; i < FBK * (HD_ / 4); i += 256) {
            int r  = i >> 5;
            int c4 = (i & 31) * 4;
            float4 tk = *(const float4*)(kbase + (size_t)r * NKV_ * HD_ + c4);
            unsigned* kd = Kw + r * QKW + (c4 >> 1);
            kd[0] = h2u(__floats2half2_rn(tk.x, tk.y));
            kd[1] = h2u(__floats2half2_rn(tk.z, tk.w));
        }
        for (int i = tid; i < 32 * 32; i += 256) {
            int sp = i & 31;
            int c4 = (i >> 5) * 4;
            float4 va = *(const float4*)(vbase + (size_t)(2 * sp)     * NKV_ * HD_ + c4);
            float4 vb = *(const float4*)(vbase + (size_t)(2 * sp + 1) * NKV_ * HD_ + c4);
            Vw[(c4 + 0) * VTW + sp] = h2u(__floats2half2_rn(va.x, vb.x));
            Vw[(c4 + 1) * VTW + sp] = h2u(__floats2half2_rn(va.y, vb.y));
            Vw[(c4 + 2) * VTW + sp] = h2u(__floats2half2_rn(va.z, vb.z));
            Vw[(c4 + 3) * VTW + sp] = h2u(__floats2half2_rn(va.w, vb.w));
        }
        __syncthreads();

        // ---- S = Q K^T ----
        float s[8][4];
#pragma unroll
        for (int nt = 0; nt < 8; nt++)
#pragma unroll
            for (int r = 0; r < 4; r++) s[nt][r] = 0.f;

#pragma unroll
        for (int ks = 0; ks < 8; ks++) {
            unsigned koff = ks * 32;
            unsigned a[4];
            ldsm4(a, qAdr + koff);
#pragma unroll
            for (int p = 0; p < 4; p++) {
                unsigned bt[4];
                ldsm4(bt, kAdr[p] + koff);
                mma_f16(s[p * 2],     a, bt);
                mma_f16(s[p * 2 + 1], a, bt + 2);
            }
        }

        if (kb >= 2 * qb) {
            int r0 = qb * FBQ + wm + grp;
            int cb = kb * FBK + qk * 2;
#pragma unroll
            for (int nt = 0; nt < 8; nt++) {
                int c0 = cb + nt * 8;
                if (c0     > r0)     s[nt][0] = -1e30f;
                if (c0 + 1 > r0)     s[nt][1] = -1e30f;
                if (c0     > r0 + 8) s[nt][2] = -1e30f;
                if (c0 + 1 > r0 + 8) s[nt][3] = -1e30f;
            }
        }

        float mx0 = -1e30f, mx1 = -1e30f;
#pragma unroll
        for (int nt = 0; nt < 8; nt++) {
            mx0 = fmaxf(mx0, fmaxf(s[nt][0], s[nt][1]));
            mx1 = fmaxf(mx1, fmaxf(s[nt][2], s[nt][3]));
        }
        mx0 = fmaxf(mx0, __shfl_xor_sync(0xffffffffu, mx0, 1));
        mx0 = fmaxf(mx0, __shfl_xor_sync(0xffffffffu, mx0, 2));
        mx1 = fmaxf(mx1, __shfl_xor_sync(0xffffffffu, mx1, 1));
        mx1 = fmaxf(mx1, __shfl_xor_sync(0xffffffffu, mx1, 2));

        float mn0 = fmaxf(m0, mx0), mn1 = fmaxf(m1, mx1);
        float corr0 = __expf(m0 - mn0), corr1 = __expf(m1 - mn1);
        m0 = mn0; m1 = mn1;

        float rs0 = 0.f, rs1 = 0.f;
#pragma unroll
        for (int nt = 0; nt < 8; nt++) {
            float p0 = __expf(s[nt][0] - mn0);
            float p1 = __expf(s[nt][1] - mn0);
            float p2 = __expf(s[nt][2] - mn1);
            float p3 = __expf(s[nt][3] - mn1);
            rs0 += p0 + p1; rs1 += p2 + p3;
            Pw[(wm + grp)     * PW + nt * 4 + qk] = h2u(__floats2half2_rn(p0, p1));
            Pw[(wm + grp + 8) * PW + nt * 4 + qk] = h2u(__floats2half2_rn(p2, p3));
        }
        rs0 += __shfl_xor_sync(0xffffffffu, rs0, 1);
        rs0 += __shfl_xor_sync(0xffffffffu, rs0, 2);
        rs1 += __shfl_xor_sync(0xffffffffu, rs1, 1);
        rs1 += __shfl_xor_sync(0xffffffffu, rs1, 2);
        l0 = l0 * corr0 + rs0;
        l1 = l1 * corr1 + rs1;

#pragma unroll
        for (int nt = 0; nt < 16; nt++) {
            oacc[nt][0] *= corr0; oacc[nt][1] *= corr0;
            oacc[nt][2] *= corr1; oacc[nt][3] *= corr1;
        }
        __syncwarp();

        // ---- O += P V ----
#pragma unroll
        for (int ks = 0; ks < 4; ks++) {
            unsigned koff = ks * 32;
            unsigned a[4];
            ldsm4(a, pAdr + koff);
#pragma unroll
            for (int p = 0; p < 8; p++) {
                unsigned bt[4];
                ldsm4(bt, vAdr[p] + koff);
                mma_f16(oacc[p * 2],     a, bt);
                mma_f16(oacc[p * 2 + 1], a, bt + 2);
            }
        }
    }

    float inv0 = 1.0f / l0, inv1 = 1.0f / l1;
    int r0 = qb * FBQ + wm + grp;
    __half* out0 = o + ((size_t)(b * S_ + r0) * NH_ + h) * HD_;
    __half* out1 = o + ((size_t)(b * S_ + r0 + 8) * NH_ + h) * HD_;
#pragma unroll
    for (int nt = 0; nt < 16; nt++) {
        int col = nt * 8 + qk * 2;
        *(__half2*)(out0 + col) = __floats2half2_rn(oacc[nt][0] * inv0, oacc[nt][1] * inv0);
        *(__half2*)(out1 + col) = __floats2half2_rn(oacc[nt][2] * inv1, oacc[nt][3] * inv1);
    }
}

// ---------------------------------------------------------------------------
__global__ __launch_bounds__(256) void swiglu_kernel(
    const float* __restrict__ g, const float* __restrict__ u,
    __half* __restrict__ outh)
{
    int idx = blockIdx.x * 256 + threadIdx.x;
    if (idx >= NTOK * (I_ / 4)) return;
    float4 gv = ((const float4*)g)[idx];
    float4 uv = ((const float4*)u)[idx];
    float r0 = gv.x / (1.f + __expf(-gv.x)) * uv.x;
    float r1 = gv.y / (1.f + __expf(-gv.y)) * uv.y;
    float r2 = gv.z / (1.f + __expf(-gv.z)) * uv.z;
    float r3 = gv.w / (1.f + __expf(-gv.w)) * uv.w;
    __half* dst = outh + (size_t)idx * 4;
    *(__half2*)(dst)     = __floats2half2_rn(r0, r1);
    *(__half2*)(dst + 2) = __floats2half2_rn(r2, r3);
}

// ---------------------------------------------------------------------------
extern "C" void kernel_launch(void* const* d_in, const int* in_sizes, int n_in,
                              void* d_out, int out_size)
{
    const float* hidden = (const float*)d_in[0];
    const float* ln1_w = (const float*)d_in[3];
    const float* Wq    = (const float*)d_in[4];
    const float* Wk    = (const float*)d_in[5];
    const float* Wv    = (const float*)d_in[6];
    const float* Wo    = (const float*)d_in[7];
    const float* qn_w  = (const float*)d_in[8];
    const float* kn_w  = (const float*)d_in[9];
    const float* ln2_w = (const float*)d_in[10];
    const float* Wg    = (const float*)d_in[11];
    const float* Wu    = (const float*)d_in[12];
    const float* Wd    = (const float*)d_in[13];
    float* out = (float*)d_out;

    float *p_q, *p_k, *p_v, *p_x, *p_g, *p_u;
    __half *p_hh, *p_oh, *p_gh;
    __half *p_wqT, *p_wkT, *p_wvT, *p_woT, *p_wgT, *p_wuT, *p_wdT;
    cudaGetSymbolAddress((void**)&p_q, g_q);
    cudaGetSymbolAddress((void**)&p_k, g_k);
    cudaGetSymbolAddress((void**)&p_v, g_v);
    cudaGetSymbolAddress((void**)&p_x, g_x);
    cudaGetSymbolAddress((void**)&p_g, g_g);
    cudaGetSymbolAddress((void**)&p_u, g_u);
    cudaGetSymbolAddress((void**)&p_hh, g_hh);
    cudaGetSymbolAddress((void**)&p_oh, g_oh);
    cudaGetSymbolAddress((void**)&p_gh, g_gh);
    cudaGetSymbolAddress((void**)&p_wqT, g_wqT);
    cudaGetSymbolAddress((void**)&p_wkT, g_wkT);
    cudaGetSymbolAddress((void**)&p_wvT, g_wvT);
    cudaGetSymbolAddress((void**)&p_woT, g_woT);
    cudaGetSymbolAddress((void**)&p_wgT, g_wgT);
    cudaGetSymbolAddress((void**)&p_wuT, g_wuT);
    cudaGetSymbolAddress((void**)&p_wdT, g_wdT);

    cudaFuncSetAttribute(flash_kernel,
                         cudaFuncAttributeMaxDynamicSharedMemorySize, FLASH_SMEM);
    cudaFuncSetAttribute(gemm_h_kernel,
                         cudaFuncAttributeMaxDynamicSharedMemorySize, HG_SMEM);

    rope_table_kernel<<<(S_ * 64 + 255) / 256, 256>>>();

    dim3 tb(32, 8);
    transpose_cvt_kernel<<<dim3(64, 64),  tb>>>(Wq, p_wqT, 2048, 2048);
    transpose_cvt_kernel<<<dim3(64, 16),  tb>>>(Wk, p_wkT, 2048, 512);
    transpose_cvt_kernel<<<dim3(64, 16),  tb>>>(Wv, p_wvT, 2048, 512);
    transpose_cvt_kernel<<<dim3(64, 64),  tb>>>(Wo, p_woT, 2048, 2048);
    transpose_cvt_kernel<<<dim3(64, 256), tb>>>(Wg, p_wgT, 2048, 8192);
    transpose_cvt_kernel<<<dim3(64, 256), tb>>>(Wu, p_wuT, 2048, 8192);
    transpose_cvt_kernel<<<dim3(256, 64), tb>>>(Wd, p_wdT, 8192, 2048);

    // Attention block
    rmsnorm_kernel<<<NTOK, 256>>>(hidden, ln1_w, p_hh);
    gemm_h_kernel<<<dim3((NH_ * HD_) / 128, NTOK / 128, 1), 256, HG_SMEM>>>(
        p_hh, p_wqT, nullptr, nullptr, p_q, nullptr, NTOK, NH_ * HD_, H_);
    gemm_h_kernel<<<dim3((NKV_ * HD_) / 128, NTOK / 128, 2), 256, HG_SMEM>>>(
        p_hh, p_wkT, p_wvT, nullptr, p_k, p_v, NTOK, NKV_ * HD_, H_);
    rope_norm_kernel<<<dim3(NTOK, NH_ / 4), 128>>>(p_q, qn_w, NH_);
    rope_norm_kernel<<<dim3(NTOK, NKV_ / 4), 128>>>(p_k, kn_w, NKV_);
    flash_kernel<<<dim3(S_ / FBQ, B_ * NH_), 256, FLASH_SMEM>>>(p_q, p_k, p_v, p_oh);
    gemm_h_kernel<<<dim3(H_ / 128, NTOK / 128, 1), 256, HG_SMEM>>>(
        p_oh, p_woT, nullptr, hidden, p_x, nullptr, NTOK, H_, H_);

    // MLP block
    rmsnorm_kernel<<<NTOK, 256>>>(p_x, ln2_w, p_hh);
    gemm_h_kernel<<<dim3(I_ / 128, NTOK / 128, 2), 256, HG_SMEM>>>(
        p_hh, p_wgT, p_wuT, nullptr, p_g, p_u, NTOK, I_, H_);
    swiglu_kernel<<<(NTOK * (I_ / 4) + 255) / 256, 256>>>(p_g, p_u, p_gh);
    gemm_h_kernel<<<dim3(H_ / 128, NTOK / 128, 1), 256, HG_SMEM>>>(
        p_gh, p_wdT, nullptr, p_x, out, nullptr, NTOK, H_, I_);
}